// round 10
// baseline (speedup 1.0000x reference)
#include <cuda_runtime.h>
#include <cuda_fp16.h>
#include <cuda_bf16.h>
#include <math.h>

#define B_    4
#define S_V_  768
#define S_E_  64
#define S_    832
#define W_V_  2048
#define W_E_  1024
#define H_    8
#define DH_   256
#define MLPV_ 16384
#define MLPE_ 4096
#define EPS_  1e-6f
#define SCALE_ 0.0625f

// ---------------- scratch ----------------
__device__ __half g_hv   [B_*S_V_*W_V_];
__device__ __half g_he   [B_*S_E_*W_E_];
__device__ float  g_mod1 [B_*3*W_E_];
__device__ float  g_mod2 [B_*3*W_E_];
__device__ __half g_q    [(long long)B_*S_*H_*DH_];
__device__ __half g_qt   [(long long)B_*H_*S_*DH_];
__device__ __half g_k    [B_*S_*DH_];
__device__ __half g_v    [B_*S_*DH_];
__device__ float  g_logits[(long long)B_*H_*S_*S_];
__device__ __half g_probs[(long long)B_*H_*S_*S_];
__device__ __half g_attnt[(long long)B_*H_*S_*DH_];
__device__ __half g_attn [(long long)B_*S_*H_*DH_];
__device__ float  g_hv1  [B_*S_V_*W_V_];
__device__ float  g_he1  [B_*S_E_*W_E_];
__device__ __half g_mg   [(long long)B_*S_V_*MLPV_];
__device__ float  g_mu   [(long long)B_*S_V_*MLPV_];
__device__ __half g_eg   [B_*S_E_*MLPE_];
__device__ float  g_eu   [B_*S_E_*MLPE_];
__device__ __half g_wbuf [127401984];

__device__ __forceinline__ float gelu_t(float x) {
    return 0.5f * x * (1.f + tanhf(0.7978845608028654f * (x + 0.044715f * x * x * x)));
}

__device__ __forceinline__ void mma_f16(float* c, const unsigned* a, const unsigned* b) {
    asm volatile(
        "mma.sync.aligned.m16n8k16.row.col.f32.f16.f16.f32 "
        "{%0,%1,%2,%3}, {%4,%5,%6,%7}, {%8,%9}, {%0,%1,%2,%3};\n"
        : "+f"(c[0]), "+f"(c[1]), "+f"(c[2]), "+f"(c[3])
        : "r"(a[0]), "r"(a[1]), "r"(a[2]), "r"(a[3]), "r"(b[0]), "r"(b[1]));
}

// ============ gemm16: fp16 operands, fp32 accum, TB=0 ============
// A (M,K) halfs row-major; B (K,N) halfs row-major. K%32==0, N%8==0.
// Block 128x128 tile, 128 threads = 4 warps (2m x 2n) of 64x64 warp tiles.
// K-tile 32, 4 cp.async stages. 2 CTAs/SM.
// smem per stage: A [128][40]h (10240B) + B [32][136]h (8704B) = 18944B
// EPI: 0 plain->fp16, 1 plain->fp32, 2 fp16(gelu(c)*aux), 3 fp32(c+aux),
//      4 fp32(aux + c*mod[(z+gm/S_E)*3W_E+2W_E+gn])
#define ASTB 10240
#define STGB 18944
template<int EPI>
__global__ __launch_bounds__(128, 2)
void gemm16(const __half* __restrict__ A, const __half* __restrict__ Bm,
            void* __restrict__ Cv, const float* __restrict__ aux,
            const float* __restrict__ modv,
            int M, int N, int K,
            long long sA, long long sB, long long sC, int bInner)
{
    extern __shared__ __align__(16) char sm[];

    const int z = blockIdx.z;
    A  += (long long)z * sA;
    Bm += (long long)(z / bInner) * sB;

    const int tid  = threadIdx.x;
    const int lane = tid & 31;
    const int wid  = tid >> 5;
    const int wm   = (wid & 1) * 64;
    const int wn   = (wid >> 1) * 64;
    const int bm   = blockIdx.y * 128;
    const int bn   = blockIdx.x * 128;
    const int row  = lane >> 2, col = lane & 3;

    unsigned sbase = (unsigned)__cvta_generic_to_shared(sm);

    auto issue = [&](int st) {
        const int ktE = st * 32;
        const unsigned sb = sbase + (unsigned)((st & 3) * STGB);
#pragma unroll
        for (int j = 0; j < 4; j++) {            // A: 128 rows x 32 halfs (512 x 16B)
            int id = tid + j * 128;
            int r = id >> 2, c = id & 3;
            int gm = bm + r;
            const __half* gp = A + (long long)(gm < M ? gm : M - 1) * K + ktE + c * 8;
            unsigned dst = sb + (unsigned)(r * 80 + c * 16);
            int zf = (gm < M) ? 16 : 0;
            asm volatile("cp.async.cg.shared.global [%0], [%1], 16, %2;\n"
                         :: "r"(dst), "l"(gp), "r"(zf));
        }
#pragma unroll
        for (int j = 0; j < 4; j++) {            // B: 32 rows x 128 halfs (512 x 16B)
            int id = tid + j * 128;
            int kr = id >> 4, c = id & 15;
            int gn = bn + c * 8;
            const __half* gp = Bm + (long long)(ktE + kr) * N + (gn < N ? gn : N - 8);
            unsigned dst = sb + (unsigned)(ASTB + kr * 272 + c * 16);
            int zf = (gn < N) ? 16 : 0;
            asm volatile("cp.async.cg.shared.global [%0], [%1], 16, %2;\n"
                         :: "r"(dst), "l"(gp), "r"(zf));
        }
    };

    float c[4][8][4];
#pragma unroll
    for (int i = 0; i < 4; i++)
#pragma unroll
        for (int j = 0; j < 8; j++)
#pragma unroll
            for (int l = 0; l < 4; l++) c[i][j][l] = 0.f;

    const unsigned aoff = (unsigned)((((lane >> 3) & 1) * 8 + (lane & 7)) * 80 + (lane >> 4) * 16);
    const int l16 = lane & 15;
    const unsigned boff = (unsigned)(ASTB + ((l16 >> 3) * 8 + (l16 & 7)) * 272 + wn * 2);

    const int nk = K / 32;
#pragma unroll 1
    for (int s = 0; s < 3; s++) { issue(s); asm volatile("cp.async.commit_group;\n"); }

#pragma unroll 1
    for (int kt = 0; kt < nk; kt++) {
        asm volatile("cp.async.wait_group 2;\n");
        __syncthreads();
        if (kt + 3 < nk) issue(kt + 3);
        asm volatile("cp.async.commit_group;\n");

        const unsigned stg = sbase + (unsigned)((kt & 3) * STGB);
#pragma unroll
        for (int sub = 0; sub < 2; sub++) {
            unsigned af[4][4], bf[8][2];
#pragma unroll
            for (int mt = 0; mt < 4; mt++) {
                unsigned ad = stg + (unsigned)((wm + mt * 16) * 80 + sub * 32) + aoff;
                asm volatile("ldmatrix.sync.aligned.m8n8.x4.shared.b16 {%0,%1,%2,%3}, [%4];"
                             : "=r"(af[mt][0]), "=r"(af[mt][1]), "=r"(af[mt][2]), "=r"(af[mt][3])
                             : "r"(ad));
            }
#pragma unroll
            for (int nt = 0; nt < 8; nt++) {
                unsigned bd = stg + (unsigned)(sub * 16 * 272 + nt * 16) + boff;
                asm volatile("ldmatrix.sync.aligned.m8n8.x2.trans.shared.b16 {%0,%1}, [%2];"
                             : "=r"(bf[nt][0]), "=r"(bf[nt][1]) : "r"(bd));
            }
#pragma unroll
            for (int mt = 0; mt < 4; mt++)
#pragma unroll
                for (int nt = 0; nt < 8; nt++)
                    mma_f16(c[mt][nt], af[mt], bf[nt]);
        }
    }

    if (EPI >= 2) aux += (long long)z * sC;
    __half* Ch = (__half*)Cv + (long long)z * sC;
    float*  Cf = (float*)Cv + (long long)z * sC;

    auto epi_store = [&](int gm, int gn, float x0, float x1) {
        long long o = (long long)gm * N + gn;
        if (EPI == 0) {
            *(__half2*)(Ch + o) = __halves2half2(__float2half_rn(x0), __float2half_rn(x1));
        } else if (EPI == 1) {
            *(float2*)(Cf + o) = make_float2(x0, x1);
        } else if (EPI == 2) {
            float2 u = *(const float2*)(aux + o);
            *(__half2*)(Ch + o) = __halves2half2(__float2half_rn(gelu_t(x0) * u.x),
                                                 __float2half_rn(gelu_t(x1) * u.y));
        } else if (EPI == 3) {
            float2 u = *(const float2*)(aux + o);
            *(float2*)(Cf + o) = make_float2(x0 + u.x, x1 + u.y);
        } else {
            int bb = z + gm / S_E_;
            float g0 = modv[(long long)bb * 3 * W_E_ + 2 * W_E_ + gn];
            float g1 = modv[(long long)bb * 3 * W_E_ + 2 * W_E_ + gn + 1];
            float2 u = *(const float2*)(aux + o);
            *(float2*)(Cf + o) = make_float2(u.x + x0 * g0, u.y + x1 * g1);
        }
    };

#pragma unroll
    for (int mt = 0; mt < 4; mt++) {
#pragma unroll
        for (int nt = 0; nt < 8; nt++) {
            int gm = bm + wm + mt * 16 + row;
            int gn = bn + wn + nt * 8 + col * 2;
            if (gn < N) {
                if (gm < M)     epi_store(gm,     gn, c[mt][nt][0], c[mt][nt][1]);
                if (gm + 8 < M) epi_store(gm + 8, gn, c[mt][nt][2], c[mt][nt][3]);
            }
        }
    }
}

// ============ gemm16_tb1: fp16, B (N,K) row-major, fp32 out (proven R8) ============
#define STG1 20480
__global__ __launch_bounds__(256, 2)
void gemm16_tb1(const __half* __restrict__ A, const __half* __restrict__ Bm,
                float* __restrict__ C, int M, int N, int K,
                long long sA, long long sB, long long sC, int bInner)
{
    extern __shared__ __align__(16) char sm[];

    const int z = blockIdx.z;
    A  += (long long)z * sA;
    Bm += (long long)(z / bInner) * sB;
    C  += (long long)z * sC;

    const int tid  = threadIdx.x;
    const int lane = tid & 31;
    const int wid  = tid >> 5;
    const int wm   = (wid & 1) * 64;
    const int wn   = (wid >> 1) * 32;
    const int bm   = blockIdx.y * 128;
    const int bn   = blockIdx.x * 128;
    const int row  = lane >> 2, col = lane & 3;

    unsigned sbase = (unsigned)__cvta_generic_to_shared(sm);

    auto issue = [&](int st) {
        const int ktE = st * 32;
        const unsigned sb = sbase + (unsigned)((st & 3) * STG1);
#pragma unroll
        for (int j = 0; j < 2; j++) {
            int id = tid + j * 256;
            int r = id >> 2, c = id & 3;
            int gm = bm + r;
            const __half* gp = A + (long long)(gm < M ? gm : M - 1) * K + ktE + c * 8;
            unsigned dst = sb + (unsigned)(r * 80 + c * 16);
            int zf = (gm < M) ? 16 : 0;
            asm volatile("cp.async.cg.shared.global [%0], [%1], 16, %2;\n"
                         :: "r"(dst), "l"(gp), "r"(zf));
        }
#pragma unroll
        for (int j = 0; j < 2; j++) {
            int id = tid + j * 256;
            int r = id >> 2, c = id & 3;
            int gn = bn + r;
            const __half* gp = Bm + (long long)(gn < N ? gn : N - 1) * K + ktE + c * 8;
            unsigned dst = sb + (unsigned)(ASTB + r * 80 + c * 16);
            int zf = (gn < N) ? 16 : 0;
            asm volatile("cp.async.cg.shared.global [%0], [%1], 16, %2;\n"
                         :: "r"(dst), "l"(gp), "r"(zf));
        }
    };

    float c[4][4][4];
#pragma unroll
    for (int i = 0; i < 4; i++)
#pragma unroll
        for (int j = 0; j < 4; j++)
#pragma unroll
            for (int l = 0; l < 4; l++) c[i][j][l] = 0.f;

    const unsigned aoff = (unsigned)((((lane >> 3) & 1) * 8 + (lane & 7)) * 80 + (lane >> 4) * 16);
    const int l16 = lane & 15;
    const unsigned boff = (unsigned)(ASTB + ((l16 & 7) + wn) * 80 + (l16 >> 3) * 16);

    const int nk = K / 32;
#pragma unroll 1
    for (int s = 0; s < 3; s++) { issue(s); asm volatile("cp.async.commit_group;\n"); }

#pragma unroll 1
    for (int kt = 0; kt < nk; kt++) {
        asm volatile("cp.async.wait_group 2;\n");
        __syncthreads();
        if (kt + 3 < nk) issue(kt + 3);
        asm volatile("cp.async.commit_group;\n");

        const unsigned stg = sbase + (unsigned)((kt & 3) * STG1);
#pragma unroll
        for (int sub = 0; sub < 2; sub++) {
            unsigned af[4][4], bf[4][2];
#pragma unroll
            for (int mt = 0; mt < 4; mt++) {
                unsigned ad = stg + (unsigned)((wm + mt * 16) * 80 + sub * 32) + aoff;
                asm volatile("ldmatrix.sync.aligned.m8n8.x4.shared.b16 {%0,%1,%2,%3}, [%4];"
                             : "=r"(af[mt][0]), "=r"(af[mt][1]), "=r"(af[mt][2]), "=r"(af[mt][3])
                             : "r"(ad));
            }
#pragma unroll
            for (int nt = 0; nt < 4; nt++) {
                unsigned bd = stg + (unsigned)(nt * 8 * 80 + sub * 32) + boff;
                asm volatile("ldmatrix.sync.aligned.m8n8.x2.shared.b16 {%0,%1}, [%2];"
                             : "=r"(bf[nt][0]), "=r"(bf[nt][1]) : "r"(bd));
            }
#pragma unroll
            for (int mt = 0; mt < 4; mt++)
#pragma unroll
                for (int nt = 0; nt < 4; nt++)
                    mma_f16(c[mt][nt], af[mt], bf[nt]);
        }
    }

#pragma unroll
    for (int mt = 0; mt < 4; mt++) {
#pragma unroll
        for (int nt = 0; nt < 4; nt++) {
            int gm = bm + wm + mt * 16 + row;
            int gn = bn + wn + nt * 8 + col * 2;
            if (gn < N) {
                if (gm < M)
                    *(float2*)(C + (long long)gm * N + gn) = make_float2(c[mt][nt][0], c[mt][nt][1]);
                if (gm + 8 < M)
                    *(float2*)(C + (long long)(gm + 8) * N + gn) = make_float2(c[mt][nt][2], c[mt][nt][3]);
            }
        }
    }
}

// ---------------- weight fp16 pre-convert ----------------
__global__ void round4(const float4* __restrict__ s, __half2* __restrict__ d, int n4)
{
    int i = blockIdx.x * 256 + threadIdx.x;
    if (i >= n4) return;
    float4 v = s[i];
    d[i * 2]     = __floats2half2_rn(v.x, v.y);
    d[i * 2 + 1] = __floats2half2_rn(v.z, v.w);
}

#define NW 13
struct RoundDesc {
    const float4* src[NW];
    long long dofs[NW];
    int blkStart[NW + 1];   // each block = 4096 floats
};

__global__ void round_many(RoundDesc d, __half* __restrict__ wbuf)
{
    int b = blockIdx.x;
    int w = 0;
#pragma unroll
    for (int i = 0; i < NW; i++) if (b >= d.blkStart[i + 1]) w = i + 1;
    int lb = b - d.blkStart[w];
    const float4* s = d.src[w] + (long long)lb * 1024;
    __half2* o = (__half2*)(wbuf + d.dofs[w]) + (long long)lb * 2048;
    int t = threadIdx.x;
#pragma unroll
    for (int i = 0; i < 4; i++) {
        float4 v = s[t + i * 256];
        o[(t + i * 256) * 2]     = __floats2half2_rn(v.x, v.y);
        o[(t + i * 256) * 2 + 1] = __floats2half2_rn(v.z, v.w);
    }
}

// ---------------- row kernels ----------------
__device__ __forceinline__ float blockReduceSum(float v) {
    __shared__ float red[256];
    int t = threadIdx.x;
    red[t] = v; __syncthreads();
    for (int s = 128; s > 0; s >>= 1) {
        if (t < s) red[t] += red[t + s];
        __syncthreads();
    }
    float r = red[0];
    __syncthreads();
    return r;
}

__global__ void rms_scale(const float* __restrict__ x, const float* __restrict__ w,
                          __half* __restrict__ out, int W)
{
    long long base = (long long)blockIdx.x * W;
    float ss = 0.f;
    for (int c = threadIdx.x; c < W; c += 256) { float t = x[base + c]; ss += t * t; }
    float tot = blockReduceSum(ss);
    float inv = rsqrtf(tot / (float)W + EPS_);
    for (int c = threadIdx.x; c < W; c += 256)
        out[base + c] = __float2half_rn(x[base + c] * inv * (1.f + w[c]));
}

__global__ void rms_mod(const float* __restrict__ x, const float* __restrict__ mod,
                        __half* __restrict__ out, int W, int rowsPerB)
{
    long long base = (long long)blockIdx.x * W;
    int b = blockIdx.x / rowsPerB;
    const float* m = mod + (long long)b * 3 * W;
    float ss = 0.f;
    for (int c = threadIdx.x; c < W; c += 256) { float t = x[base + c]; ss += t * t; }
    float tot = blockReduceSum(ss);
    float inv = rsqrtf(tot / (float)W + EPS_);
    for (int c = threadIdx.x; c < W; c += 256)
        out[base + c] = __float2half_rn(x[base + c] * inv * (1.f + m[c]) + m[W + c]);
}

__global__ void modmm2(const float* __restrict__ cond, const float* __restrict__ W,
                       const float* __restrict__ bias, float* __restrict__ out)
{
    const int NT = 3 * W_E_;
    __shared__ float cs[W_E_];
    __shared__ float part[4][64];
    int bb = blockIdx.y;
    int tid = threadIdx.x;
    for (int i = tid; i < W_E_; i += 256) cs[i] = cond[bb * W_E_ + i];
    __syncthreads();
    int tx = tid & 63, ty = tid >> 6;
    int c = blockIdx.x * 64 + tx;
    const float* Wp = W + (long long)(ty * 256) * NT + c;
    const float* cp = cs + ty * 256;
    float s = 0.f;
#pragma unroll 4
    for (int k = 0; k < 256; k++) s += cp[k] * Wp[(long long)k * NT];
    part[ty][tx] = s;
    __syncthreads();
    if (ty == 0)
        out[(long long)bb * NT + c] = part[0][tx] + part[1][tx] + part[2][tx] + part[3][tx] + bias[c];
}

__global__ void rope4h(__half* __restrict__ x, const int* __restrict__ pos, int nh)
{
    int idx = blockIdx.x * blockDim.x + threadIdx.x;
    int total = B_ * S_ * nh * 32;
    if (idx >= total) return;
    int d4 = (idx & 31) << 2;
    int h = (idx >> 5) % nh;
    int s = (idx / (32 * nh)) % S_;
    int b = idx / (32 * nh * S_);
    float p = (float)pos[b * S_ + s];
    __half* base = x + (((long long)(b * S_ + s) * nh + h) << 8);
    __half2 x1a = *(__half2*)(base + d4),       x1b = *(__half2*)(base + d4 + 2);
    __half2 x2a = *(__half2*)(base + d4 + 128), x2b = *(__half2*)(base + d4 + 130);
    float r1[4] = {__low2float(x1a), __high2float(x1a), __low2float(x1b), __high2float(x1b)};
    float r2[4] = {__low2float(x2a), __high2float(x2a), __low2float(x2b), __high2float(x2b)};
#pragma unroll
    for (int j = 0; j < 4; j++) {
        float ang = p * powf(10000.f, -(float)(2 * (d4 + j)) / 256.f);
        float sn, cs2; sincosf(ang, &sn, &cs2);
        float a = r1[j], bb = r2[j];
        r1[j] = a * cs2 - bb * sn;
        r2[j] = bb * cs2 + a * sn;
    }
    *(__half2*)(base + d4)       = __floats2half2_rn(r1[0], r1[1]);
    *(__half2*)(base + d4 + 2)   = __floats2half2_rn(r1[2], r1[3]);
    *(__half2*)(base + d4 + 128) = __floats2half2_rn(r2[0], r2[1]);
    *(__half2*)(base + d4 + 130) = __floats2half2_rn(r2[2], r2[3]);
}

__global__ void q_to_bhsd8h(const uint4* __restrict__ q, uint4* __restrict__ qt)
{
    int idx = blockIdx.x * blockDim.x + threadIdx.x;
    int total = B_ * H_ * S_ * 32;
    if (idx >= total) return;
    int d = idx & 31;
    int s = (idx >> 5) % S_;
    int h = (idx / (32 * S_)) % H_;
    int b = idx / (32 * S_ * H_);
    qt[idx] = q[(((b * S_ + s) * H_ + h) * 32) + d];
}

__global__ void bhsd_to_bshd8h(const uint4* __restrict__ a, uint4* __restrict__ o)
{
    int idx = blockIdx.x * blockDim.x + threadIdx.x;
    int total = B_ * S_ * H_ * 32;
    if (idx >= total) return;
    int d = idx & 31;
    int h = (idx >> 5) % H_;
    int s = (idx / (32 * H_)) % S_;
    int b = idx / (32 * H_ * S_);
    o[idx] = a[(((b * H_ + h) * S_ + s) * 32) + d];
}

__global__ void softmax4h(const float* __restrict__ logits, const float* __restrict__ mask,
                          __half* __restrict__ probs)
{
    int rowid = blockIdx.x;
    int b = rowid / (H_ * S_);
    int q = rowid % S_;
    const float4* row = (const float4*)(logits + (long long)rowid * S_);
    const float4* m = (const float4*)(mask + ((long long)b * S_ + q) * S_);
    __half* prow = probs + (long long)rowid * S_;
    int t = threadIdx.x;
    const bool act = t < 208;
    float4 v = make_float4(-1e30f, -1e30f, -1e30f, -1e30f);
    if (act) {
        float4 lv = row[t], mv = m[t];
        v.x = lv.x * SCALE_ + mv.x; v.y = lv.y * SCALE_ + mv.y;
        v.z = lv.z * SCALE_ + mv.z; v.w = lv.w * SCALE_ + mv.w;
    }
    float mx = fmaxf(fmaxf(v.x, v.y), fmaxf(v.z, v.w));
    __shared__ float red[256];
    red[t] = mx; __syncthreads();
    for (int s = 128; s > 0; s >>= 1) { if (t < s) red[t] = fmaxf(red[t], red[t + s]); __syncthreads(); }
    mx = red[0]; __syncthreads();
    float sum = 0.f;
    if (act) {
        v.x = __expf(v.x - mx); v.y = __expf(v.y - mx);
        v.z = __expf(v.z - mx); v.w = __expf(v.w - mx);
        sum = v.x + v.y + v.z + v.w;
    }
    red[t] = sum; __syncthreads();
    for (int s = 128; s > 0; s >>= 1) { if (t < s) red[t] += red[t + s]; __syncthreads(); }
    float inv = 1.f / red[0];
    if (act) {
        *(__half2*)(prow + t * 4)     = __floats2half2_rn(v.x * inv, v.y * inv);
        *(__half2*)(prow + t * 4 + 2) = __floats2half2_rn(v.z * inv, v.w * inv);
    }
}

// ---------------- host launch ----------------
#define GETSYMF(var, sym) do { void* p__; cudaGetSymbolAddress(&p__, sym); var = (float*)p__; } while (0)
#define GETSYMH(var, sym) do { void* p__; cudaGetSymbolAddress(&p__, sym); var = (__half*)p__; } while (0)

extern "C" void kernel_launch(void* const* d_in, const int* in_sizes, int n_in,
                              void* d_out, int out_size)
{
    const float *embeds_vlm, *embeds_exp, *cond, *attn_mask;
    const int* pos;
    const float *vlm_ln1_w, *vlm_ln2_w, *vlm_q_w, *vlm_k_w, *vlm_v_w, *vlm_o_w;
    const float *vlm_gate_w, *vlm_up_w, *vlm_down_w;
    const float *exp_ln1_dw, *exp_ln1_db, *exp_ln2_dw, *exp_ln2_db;
    const float *exp_q_w, *exp_k_w, *exp_v_w, *exp_o_w, *exp_gate_w, *exp_up_w, *exp_down_w;

    if (in_sizes[3] == B_ * S_) {
        embeds_vlm = (const float*)d_in[0];  embeds_exp = (const float*)d_in[1];
        cond       = (const float*)d_in[2];  pos        = (const int*)  d_in[3];
        attn_mask  = (const float*)d_in[4];
        vlm_ln1_w  = (const float*)d_in[5];  vlm_ln2_w  = (const float*)d_in[6];
        vlm_q_w    = (const float*)d_in[7];  vlm_k_w    = (const float*)d_in[8];
        vlm_v_w    = (const float*)d_in[9];  vlm_o_w    = (const float*)d_in[10];
        vlm_gate_w = (const float*)d_in[11]; vlm_up_w   = (const float*)d_in[12];
        vlm_down_w = (const float*)d_in[13];
        exp_ln1_dw = (const float*)d_in[14]; exp_ln1_db = (const float*)d_in[15];
        exp_ln2_dw = (const float*)d_in[16]; exp_ln2_db = (const float*)d_in[17];
        exp_q_w    = (const float*)d_in[18]; exp_k_w    = (const float*)d_in[19];
        exp_v_w    = (const float*)d_in[20]; exp_o_w    = (const float*)d_in[21];
        exp_gate_w = (const float*)d_in[22]; exp_up_w   = (const float*)d_in[23];
        exp_down_w = (const float*)d_in[24];
    } else {
        embeds_vlm = (const float*)d_in[0];  embeds_exp = (const float*)d_in[1];
        cond       = (const float*)d_in[2];
        vlm_ln1_w  = (const float*)d_in[3];  vlm_ln2_w  = (const float*)d_in[4];
        vlm_q_w    = (const float*)d_in[5];  vlm_k_w    = (const float*)d_in[6];
        vlm_v_w    = (const float*)d_in[7];  vlm_o_w    = (const float*)d_in[8];
        vlm_gate_w = (const float*)d_in[9];  vlm_up_w   = (const float*)d_in[10];
        vlm_down_w = (const float*)d_in[11];
        exp_ln1_dw = (const float*)d_in[12]; exp_ln1_db = (const float*)d_in[13];
        exp_ln2_dw = (const float*)d_in[14]; exp_ln2_db = (const float*)d_in[15];
        exp_q_w    = (const float*)d_in[16]; exp_k_w    = (const float*)d_in[17];
        exp_v_w    = (const float*)d_in[18]; exp_o_w    = (const float*)d_in[19];
        exp_gate_w = (const float*)d_in[20]; exp_up_w   = (const float*)d_in[21];
        exp_down_w = (const float*)d_in[22];
        pos        = (const int*)  d_in[23];
        attn_mask  = (const float*)d_in[24];
    }

    __half *hv, *he, *q, *qt, *k, *v, *probs, *attnt, *attn, *mg, *eg, *wb;
    float *mod1, *mod2, *logits, *hv1, *he1, *mu, *eu;
    GETSYMH(hv, g_hv);   GETSYMH(he, g_he);   GETSYMF(mod1, g_mod1); GETSYMF(mod2, g_mod2);
    GETSYMH(q, g_q);     GETSYMH(qt, g_qt);   GETSYMH(k, g_k);       GETSYMH(v, g_v);
    GETSYMF(logits, g_logits); GETSYMH(probs, g_probs);
    GETSYMH(attnt, g_attnt);   GETSYMH(attn, g_attn);
    GETSYMF(hv1, g_hv1); GETSYMF(he1, g_he1);
    GETSYMH(mg, g_mg);   GETSYMF(mu, g_mu);
    GETSYMH(eg, g_eg);   GETSYMF(eu, g_eu);   GETSYMH(wb, g_wbuf);

    const long long n_vq = (long long)W_V_ * H_ * DH_;
    const float* srcs[NW] = {vlm_k_w, vlm_v_w, vlm_o_w, vlm_gate_w, vlm_up_w, vlm_down_w,
                             exp_q_w, exp_k_w, exp_v_w, exp_o_w, exp_gate_w, exp_up_w, exp_down_w};
    long long cnts[NW] = {
        (long long)W_V_*DH_, (long long)W_V_*DH_, (long long)H_*DH_*W_V_,
        (long long)W_V_*MLPV_, (long long)W_V_*MLPV_, (long long)MLPV_*W_V_,
        (long long)W_E_*H_*DH_, (long long)W_E_*DH_, (long long)W_E_*DH_, (long long)H_*DH_*W_E_,
        (long long)W_E_*MLPE_, (long long)W_E_*MLPE_, (long long)MLPE_*W_E_};
    RoundDesc rd;
    long long ofs = n_vq; int blk = 0;
    const __half* wptr[NW];
    for (int i = 0; i < NW; i++) {
        rd.src[i] = (const float4*)srcs[i];
        rd.dofs[i] = ofs;
        rd.blkStart[i] = blk;
        wptr[i] = wb + ofs;
        ofs += cnts[i];
        blk += (int)(cnts[i] / 4096);
    }
    rd.blkStart[NW] = blk;
    const __half* w_vq = wb;
    const __half *w_vk = wptr[0], *w_vv = wptr[1], *w_vo = wptr[2];
    const __half *w_vg = wptr[3], *w_vu = wptr[4], *w_vd = wptr[5];
    const __half *w_eq = wptr[6], *w_ek = wptr[7], *w_ev = wptr[8], *w_eo = wptr[9];
    const __half *w_egw = wptr[10], *w_euw = wptr[11], *w_ed = wptr[12];

    const int SMG = 4 * STGB;   // 75776 B
    const int SMT = 4 * STG1;   // 81920 B
    cudaFuncSetAttribute(gemm16<0>, cudaFuncAttributeMaxDynamicSharedMemorySize, SMG);
    cudaFuncSetAttribute(gemm16<1>, cudaFuncAttributeMaxDynamicSharedMemorySize, SMG);
    cudaFuncSetAttribute(gemm16<2>, cudaFuncAttributeMaxDynamicSharedMemorySize, SMG);
    cudaFuncSetAttribute(gemm16<3>, cudaFuncAttributeMaxDynamicSharedMemorySize, SMG);
    cudaFuncSetAttribute(gemm16<4>, cudaFuncAttributeMaxDynamicSharedMemorySize, SMG);
    cudaFuncSetAttribute(gemm16_tb1, cudaFuncAttributeMaxDynamicSharedMemorySize, SMT);

    float* out_v = (float*)d_out;
    float* out_e = (float*)d_out + (long long)B_ * S_V_ * W_V_;

    long long sHv = (long long)S_V_ * W_V_, sHe = (long long)S_E_ * W_E_;
    long long sQ = (long long)S_ * H_ * DH_, sK = (long long)S_ * DH_;
    long long sL = (long long)S_ * S_;

    // L0..L2
    round4<<<(int)((n_vq / 4 + 255) / 256), 256>>>((const float4*)vlm_q_w, (__half2*)wb, (int)(n_vq / 4));
    rms_scale<<<B_ * S_V_, 256>>>(embeds_vlm, vlm_ln1_w, hv, W_V_);
    modmm2<<<dim3(48, B_), 256>>>(cond, exp_ln1_dw, exp_ln1_db, mod1);
    // L3: VLM Q projection (ncu target)
    gemm16<0><<<dim3(16, 6, B_), 128, SMG>>>(hv, w_vq, q, nullptr, nullptr, S_V_, H_ * DH_, W_V_, sHv, 0, sQ, 1);
    // L4..L6
    round_many<<<blk, 256>>>(rd, wb);
    rms_mod<<<B_ * S_E_, 256>>>(embeds_exp, mod1, he, W_E_, S_E_);
    modmm2<<<dim3(48, B_), 256>>>(cond, exp_ln2_dw, exp_ln2_db, mod2);

    // QKV remainder
    gemm16<0><<<dim3(16, 1, B_), 128, SMG>>>(he, w_eq, q + (long long)S_V_ * H_ * DH_, nullptr, nullptr, S_E_, H_ * DH_, W_E_, sHe, 0, sQ, 1);
    gemm16<0><<<dim3(2, 6, B_), 128, SMG>>>(hv, w_vk, k, nullptr, nullptr, S_V_, DH_, W_V_, sHv, 0, sK, 1);
    gemm16<0><<<dim3(2, 1, B_), 128, SMG>>>(he, w_ek, k + S_V_ * DH_, nullptr, nullptr, S_E_, DH_, W_E_, sHe, 0, sK, 1);
    gemm16<0><<<dim3(2, 6, B_), 128, SMG>>>(hv, w_vv, v, nullptr, nullptr, S_V_, DH_, W_V_, sHv, 0, sK, 1);
    gemm16<0><<<dim3(2, 1, B_), 128, SMG>>>(he, w_ev, v + S_V_ * DH_, nullptr, nullptr, S_E_, DH_, W_E_, sHe, 0, sK, 1);

    // RoPE
    rope4h<<<(B_ * S_ * H_ * 32 + 255) / 256, 256>>>(q, pos, H_);
    rope4h<<<(B_ * S_ * 1 * 32 + 255) / 256, 256>>>(k, pos, 1);

    // attention
    {
        int nq8 = B_ * H_ * S_ * 32;
        q_to_bhsd8h<<<(nq8 + 255) / 256, 256>>>((const uint4*)q, (uint4*)qt);
        gemm16_tb1<<<dim3(7, 7, B_ * H_), 256, SMT>>>(qt, k, logits, S_, S_, DH_, sK, sK, sL, H_);
        softmax4h<<<B_ * H_ * S_, 256>>>(logits, attn_mask, probs);
        gemm16<0><<<dim3(2, 7, B_ * H_), 128, SMG>>>(probs, v, attnt, nullptr, nullptr, S_, DH_, S_, sL, sK, sK, H_);
        bhsd_to_bshd8h<<<(nq8 + 255) / 256, 256>>>((const uint4*)attnt, (uint4*)attn);
    }

    // output projections + residuals
    {
        long long sA = (long long)S_ * H_ * DH_;
        gemm16<3><<<dim3(16, 6, B_), 128, SMG>>>(attn, w_vo, hv1, embeds_vlm, nullptr, S_V_, W_V_, H_ * DH_, sA, 0, sHv, 1);
        gemm16<4><<<dim3(8, 1, B_), 128, SMG>>>(attn + (long long)S_V_ * H_ * DH_, w_eo, he1, embeds_exp, mod1, S_E_, W_E_, H_ * DH_, sA, 0, sHe, 1);
    }

    // pre-MLP norms
    rms_scale<<<B_ * S_V_, 256>>>(hv1, vlm_ln2_w, hv, W_V_);
    rms_mod<<<B_ * S_E_, 256>>>(he1, mod2, he, W_E_, S_E_);

    // VLM MLP
    {
        int M = B_ * S_V_;
        gemm16<1><<<dim3(128, 24, 1), 128, SMG>>>(hv, w_vu, mu, nullptr, nullptr, M, MLPV_, W_V_, 0, 0, 0, 1);
        gemm16<2><<<dim3(128, 24, 1), 128, SMG>>>(hv, w_vg, mg, mu, nullptr, M, MLPV_, W_V_, 0, 0, 0, 1);
        gemm16<3><<<dim3(16, 24, 1), 128, SMG>>>(mg, w_vd, out_v, hv1, nullptr, M, W_V_, MLPV_, 0, 0, 0, 1);
    }

    // expert MLP
    {
        int M = B_ * S_E_;
        gemm16<1><<<dim3(32, 2, 1), 128, SMG>>>(he, w_euw, eu, nullptr, nullptr, M, MLPE_, W_E_, 0, 0, 0, 1);
        gemm16<2><<<dim3(32, 2, 1), 128, SMG>>>(he, w_egw, eg, eu, nullptr, M, MLPE_, W_E_, 0, 0, 0, 1);
        gemm16<4><<<dim3(8, 2, 1), 128, SMG>>>(eg, w_ed, out_e, he1, mod2, M, W_E_, MLPE_, 0, 0, 0, 1);
    }
}

// round 11
// speedup vs baseline: 1.0940x; 1.0940x over previous
#include <cuda_runtime.h>
#include <cuda_fp16.h>
#include <cuda_bf16.h>
#include <math.h>

#define B_    4
#define S_V_  768
#define S_E_  64
#define S_    832
#define W_V_  2048
#define W_E_  1024
#define H_    8
#define DH_   256
#define MLPV_ 16384
#define MLPE_ 4096
#define EPS_  1e-6f
#define SCALE_ 0.0625f

// ---------------- scratch ----------------
__device__ __half g_hv   [B_*S_V_*W_V_];
__device__ __half g_he   [B_*S_E_*W_E_];
__device__ float  g_mod1 [B_*3*W_E_];
__device__ float  g_mod2 [B_*3*W_E_];
__device__ __half g_q    [(long long)B_*S_*H_*DH_];
__device__ __half g_qt   [(long long)B_*H_*S_*DH_];
__device__ __half g_k    [B_*S_*DH_];
__device__ __half g_v    [B_*S_*DH_];
__device__ float  g_logits[(long long)B_*H_*S_*S_];
__device__ __half g_probs[(long long)B_*H_*S_*S_];
__device__ __half g_attnt[(long long)B_*H_*S_*DH_];
__device__ __half g_attn [(long long)B_*S_*H_*DH_];
__device__ float  g_hv1  [B_*S_V_*W_V_];
__device__ float  g_he1  [B_*S_E_*W_E_];
__device__ __half g_mg   [(long long)B_*S_V_*MLPV_];
__device__ __half g_mu   [(long long)B_*S_V_*MLPV_];
__device__ __half g_eg   [B_*S_E_*MLPE_];
__device__ __half g_eu   [B_*S_E_*MLPE_];
__device__ __half g_wbuf [127401984];

__device__ __forceinline__ float gelu_t(float x) {
    return 0.5f * x * (1.f + tanhf(0.7978845608028654f * (x + 0.044715f * x * x * x)));
}

__device__ __forceinline__ void mma_f16(float* c, const unsigned* a, const unsigned* b) {
    asm volatile(
        "mma.sync.aligned.m16n8k16.row.col.f32.f16.f16.f32 "
        "{%0,%1,%2,%3}, {%4,%5,%6,%7}, {%8,%9}, {%0,%1,%2,%3};\n"
        : "+f"(c[0]), "+f"(c[1]), "+f"(c[2]), "+f"(c[3])
        : "r"(a[0]), "r"(a[1]), "r"(a[2]), "r"(a[3]), "r"(b[0]), "r"(b[1]));
}

// ============ gemm16: fp16 operands, fp32 accum, TB=0 (R8 proven) ============
// Block 128x128, 256 thr, 8 warps (2m x 4n) of 64x32, K-tile 32, 4 stages.
// EPI: 0 plain->fp16, 1 plain->fp32, 3 fp32(c+aux), 4 fp32 gated residual,
//      5 fp16(gelu(c)*auxh)  [aux reinterpreted as __half*, z must be 0]
#define ASTB 10240
#define STGB 18944
template<int EPI>
__global__ __launch_bounds__(256, 2)
void gemm16(const __half* __restrict__ A, const __half* __restrict__ Bm,
            void* __restrict__ Cv, const float* __restrict__ aux,
            const float* __restrict__ modv,
            int M, int N, int K,
            long long sA, long long sB, long long sC, int bInner)
{
    extern __shared__ __align__(16) char sm[];

    const int z = blockIdx.z;
    A  += (long long)z * sA;
    Bm += (long long)(z / bInner) * sB;

    const int tid  = threadIdx.x;
    const int lane = tid & 31;
    const int wid  = tid >> 5;
    const int wm   = (wid & 1) * 64;
    const int wn   = (wid >> 1) * 32;
    const int bm   = blockIdx.y * 128;
    const int bn   = blockIdx.x * 128;
    const int row  = lane >> 2, col = lane & 3;

    unsigned sbase = (unsigned)__cvta_generic_to_shared(sm);

    auto issue = [&](int st) {
        const int ktE = st * 32;
        const unsigned sb = sbase + (unsigned)((st & 3) * STGB);
#pragma unroll
        for (int j = 0; j < 2; j++) {
            int id = tid + j * 256;
            int r = id >> 2, c = id & 3;
            int gm = bm + r;
            const __half* gp = A + (long long)(gm < M ? gm : M - 1) * K + ktE + c * 8;
            unsigned dst = sb + (unsigned)(r * 80 + c * 16);
            int zf = (gm < M) ? 16 : 0;
            asm volatile("cp.async.cg.shared.global [%0], [%1], 16, %2;\n"
                         :: "r"(dst), "l"(gp), "r"(zf));
        }
#pragma unroll
        for (int j = 0; j < 2; j++) {
            int id = tid + j * 256;
            int kr = id >> 4, c = id & 15;
            int gn = bn + c * 8;
            const __half* gp = Bm + (long long)(ktE + kr) * N + (gn < N ? gn : N - 8);
            unsigned dst = sb + (unsigned)(ASTB + kr * 272 + c * 16);
            int zf = (gn < N) ? 16 : 0;
            asm volatile("cp.async.cg.shared.global [%0], [%1], 16, %2;\n"
                         :: "r"(dst), "l"(gp), "r"(zf));
        }
    };

    float c[4][4][4];
#pragma unroll
    for (int i = 0; i < 4; i++)
#pragma unroll
        for (int j = 0; j < 4; j++)
#pragma unroll
            for (int l = 0; l < 4; l++) c[i][j][l] = 0.f;

    const unsigned aoff = (unsigned)((((lane >> 3) & 1) * 8 + (lane & 7)) * 80 + (lane >> 4) * 16);
    const int l16 = lane & 15;
    const unsigned boff = (unsigned)(ASTB + ((l16 >> 3) * 8 + (l16 & 7)) * 272 + wn * 2);

    const int nk = K / 32;
#pragma unroll 1
    for (int s = 0; s < 3; s++) { issue(s); asm volatile("cp.async.commit_group;\n"); }

#pragma unroll 1
    for (int kt = 0; kt < nk; kt++) {
        asm volatile("cp.async.wait_group 2;\n");
        __syncthreads();
        if (kt + 3 < nk) issue(kt + 3);
        asm volatile("cp.async.commit_group;\n");

        const unsigned stg = sbase + (unsigned)((kt & 3) * STGB);
#pragma unroll
        for (int sub = 0; sub < 2; sub++) {
            unsigned af[4][4], bf[4][2];
#pragma unroll
            for (int mt = 0; mt < 4; mt++) {
                unsigned ad = stg + (unsigned)((wm + mt * 16) * 80 + sub * 32) + aoff;
                asm volatile("ldmatrix.sync.aligned.m8n8.x4.shared.b16 {%0,%1,%2,%3}, [%4];"
                             : "=r"(af[mt][0]), "=r"(af[mt][1]), "=r"(af[mt][2]), "=r"(af[mt][3])
                             : "r"(ad));
            }
#pragma unroll
            for (int nt = 0; nt < 4; nt++) {
                unsigned bd = stg + (unsigned)(sub * 16 * 272 + nt * 16) + boff;
                asm volatile("ldmatrix.sync.aligned.m8n8.x2.trans.shared.b16 {%0,%1}, [%2];"
                             : "=r"(bf[nt][0]), "=r"(bf[nt][1]) : "r"(bd));
            }
#pragma unroll
            for (int mt = 0; mt < 4; mt++)
#pragma unroll
                for (int nt = 0; nt < 4; nt++)
                    mma_f16(c[mt][nt], af[mt], bf[nt]);
        }
    }

    if (EPI == 3 || EPI == 4) aux += (long long)z * sC;
    __half* Ch = (__half*)Cv + (long long)z * sC;
    float*  Cf = (float*)Cv + (long long)z * sC;
    const __half* auxh = (const __half*)(const void*)aux;   // EPI5 (z==0 only)

    auto epi_store = [&](int gm, int gn, float x0, float x1) {
        long long o = (long long)gm * N + gn;
        if (EPI == 0) {
            *(__half2*)(Ch + o) = __halves2half2(__float2half_rn(x0), __float2half_rn(x1));
        } else if (EPI == 1) {
            *(float2*)(Cf + o) = make_float2(x0, x1);
        } else if (EPI == 3) {
            float2 u = *(const float2*)(aux + o);
            *(float2*)(Cf + o) = make_float2(x0 + u.x, x1 + u.y);
        } else if (EPI == 4) {
            int bb = z + gm / S_E_;
            float g0 = modv[(long long)bb * 3 * W_E_ + 2 * W_E_ + gn];
            float g1 = modv[(long long)bb * 3 * W_E_ + 2 * W_E_ + gn + 1];
            float2 u = *(const float2*)(aux + o);
            *(float2*)(Cf + o) = make_float2(u.x + x0 * g0, u.y + x1 * g1);
        } else {  // EPI == 5
            __half2 u = *(const __half2*)(auxh + o);
            *(__half2*)(Ch + o) = __halves2half2(
                __float2half_rn(gelu_t(x0) * __low2float(u)),
                __float2half_rn(gelu_t(x1) * __high2float(u)));
        }
    };

#pragma unroll
    for (int mt = 0; mt < 4; mt++) {
#pragma unroll
        for (int nt = 0; nt < 4; nt++) {
            int gm = bm + wm + mt * 16 + row;
            int gn = bn + wn + nt * 8 + col * 2;
            if (gn < N) {
                if (gm < M)     epi_store(gm,     gn, c[mt][nt][0], c[mt][nt][1]);
                if (gm + 8 < M) epi_store(gm + 8, gn, c[mt][nt][2], c[mt][nt][3]);
            }
        }
    }
}

// ============ gemm16m64: 64x128 tile, 128 thr (4 warps 1m x 4n of 64x32), 3 stages ====
// For wave-starved GEMMs (384-tile shapes -> 768 finer tiles). EPI: 0 fp16, 3 fp32 c+aux.
#define A64B 5120
#define STG64 (A64B + 8704)   // 13824 B per stage
template<int EPI>
__global__ __launch_bounds__(128, 4)
void gemm16m64(const __half* __restrict__ A, const __half* __restrict__ Bm,
               void* __restrict__ Cv, const float* __restrict__ aux,
               int M, int N, int K, long long sA, long long sC)
{
    extern __shared__ __align__(16) char sm[];

    const int z = blockIdx.z;
    A += (long long)z * sA;

    const int tid  = threadIdx.x;
    const int lane = tid & 31;
    const int wid  = tid >> 5;
    const int wn   = wid * 32;
    const int bm   = blockIdx.y * 64;
    const int bn   = blockIdx.x * 128;
    const int row  = lane >> 2, col = lane & 3;

    unsigned sbase = (unsigned)__cvta_generic_to_shared(sm);

    auto issue = [&](int st) {
        const int ktE = st * 32;
        const unsigned sb = sbase + (unsigned)((st % 3) * STG64);
#pragma unroll
        for (int j = 0; j < 2; j++) {            // A: 64 rows x 32 halfs
            int id = tid + j * 128;
            int r = id >> 2, c = id & 3;
            int gm = bm + r;
            const __half* gp = A + (long long)(gm < M ? gm : M - 1) * K + ktE + c * 8;
            unsigned dst = sb + (unsigned)(r * 80 + c * 16);
            int zf = (gm < M) ? 16 : 0;
            asm volatile("cp.async.cg.shared.global [%0], [%1], 16, %2;\n"
                         :: "r"(dst), "l"(gp), "r"(zf));
        }
#pragma unroll
        for (int j = 0; j < 4; j++) {            // B: 32 rows x 128 halfs
            int id = tid + j * 128;
            int kr = id >> 4, c = id & 15;
            int gn = bn + c * 8;
            const __half* gp = Bm + (long long)(ktE + kr) * N + (gn < N ? gn : N - 8);
            unsigned dst = sb + (unsigned)(A64B + kr * 272 + c * 16);
            int zf = (gn < N) ? 16 : 0;
            asm volatile("cp.async.cg.shared.global [%0], [%1], 16, %2;\n"
                         :: "r"(dst), "l"(gp), "r"(zf));
        }
    };

    float c[4][4][4];
#pragma unroll
    for (int i = 0; i < 4; i++)
#pragma unroll
        for (int j = 0; j < 4; j++)
#pragma unroll
            for (int l = 0; l < 4; l++) c[i][j][l] = 0.f;

    const unsigned aoff = (unsigned)((((lane >> 3) & 1) * 8 + (lane & 7)) * 80 + (lane >> 4) * 16);
    const int l16 = lane & 15;
    const unsigned boff = (unsigned)(A64B + ((l16 >> 3) * 8 + (l16 & 7)) * 272 + wn * 2);

    const int nk = K / 32;
    issue(0); asm volatile("cp.async.commit_group;\n");
    issue(1); asm volatile("cp.async.commit_group;\n");

#pragma unroll 1
    for (int kt = 0; kt < nk; kt++) {
        asm volatile("cp.async.wait_group 1;\n");
        __syncthreads();
        if (kt + 2 < nk) issue(kt + 2);
        asm volatile("cp.async.commit_group;\n");

        const unsigned stg = sbase + (unsigned)((kt % 3) * STG64);
#pragma unroll
        for (int sub = 0; sub < 2; sub++) {
            unsigned af[4][4], bf[4][2];
#pragma unroll
            for (int mt = 0; mt < 4; mt++) {
                unsigned ad = stg + (unsigned)((mt * 16) * 80 + sub * 32) + aoff;
                asm volatile("ldmatrix.sync.aligned.m8n8.x4.shared.b16 {%0,%1,%2,%3}, [%4];"
                             : "=r"(af[mt][0]), "=r"(af[mt][1]), "=r"(af[mt][2]), "=r"(af[mt][3])
                             : "r"(ad));
            }
#pragma unroll
            for (int nt = 0; nt < 4; nt++) {
                unsigned bd = stg + (unsigned)(sub * 16 * 272 + nt * 16) + boff;
                asm volatile("ldmatrix.sync.aligned.m8n8.x2.trans.shared.b16 {%0,%1}, [%2];"
                             : "=r"(bf[nt][0]), "=r"(bf[nt][1]) : "r"(bd));
            }
#pragma unroll
            for (int mt = 0; mt < 4; mt++)
#pragma unroll
                for (int nt = 0; nt < 4; nt++)
                    mma_f16(c[mt][nt], af[mt], bf[nt]);
        }
    }

    if (EPI == 3) aux += (long long)z * sC;
    __half* Ch = (__half*)Cv + (long long)z * sC;
    float*  Cf = (float*)Cv + (long long)z * sC;

#pragma unroll
    for (int mt = 0; mt < 4; mt++) {
#pragma unroll
        for (int nt = 0; nt < 4; nt++) {
            int gm = bm + mt * 16 + row;
            int gn = bn + wn + nt * 8 + col * 2;
            if (gn >= N) continue;
#pragma unroll
            for (int hh = 0; hh < 2; hh++) {
                int g = gm + hh * 8;
                if (g >= M) continue;
                long long o = (long long)g * N + gn;
                float x0 = c[mt][nt][hh * 2], x1 = c[mt][nt][hh * 2 + 1];
                if (EPI == 0) {
                    *(__half2*)(Ch + o) = __halves2half2(__float2half_rn(x0), __float2half_rn(x1));
                } else {
                    float2 u = *(const float2*)(aux + o);
                    *(float2*)(Cf + o) = make_float2(x0 + u.x, x1 + u.y);
                }
            }
        }
    }
}

// ============ gemm16_tb1: fp16, B (N,K) row-major, fp32 out (proven R8) ============
#define STG1 20480
__global__ __launch_bounds__(256, 2)
void gemm16_tb1(const __half* __restrict__ A, const __half* __restrict__ Bm,
                float* __restrict__ C, int M, int N, int K,
                long long sA, long long sB, long long sC, int bInner)
{
    extern __shared__ __align__(16) char sm[];

    const int z = blockIdx.z;
    A  += (long long)z * sA;
    Bm += (long long)(z / bInner) * sB;
    C  += (long long)z * sC;

    const int tid  = threadIdx.x;
    const int lane = tid & 31;
    const int wid  = tid >> 5;
    const int wm   = (wid & 1) * 64;
    const int wn   = (wid >> 1) * 32;
    const int bm   = blockIdx.y * 128;
    const int bn   = blockIdx.x * 128;
    const int row  = lane >> 2, col = lane & 3;

    unsigned sbase = (unsigned)__cvta_generic_to_shared(sm);

    auto issue = [&](int st) {
        const int ktE = st * 32;
        const unsigned sb = sbase + (unsigned)((st & 3) * STG1);
#pragma unroll
        for (int j = 0; j < 2; j++) {
            int id = tid + j * 256;
            int r = id >> 2, c = id & 3;
            int gm = bm + r;
            const __half* gp = A + (long long)(gm < M ? gm : M - 1) * K + ktE + c * 8;
            unsigned dst = sb + (unsigned)(r * 80 + c * 16);
            int zf = (gm < M) ? 16 : 0;
            asm volatile("cp.async.cg.shared.global [%0], [%1], 16, %2;\n"
                         :: "r"(dst), "l"(gp), "r"(zf));
        }
#pragma unroll
        for (int j = 0; j < 2; j++) {
            int id = tid + j * 256;
            int r = id >> 2, c = id & 3;
            int gn = bn + r;
            const __half* gp = Bm + (long long)(gn < N ? gn : N - 1) * K + ktE + c * 8;
            unsigned dst = sb + (unsigned)(ASTB + r * 80 + c * 16);
            int zf = (gn < N) ? 16 : 0;
            asm volatile("cp.async.cg.shared.global [%0], [%1], 16, %2;\n"
                         :: "r"(dst), "l"(gp), "r"(zf));
        }
    };

    float c[4][4][4];
#pragma unroll
    for (int i = 0; i < 4; i++)
#pragma unroll
        for (int j = 0; j < 4; j++)
#pragma unroll
            for (int l = 0; l < 4; l++) c[i][j][l] = 0.f;

    const unsigned aoff = (unsigned)((((lane >> 3) & 1) * 8 + (lane & 7)) * 80 + (lane >> 4) * 16);
    const int l16 = lane & 15;
    const unsigned boff = (unsigned)(ASTB + ((l16 & 7) + wn) * 80 + (l16 >> 3) * 16);

    const int nk = K / 32;
#pragma unroll 1
    for (int s = 0; s < 3; s++) { issue(s); asm volatile("cp.async.commit_group;\n"); }

#pragma unroll 1
    for (int kt = 0; kt < nk; kt++) {
        asm volatile("cp.async.wait_group 2;\n");
        __syncthreads();
        if (kt + 3 < nk) issue(kt + 3);
        asm volatile("cp.async.commit_group;\n");

        const unsigned stg = sbase + (unsigned)((kt & 3) * STG1);
#pragma unroll
        for (int sub = 0; sub < 2; sub++) {
            unsigned af[4][4], bf[4][2];
#pragma unroll
            for (int mt = 0; mt < 4; mt++) {
                unsigned ad = stg + (unsigned)((wm + mt * 16) * 80 + sub * 32) + aoff;
                asm volatile("ldmatrix.sync.aligned.m8n8.x4.shared.b16 {%0,%1,%2,%3}, [%4];"
                             : "=r"(af[mt][0]), "=r"(af[mt][1]), "=r"(af[mt][2]), "=r"(af[mt][3])
                             : "r"(ad));
            }
#pragma unroll
            for (int nt = 0; nt < 4; nt++) {
                unsigned bd = stg + (unsigned)(nt * 8 * 80 + sub * 32) + boff;
                asm volatile("ldmatrix.sync.aligned.m8n8.x2.shared.b16 {%0,%1}, [%2];"
                             : "=r"(bf[nt][0]), "=r"(bf[nt][1]) : "r"(bd));
            }
#pragma unroll
            for (int mt = 0; mt < 4; mt++)
#pragma unroll
                for (int nt = 0; nt < 4; nt++)
                    mma_f16(c[mt][nt], af[mt], bf[nt]);
        }
    }

#pragma unroll
    for (int mt = 0; mt < 4; mt++) {
#pragma unroll
        for (int nt = 0; nt < 4; nt++) {
            int gm = bm + wm + mt * 16 + row;
            int gn = bn + wn + nt * 8 + col * 2;
            if (gn < N) {
                if (gm < M)
                    *(float2*)(C + (long long)gm * N + gn) = make_float2(c[mt][nt][0], c[mt][nt][1]);
                if (gm + 8 < M)
                    *(float2*)(C + (long long)(gm + 8) * N + gn) = make_float2(c[mt][nt][2], c[mt][nt][3]);
            }
        }
    }
}

// ---------------- weight fp16 pre-convert ----------------
__global__ void round4(const float4* __restrict__ s, __half2* __restrict__ d, int n4)
{
    int i = blockIdx.x * 256 + threadIdx.x;
    if (i >= n4) return;
    float4 v = s[i];
    d[i * 2]     = __floats2half2_rn(v.x, v.y);
    d[i * 2 + 1] = __floats2half2_rn(v.z, v.w);
}

#define NW 13
struct RoundDesc {
    const float4* src[NW];
    long long dofs[NW];
    int blkStart[NW + 1];
};

__global__ void round_many(RoundDesc d, __half* __restrict__ wbuf)
{
    int b = blockIdx.x;
    int w = 0;
#pragma unroll
    for (int i = 0; i < NW; i++) if (b >= d.blkStart[i + 1]) w = i + 1;
    int lb = b - d.blkStart[w];
    const float4* s = d.src[w] + (long long)lb * 1024;
    __half2* o = (__half2*)(wbuf + d.dofs[w]) + (long long)lb * 2048;
    int t = threadIdx.x;
#pragma unroll
    for (int i = 0; i < 4; i++) {
        float4 v = s[t + i * 256];
        o[(t + i * 256) * 2]     = __floats2half2_rn(v.x, v.y);
        o[(t + i * 256) * 2 + 1] = __floats2half2_rn(v.z, v.w);
    }
}

// ---------------- row kernels ----------------
__device__ __forceinline__ float blockReduceSum(float v) {
    __shared__ float red[256];
    int t = threadIdx.x;
    red[t] = v; __syncthreads();
    for (int s = 128; s > 0; s >>= 1) {
        if (t < s) red[t] += red[t + s];
        __syncthreads();
    }
    float r = red[0];
    __syncthreads();
    return r;
}

__global__ void rms_scale(const float* __restrict__ x, const float* __restrict__ w,
                          __half* __restrict__ out, int W)
{
    long long base = (long long)blockIdx.x * W;
    float ss = 0.f;
    for (int c = threadIdx.x; c < W; c += 256) { float t = x[base + c]; ss += t * t; }
    float tot = blockReduceSum(ss);
    float inv = rsqrtf(tot / (float)W + EPS_);
    for (int c = threadIdx.x; c < W; c += 256)
        out[base + c] = __float2half_rn(x[base + c] * inv * (1.f + w[c]));
}

__global__ void rms_mod(const float* __restrict__ x, const float* __restrict__ mod,
                        __half* __restrict__ out, int W, int rowsPerB)
{
    long long base = (long long)blockIdx.x * W;
    int b = blockIdx.x / rowsPerB;
    const float* m = mod + (long long)b * 3 * W;
    float ss = 0.f;
    for (int c = threadIdx.x; c < W; c += 256) { float t = x[base + c]; ss += t * t; }
    float tot = blockReduceSum(ss);
    float inv = rsqrtf(tot / (float)W + EPS_);
    for (int c = threadIdx.x; c < W; c += 256)
        out[base + c] = __float2half_rn(x[base + c] * inv * (1.f + m[c]) + m[W + c]);
}

__global__ void modmm2(const float* __restrict__ cond, const float* __restrict__ W,
                       const float* __restrict__ bias, float* __restrict__ out)
{
    const int NT = 3 * W_E_;
    __shared__ float cs[W_E_];
    __shared__ float part[4][64];
    int bb = blockIdx.y;
    int tid = threadIdx.x;
    for (int i = tid; i < W_E_; i += 256) cs[i] = cond[bb * W_E_ + i];
    __syncthreads();
    int tx = tid & 63, ty = tid >> 6;
    int c = blockIdx.x * 64 + tx;
    const float* Wp = W + (long long)(ty * 256) * NT + c;
    const float* cp = cs + ty * 256;
    float s = 0.f;
#pragma unroll 4
    for (int k = 0; k < 256; k++) s += cp[k] * Wp[(long long)k * NT];
    part[ty][tx] = s;
    __syncthreads();
    if (ty == 0)
        out[(long long)bb * NT + c] = part[0][tx] + part[1][tx] + part[2][tx] + part[3][tx] + bias[c];
}

__global__ void rope4h(__half* __restrict__ x, const int* __restrict__ pos, int nh)
{
    int idx = blockIdx.x * blockDim.x + threadIdx.x;
    int total = B_ * S_ * nh * 32;
    if (idx >= total) return;
    int d4 = (idx & 31) << 2;
    int h = (idx >> 5) % nh;
    int s = (idx / (32 * nh)) % S_;
    int b = idx / (32 * nh * S_);
    float p = (float)pos[b * S_ + s];
    __half* base = x + (((long long)(b * S_ + s) * nh + h) << 8);
    __half2 x1a = *(__half2*)(base + d4),       x1b = *(__half2*)(base + d4 + 2);
    __half2 x2a = *(__half2*)(base + d4 + 128), x2b = *(__half2*)(base + d4 + 130);
    float r1[4] = {__low2float(x1a), __high2float(x1a), __low2float(x1b), __high2float(x1b)};
    float r2[4] = {__low2float(x2a), __high2float(x2a), __low2float(x2b), __high2float(x2b)};
#pragma unroll
    for (int j = 0; j < 4; j++) {
        float ang = p * powf(10000.f, -(float)(2 * (d4 + j)) / 256.f);
        float sn, cs2; sincosf(ang, &sn, &cs2);
        float a = r1[j], bb = r2[j];
        r1[j] = a * cs2 - bb * sn;
        r2[j] = bb * cs2 + a * sn;
    }
    *(__half2*)(base + d4)       = __floats2half2_rn(r1[0], r1[1]);
    *(__half2*)(base + d4 + 2)   = __floats2half2_rn(r1[2], r1[3]);
    *(__half2*)(base + d4 + 128) = __floats2half2_rn(r2[0], r2[1]);
    *(__half2*)(base + d4 + 130) = __floats2half2_rn(r2[2], r2[3]);
}

__global__ void q_to_bhsd8h(const uint4* __restrict__ q, uint4* __restrict__ qt)
{
    int idx = blockIdx.x * blockDim.x + threadIdx.x;
    int total = B_ * H_ * S_ * 32;
    if (idx >= total) return;
    int d = idx & 31;
    int s = (idx >> 5) % S_;
    int h = (idx / (32 * S_)) % H_;
    int b = idx / (32 * S_ * H_);
    qt[idx] = q[(((b * S_ + s) * H_ + h) * 32) + d];
}

__global__ void bhsd_to_bshd8h(const uint4* __restrict__ a, uint4* __restrict__ o)
{
    int idx = blockIdx.x * blockDim.x + threadIdx.x;
    int total = B_ * S_ * H_ * 32;
    if (idx >= total) return;
    int d = idx & 31;
    int h = (idx >> 5) % H_;
    int s = (idx / (32 * H_)) % S_;
    int b = idx / (32 * H_ * S_);
    o[idx] = a[(((b * H_ + h) * S_ + s) * 32) + d];
}

__global__ void softmax4h(const float* __restrict__ logits, const float* __restrict__ mask,
                          __half* __restrict__ probs)
{
    int rowid = blockIdx.x;
    int b = rowid / (H_ * S_);
    int q = rowid % S_;
    const float4* row = (const float4*)(logits + (long long)rowid * S_);
    const float4* m = (const float4*)(mask + ((long long)b * S_ + q) * S_);
    __half* prow = probs + (long long)rowid * S_;
    int t = threadIdx.x;
    const bool act = t < 208;
    float4 v = make_float4(-1e30f, -1e30f, -1e30f, -1e30f);
    if (act) {
        float4 lv = row[t], mv = m[t];
        v.x = lv.x * SCALE_ + mv.x; v.y = lv.y * SCALE_ + mv.y;
        v.z = lv.z * SCALE_ + mv.z; v.w = lv.w * SCALE_ + mv.w;
    }
    float mx = fmaxf(fmaxf(v.x, v.y), fmaxf(v.z, v.w));
    __shared__ float red[256];
    red[t] = mx; __syncthreads();
    for (int s = 128; s > 0; s >>= 1) { if (t < s) red[t] = fmaxf(red[t], red[t + s]); __syncthreads(); }
    mx = red[0]; __syncthreads();
    float sum = 0.f;
    if (act) {
        v.x = __expf(v.x - mx); v.y = __expf(v.y - mx);
        v.z = __expf(v.z - mx); v.w = __expf(v.w - mx);
        sum = v.x + v.y + v.z + v.w;
    }
    red[t] = sum; __syncthreads();
    for (int s = 128; s > 0; s >>= 1) { if (t < s) red[t] += red[t + s]; __syncthreads(); }
    float inv = 1.f / red[0];
    if (act) {
        *(__half2*)(prow + t * 4)     = __floats2half2_rn(v.x * inv, v.y * inv);
        *(__half2*)(prow + t * 4 + 2) = __floats2half2_rn(v.z * inv, v.w * inv);
    }
}

// ---------------- host launch ----------------
#define GETSYMF(var, sym) do { void* p__; cudaGetSymbolAddress(&p__, sym); var = (float*)p__; } while (0)
#define GETSYMH(var, sym) do { void* p__; cudaGetSymbolAddress(&p__, sym); var = (__half*)p__; } while (0)

extern "C" void kernel_launch(void* const* d_in, const int* in_sizes, int n_in,
                              void* d_out, int out_size)
{
    const float *embeds_vlm, *embeds_exp, *cond, *attn_mask;
    const int* pos;
    const float *vlm_ln1_w, *vlm_ln2_w, *vlm_q_w, *vlm_k_w, *vlm_v_w, *vlm_o_w;
    const float *vlm_gate_w, *vlm_up_w, *vlm_down_w;
    const float *exp_ln1_dw, *exp_ln1_db, *exp_ln2_dw, *exp_ln2_db;
    const float *exp_q_w, *exp_k_w, *exp_v_w, *exp_o_w, *exp_gate_w, *exp_up_w, *exp_down_w;

    if (in_sizes[3] == B_ * S_) {
        embeds_vlm = (const float*)d_in[0];  embeds_exp = (const float*)d_in[1];
        cond       = (const float*)d_in[2];  pos        = (const int*)  d_in[3];
        attn_mask  = (const float*)d_in[4];
        vlm_ln1_w  = (const float*)d_in[5];  vlm_ln2_w  = (const float*)d_in[6];
        vlm_q_w    = (const float*)d_in[7];  vlm_k_w    = (const float*)d_in[8];
        vlm_v_w    = (const float*)d_in[9];  vlm_o_w    = (const float*)d_in[10];
        vlm_gate_w = (const float*)d_in[11]; vlm_up_w   = (const float*)d_in[12];
        vlm_down_w = (const float*)d_in[13];
        exp_ln1_dw = (const float*)d_in[14]; exp_ln1_db = (const float*)d_in[15];
        exp_ln2_dw = (const float*)d_in[16]; exp_ln2_db = (const float*)d_in[17];
        exp_q_w    = (const float*)d_in[18]; exp_k_w    = (const float*)d_in[19];
        exp_v_w    = (const float*)d_in[20]; exp_o_w    = (const float*)d_in[21];
        exp_gate_w = (const float*)d_in[22]; exp_up_w   = (const float*)d_in[23];
        exp_down_w = (const float*)d_in[24];
    } else {
        embeds_vlm = (const float*)d_in[0];  embeds_exp = (const float*)d_in[1];
        cond       = (const float*)d_in[2];
        vlm_ln1_w  = (const float*)d_in[3];  vlm_ln2_w  = (const float*)d_in[4];
        vlm_q_w    = (const float*)d_in[5];  vlm_k_w    = (const float*)d_in[6];
        vlm_v_w    = (const float*)d_in[7];  vlm_o_w    = (const float*)d_in[8];
        vlm_gate_w = (const float*)d_in[9];  vlm_up_w   = (const float*)d_in[10];
        vlm_down_w = (const float*)d_in[11];
        exp_ln1_dw = (const float*)d_in[12]; exp_ln1_db = (const float*)d_in[13];
        exp_ln2_dw = (const float*)d_in[14]; exp_ln2_db = (const float*)d_in[15];
        exp_q_w    = (const float*)d_in[16]; exp_k_w    = (const float*)d_in[17];
        exp_v_w    = (const float*)d_in[18]; exp_o_w    = (const float*)d_in[19];
        exp_gate_w = (const float*)d_in[20]; exp_up_w   = (const float*)d_in[21];
        exp_down_w = (const float*)d_in[22];
        pos        = (const int*)  d_in[23];
        attn_mask  = (const float*)d_in[24];
    }

    __half *hv, *he, *q, *qt, *k, *v, *probs, *attnt, *attn, *mg, *mu, *eg, *eu, *wb;
    float *mod1, *mod2, *logits, *hv1, *he1;
    GETSYMH(hv, g_hv);   GETSYMH(he, g_he);   GETSYMF(mod1, g_mod1); GETSYMF(mod2, g_mod2);
    GETSYMH(q, g_q);     GETSYMH(qt, g_qt);   GETSYMH(k, g_k);       GETSYMH(v, g_v);
    GETSYMF(logits, g_logits); GETSYMH(probs, g_probs);
    GETSYMH(attnt, g_attnt);   GETSYMH(attn, g_attn);
    GETSYMF(hv1, g_hv1); GETSYMF(he1, g_he1);
    GETSYMH(mg, g_mg);   GETSYMH(mu, g_mu);
    GETSYMH(eg, g_eg);   GETSYMH(eu, g_eu);   GETSYMH(wb, g_wbuf);

    const long long n_vq = (long long)W_V_ * H_ * DH_;
    const float* srcs[NW] = {vlm_k_w, vlm_v_w, vlm_o_w, vlm_gate_w, vlm_up_w, vlm_down_w,
                             exp_q_w, exp_k_w, exp_v_w, exp_o_w, exp_gate_w, exp_up_w, exp_down_w};
    long long cnts[NW] = {
        (long long)W_V_*DH_, (long long)W_V_*DH_, (long long)H_*DH_*W_V_,
        (long long)W_V_*MLPV_, (long long)W_V_*MLPV_, (long long)MLPV_*W_V_,
        (long long)W_E_*H_*DH_, (long long)W_E_*DH_, (long long)W_E_*DH_, (long long)H_*DH_*W_E_,
        (long long)W_E_*MLPE_, (long long)W_E_*MLPE_, (long long)MLPE_*W_E_};
    RoundDesc rd;
    long long ofs = n_vq; int blk = 0;
    const __half* wptr[NW];
    for (int i = 0; i < NW; i++) {
        rd.src[i] = (const float4*)srcs[i];
        rd.dofs[i] = ofs;
        rd.blkStart[i] = blk;
        wptr[i] = wb + ofs;
        ofs += cnts[i];
        blk += (int)(cnts[i] / 4096);
    }
    rd.blkStart[NW] = blk;
    const __half* w_vq = wb;
    const __half *w_vk = wptr[0], *w_vv = wptr[1], *w_vo = wptr[2];
    const __half *w_vg = wptr[3], *w_vu = wptr[4], *w_vd = wptr[5];
    const __half *w_eq = wptr[6], *w_ek = wptr[7], *w_ev = wptr[8], *w_eo = wptr[9];
    const __half *w_egw = wptr[10], *w_euw = wptr[11], *w_ed = wptr[12];

    const int SMG  = 4 * STGB;    // 75776 B
    const int SMT  = 4 * STG1;    // 81920 B
    const int SM64 = 3 * STG64;   // 41472 B
    cudaFuncSetAttribute(gemm16<0>, cudaFuncAttributeMaxDynamicSharedMemorySize, SMG);
    cudaFuncSetAttribute(gemm16<1>, cudaFuncAttributeMaxDynamicSharedMemorySize, SMG);
    cudaFuncSetAttribute(gemm16<3>, cudaFuncAttributeMaxDynamicSharedMemorySize, SMG);
    cudaFuncSetAttribute(gemm16<4>, cudaFuncAttributeMaxDynamicSharedMemorySize, SMG);
    cudaFuncSetAttribute(gemm16<5>, cudaFuncAttributeMaxDynamicSharedMemorySize, SMG);
    cudaFuncSetAttribute(gemm16_tb1, cudaFuncAttributeMaxDynamicSharedMemorySize, SMT);
    cudaFuncSetAttribute(gemm16m64<0>, cudaFuncAttributeMaxDynamicSharedMemorySize, SM64);
    cudaFuncSetAttribute(gemm16m64<3>, cudaFuncAttributeMaxDynamicSharedMemorySize, SM64);

    float* out_v = (float*)d_out;
    float* out_e = (float*)d_out + (long long)B_ * S_V_ * W_V_;

    long long sHv = (long long)S_V_ * W_V_, sHe = (long long)S_E_ * W_E_;
    long long sQ = (long long)S_ * H_ * DH_, sK = (long long)S_ * DH_;
    long long sL = (long long)S_ * S_;

    // L0..L2
    round4<<<(int)((n_vq / 4 + 255) / 256), 256>>>((const float4*)vlm_q_w, (__half2*)wb, (int)(n_vq / 4));
    rms_scale<<<B_ * S_V_, 256>>>(embeds_vlm, vlm_ln1_w, hv, W_V_);
    modmm2<<<dim3(48, B_), 256>>>(cond, exp_ln1_dw, exp_ln1_db, mod1);
    // L3: VLM Q projection on m64 tiles (ncu target): 768 blocks
    gemm16m64<0><<<dim3(16, 12, B_), 128, SM64>>>(hv, w_vq, q, nullptr, S_V_, H_ * DH_, W_V_, sHv, sQ);
    // L4..L6
    round_many<<<blk, 256>>>(rd, wb);
    rms_mod<<<B_ * S_E_, 256>>>(embeds_exp, mod1, he, W_E_, S_E_);
    modmm2<<<dim3(48, B_), 256>>>(cond, exp_ln2_dw, exp_ln2_db, mod2);

    // QKV remainder
    gemm16<0><<<dim3(16, 1, B_), 256, SMG>>>(he, w_eq, q + (long long)S_V_ * H_ * DH_, nullptr, nullptr, S_E_, H_ * DH_, W_E_, sHe, 0, sQ, 1);
    gemm16<0><<<dim3(2, 6, B_), 256, SMG>>>(hv, w_vk, k, nullptr, nullptr, S_V_, DH_, W_V_, sHv, 0, sK, 1);
    gemm16<0><<<dim3(2, 1, B_), 256, SMG>>>(he, w_ek, k + S_V_ * DH_, nullptr, nullptr, S_E_, DH_, W_E_, sHe, 0, sK, 1);
    gemm16<0><<<dim3(2, 6, B_), 256, SMG>>>(hv, w_vv, v, nullptr, nullptr, S_V_, DH_, W_V_, sHv, 0, sK, 1);
    gemm16<0><<<dim3(2, 1, B_), 256, SMG>>>(he, w_ev, v + S_V_ * DH_, nullptr, nullptr, S_E_, DH_, W_E_, sHe, 0, sK, 1);

    // RoPE
    rope4h<<<(B_ * S_ * H_ * 32 + 255) / 256, 256>>>(q, pos, H_);
    rope4h<<<(B_ * S_ * 1 * 32 + 255) / 256, 256>>>(k, pos, 1);

    // attention
    {
        int nq8 = B_ * H_ * S_ * 32;
        q_to_bhsd8h<<<(nq8 + 255) / 256, 256>>>((const uint4*)q, (uint4*)qt);
        gemm16_tb1<<<dim3(7, 7, B_ * H_), 256, SMT>>>(qt, k, logits, S_, S_, DH_, sK, sK, sL, H_);
        softmax4h<<<B_ * H_ * S_, 256>>>(logits, attn_mask, probs);
        gemm16<0><<<dim3(2, 7, B_ * H_), 256, SMG>>>(probs, v, attnt, nullptr, nullptr, S_, DH_, S_, sL, sK, sK, H_);
        bhsd_to_bshd8h<<<(nq8 + 255) / 256, 256>>>((const uint4*)attnt, (uint4*)attn);
    }

    // output projections + residuals
    {
        long long sA = (long long)S_ * H_ * DH_;
        gemm16m64<3><<<dim3(16, 12, B_), 128, SM64>>>(attn, w_vo, hv1, embeds_vlm, S_V_, W_V_, H_ * DH_, sA, sHv);
        gemm16<4><<<dim3(8, 1, B_), 256, SMG>>>(attn + (long long)S_V_ * H_ * DH_, w_eo, he1, embeds_exp, mod1, S_E_, W_E_, H_ * DH_, sA, 0, sHe, 1);
    }

    // pre-MLP norms
    rms_scale<<<B_ * S_V_, 256>>>(hv1, vlm_ln2_w, hv, W_V_);
    rms_mod<<<B_ * S_E_, 256>>>(he1, mod2, he, W_E_, S_E_);

    // VLM MLP: up (fp16 out), gate with fused gelu*up(fp16), down on m64 with residual
    {
        int M = B_ * S_V_;
        gemm16<0><<<dim3(128, 24, 1), 256, SMG>>>(hv, w_vu, mu, nullptr, nullptr, M, MLPV_, W_V_, 0, 0, 0, 1);
        gemm16<5><<<dim3(128, 24, 1), 256, SMG>>>(hv, w_vg, mg, (const float*)(const void*)mu, nullptr, M, MLPV_, W_V_, 0, 0, 0, 1);
        gemm16m64<3><<<dim3(16, 48, 1), 128, SM64>>>(mg, w_vd, out_v, hv1, M, W_V_, MLPV_, 0, 0);
    }

    // expert MLP
    {
        int M = B_ * S_E_;
        gemm16<0><<<dim3(32, 2, 1), 256, SMG>>>(he, w_euw, eu, nullptr, nullptr, M, MLPE_, W_E_, 0, 0, 0, 1);
        gemm16<5><<<dim3(32, 2, 1), 256, SMG>>>(he, w_egw, eg, (const float*)(const void*)eu, nullptr, M, MLPE_, W_E_, 0, 0, 0, 1);
        gemm16<4><<<dim3(8, 2, 1), 256, SMG>>>(eg, w_ed, out_e, he1, mod2, M, W_E_, MLPE_, 0, 0, 0, 1);
    }
}

// round 12
// speedup vs baseline: 1.1394x; 1.0416x over previous
#include <cuda_runtime.h>
#include <cuda_fp16.h>
#include <cuda_bf16.h>
#include <math.h>

#define B_    4
#define S_V_  768
#define S_E_  64
#define S_    832
#define W_V_  2048
#define W_E_  1024
#define H_    8
#define DH_   256
#define MLPV_ 16384
#define MLPE_ 4096
#define EPS_  1e-6f
#define SCALE_ 0.0625f

// ---------------- scratch ----------------
__device__ __half g_hv   [B_*S_V_*W_V_];
__device__ __half g_he   [B_*S_E_*W_E_];
__device__ float  g_mod1 [B_*3*W_E_];
__device__ float  g_mod2 [B_*3*W_E_];
__device__ __half g_q    [(long long)B_*S_*H_*DH_];
__device__ __half g_qt   [(long long)B_*H_*S_*DH_];
__device__ __half g_k    [B_*S_*DH_];
__device__ __half g_v    [B_*S_*DH_];
__device__ float  g_logits[(long long)B_*H_*S_*S_];
__device__ __half g_probs[(long long)B_*H_*S_*S_];
__device__ __half g_attnt[(long long)B_*H_*S_*DH_];
__device__ __half g_attn [(long long)B_*S_*H_*DH_];
__device__ float  g_hv1  [B_*S_V_*W_V_];
__device__ float  g_he1  [B_*S_E_*W_E_];
__device__ __half g_mg   [(long long)B_*S_V_*MLPV_];
__device__ __half g_mu   [(long long)B_*S_V_*MLPV_];
__device__ __half g_eg   [B_*S_E_*MLPE_];
__device__ __half g_eu   [B_*S_E_*MLPE_];
__device__ __half g_wbuf [127401984];

__device__ __forceinline__ float gelu_t(float x) {
    return 0.5f * x * (1.f + tanhf(0.7978845608028654f * (x + 0.044715f * x * x * x)));
}

__device__ __forceinline__ void mma_f16(float* c, const unsigned* a, const unsigned* b) {
    asm volatile(
        "mma.sync.aligned.m16n8k16.row.col.f32.f16.f16.f32 "
        "{%0,%1,%2,%3}, {%4,%5,%6,%7}, {%8,%9}, {%0,%1,%2,%3};\n"
        : "+f"(c[0]), "+f"(c[1]), "+f"(c[2]), "+f"(c[3])
        : "r"(a[0]), "r"(a[1]), "r"(a[2]), "r"(a[3]), "r"(b[0]), "r"(b[1]));
}

// ============ gemm16: fp16 operands, fp32 accum, TB=0 ============
// Block 128x128, 256 thr, 8 warps (2m x 4n) of 64x32, K-tile 32, 4 stages.
// B fragments via ldmatrix.x4.trans (2 n-tiles per instruction).
// EPI: 0 plain->fp16, 1 plain->fp32, 3 fp32(c+aux), 4 fp32 gated residual,
//      5 fp16(gelu(c)*auxh)  [aux reinterpreted as __half*, z must be 0]
#define ASTB 10240
#define STGB 18944
template<int EPI>
__global__ __launch_bounds__(256, 2)
void gemm16(const __half* __restrict__ A, const __half* __restrict__ Bm,
            void* __restrict__ Cv, const float* __restrict__ aux,
            const float* __restrict__ modv,
            int M, int N, int K,
            long long sA, long long sB, long long sC, int bInner)
{
    extern __shared__ __align__(16) char sm[];

    const int z = blockIdx.z;
    A  += (long long)z * sA;
    Bm += (long long)(z / bInner) * sB;

    const int tid  = threadIdx.x;
    const int lane = tid & 31;
    const int wid  = tid >> 5;
    const int wm   = (wid & 1) * 64;
    const int wn   = (wid >> 1) * 32;
    const int bm   = blockIdx.y * 128;
    const int bn   = blockIdx.x * 128;
    const int row  = lane >> 2, col = lane & 3;

    unsigned sbase = (unsigned)__cvta_generic_to_shared(sm);

    auto issue = [&](int st) {
        const int ktE = st * 32;
        const unsigned sb = sbase + (unsigned)((st & 3) * STGB);
#pragma unroll
        for (int j = 0; j < 2; j++) {
            int id = tid + j * 256;
            int r = id >> 2, c = id & 3;
            int gm = bm + r;
            const __half* gp = A + (long long)(gm < M ? gm : M - 1) * K + ktE + c * 8;
            unsigned dst = sb + (unsigned)(r * 80 + c * 16);
            int zf = (gm < M) ? 16 : 0;
            asm volatile("cp.async.cg.shared.global [%0], [%1], 16, %2;\n"
                         :: "r"(dst), "l"(gp), "r"(zf));
        }
#pragma unroll
        for (int j = 0; j < 2; j++) {
            int id = tid + j * 256;
            int kr = id >> 4, c = id & 15;
            int gn = bn + c * 8;
            const __half* gp = Bm + (long long)(ktE + kr) * N + (gn < N ? gn : N - 8);
            unsigned dst = sb + (unsigned)(ASTB + kr * 272 + c * 16);
            int zf = (gn < N) ? 16 : 0;
            asm volatile("cp.async.cg.shared.global [%0], [%1], 16, %2;\n"
                         :: "r"(dst), "l"(gp), "r"(zf));
        }
    };

    float c[4][4][4];
#pragma unroll
    for (int i = 0; i < 4; i++)
#pragma unroll
        for (int j = 0; j < 4; j++)
#pragma unroll
            for (int l = 0; l < 4; l++) c[i][j][l] = 0.f;

    const unsigned aoff = (unsigned)((((lane >> 3) & 1) * 8 + (lane & 7)) * 80 + (lane >> 4) * 16);
    // B x4.trans: matrices {k0-7@n, k8-15@n, k0-7@n+8, k8-15@n+8}
    const unsigned boff4 = (unsigned)(ASTB + (((lane >> 3) & 1) * 8 + (lane & 7)) * 272
                                      + (lane >> 4) * 16 + wn * 2);

    const int nk = K / 32;
#pragma unroll 1
    for (int s = 0; s < 3; s++) { issue(s); asm volatile("cp.async.commit_group;\n"); }

#pragma unroll 1
    for (int kt = 0; kt < nk; kt++) {
        asm volatile("cp.async.wait_group 2;\n");
        __syncthreads();
        if (kt + 3 < nk) issue(kt + 3);
        asm volatile("cp.async.commit_group;\n");

        const unsigned stg = sbase + (unsigned)((kt & 3) * STGB);
#pragma unroll
        for (int sub = 0; sub < 2; sub++) {
            unsigned af[4][4], bf[4][2];
#pragma unroll
            for (int mt = 0; mt < 4; mt++) {
                unsigned ad = stg + (unsigned)((wm + mt * 16) * 80 + sub * 32) + aoff;
                asm volatile("ldmatrix.sync.aligned.m8n8.x4.shared.b16 {%0,%1,%2,%3}, [%4];"
                             : "=r"(af[mt][0]), "=r"(af[mt][1]), "=r"(af[mt][2]), "=r"(af[mt][3])
                             : "r"(ad));
            }
#pragma unroll
            for (int ntp = 0; ntp < 2; ntp++) {
                unsigned bd = stg + (unsigned)(sub * 16 * 272 + ntp * 32) + boff4;
                asm volatile("ldmatrix.sync.aligned.m8n8.x4.trans.shared.b16 {%0,%1,%2,%3}, [%4];"
                             : "=r"(bf[2*ntp][0]), "=r"(bf[2*ntp][1]),
                               "=r"(bf[2*ntp+1][0]), "=r"(bf[2*ntp+1][1])
                             : "r"(bd));
            }
#pragma unroll
            for (int mt = 0; mt < 4; mt++)
#pragma unroll
                for (int nt = 0; nt < 4; nt++)
                    mma_f16(c[mt][nt], af[mt], bf[nt]);
        }
    }

    if (EPI == 3 || EPI == 4) aux += (long long)z * sC;
    __half* Ch = (__half*)Cv + (long long)z * sC;
    float*  Cf = (float*)Cv + (long long)z * sC;
    const __half* auxh = (const __half*)(const void*)aux;

    auto epi_store = [&](int gm, int gn, float x0, float x1) {
        long long o = (long long)gm * N + gn;
        if (EPI == 0) {
            *(__half2*)(Ch + o) = __halves2half2(__float2half_rn(x0), __float2half_rn(x1));
        } else if (EPI == 1) {
            *(float2*)(Cf + o) = make_float2(x0, x1);
        } else if (EPI == 3) {
            float2 u = *(const float2*)(aux + o);
            *(float2*)(Cf + o) = make_float2(x0 + u.x, x1 + u.y);
        } else if (EPI == 4) {
            int bb = z + gm / S_E_;
            float g0 = modv[(long long)bb * 3 * W_E_ + 2 * W_E_ + gn];
            float g1 = modv[(long long)bb * 3 * W_E_ + 2 * W_E_ + gn + 1];
            float2 u = *(const float2*)(aux + o);
            *(float2*)(Cf + o) = make_float2(u.x + x0 * g0, u.y + x1 * g1);
        } else {
            __half2 u = *(const __half2*)(auxh + o);
            *(__half2*)(Ch + o) = __halves2half2(
                __float2half_rn(gelu_t(x0) * __low2float(u)),
                __float2half_rn(gelu_t(x1) * __high2float(u)));
        }
    };

#pragma unroll
    for (int mt = 0; mt < 4; mt++) {
#pragma unroll
        for (int nt = 0; nt < 4; nt++) {
            int gm = bm + wm + mt * 16 + row;
            int gn = bn + wn + nt * 8 + col * 2;
            if (gn < N) {
                if (gm < M)     epi_store(gm,     gn, c[mt][nt][0], c[mt][nt][1]);
                if (gm + 8 < M) epi_store(gm + 8, gn, c[mt][nt][2], c[mt][nt][3]);
            }
        }
    }
}

// ============ gemm16m64: 64x128 tile, 128 thr (4 warps 1m x 4n of 64x32), 3 stages ====
#define A64B 5120
#define STG64 (A64B + 8704)
template<int EPI>
__global__ __launch_bounds__(128, 4)
void gemm16m64(const __half* __restrict__ A, const __half* __restrict__ Bm,
               void* __restrict__ Cv, const float* __restrict__ aux,
               int M, int N, int K, long long sA, long long sC)
{
    extern __shared__ __align__(16) char sm[];

    const int z = blockIdx.z;
    A += (long long)z * sA;

    const int tid  = threadIdx.x;
    const int lane = tid & 31;
    const int wid  = tid >> 5;
    const int wn   = wid * 32;
    const int bm   = blockIdx.y * 64;
    const int bn   = blockIdx.x * 128;
    const int row  = lane >> 2, col = lane & 3;

    unsigned sbase = (unsigned)__cvta_generic_to_shared(sm);

    auto issue = [&](int st) {
        const int ktE = st * 32;
        const unsigned sb = sbase + (unsigned)((st % 3) * STG64);
#pragma unroll
        for (int j = 0; j < 2; j++) {
            int id = tid + j * 128;
            int r = id >> 2, c = id & 3;
            int gm = bm + r;
            const __half* gp = A + (long long)(gm < M ? gm : M - 1) * K + ktE + c * 8;
            unsigned dst = sb + (unsigned)(r * 80 + c * 16);
            int zf = (gm < M) ? 16 : 0;
            asm volatile("cp.async.cg.shared.global [%0], [%1], 16, %2;\n"
                         :: "r"(dst), "l"(gp), "r"(zf));
        }
#pragma unroll
        for (int j = 0; j < 4; j++) {
            int id = tid + j * 128;
            int kr = id >> 4, c = id & 15;
            int gn = bn + c * 8;
            const __half* gp = Bm + (long long)(ktE + kr) * N + (gn < N ? gn : N - 8);
            unsigned dst = sb + (unsigned)(A64B + kr * 272 + c * 16);
            int zf = (gn < N) ? 16 : 0;
            asm volatile("cp.async.cg.shared.global [%0], [%1], 16, %2;\n"
                         :: "r"(dst), "l"(gp), "r"(zf));
        }
    };

    float c[4][4][4];
#pragma unroll
    for (int i = 0; i < 4; i++)
#pragma unroll
        for (int j = 0; j < 4; j++)
#pragma unroll
            for (int l = 0; l < 4; l++) c[i][j][l] = 0.f;

    const unsigned aoff = (unsigned)((((lane >> 3) & 1) * 8 + (lane & 7)) * 80 + (lane >> 4) * 16);
    const unsigned boff4 = (unsigned)(A64B + (((lane >> 3) & 1) * 8 + (lane & 7)) * 272
                                      + (lane >> 4) * 16 + wn * 2);

    const int nk = K / 32;
    issue(0); asm volatile("cp.async.commit_group;\n");
    issue(1); asm volatile("cp.async.commit_group;\n");

#pragma unroll 1
    for (int kt = 0; kt < nk; kt++) {
        asm volatile("cp.async.wait_group 1;\n");
        __syncthreads();
        if (kt + 2 < nk) issue(kt + 2);
        asm volatile("cp.async.commit_group;\n");

        const unsigned stg = sbase + (unsigned)((kt % 3) * STG64);
#pragma unroll
        for (int sub = 0; sub < 2; sub++) {
            unsigned af[4][4], bf[4][2];
#pragma unroll
            for (int mt = 0; mt < 4; mt++) {
                unsigned ad = stg + (unsigned)((mt * 16) * 80 + sub * 32) + aoff;
                asm volatile("ldmatrix.sync.aligned.m8n8.x4.shared.b16 {%0,%1,%2,%3}, [%4];"
                             : "=r"(af[mt][0]), "=r"(af[mt][1]), "=r"(af[mt][2]), "=r"(af[mt][3])
                             : "r"(ad));
            }
#pragma unroll
            for (int ntp = 0; ntp < 2; ntp++) {
                unsigned bd = stg + (unsigned)(sub * 16 * 272 + ntp * 32) + boff4;
                asm volatile("ldmatrix.sync.aligned.m8n8.x4.trans.shared.b16 {%0,%1,%2,%3}, [%4];"
                             : "=r"(bf[2*ntp][0]), "=r"(bf[2*ntp][1]),
                               "=r"(bf[2*ntp+1][0]), "=r"(bf[2*ntp+1][1])
                             : "r"(bd));
            }
#pragma unroll
            for (int mt = 0; mt < 4; mt++)
#pragma unroll
                for (int nt = 0; nt < 4; nt++)
                    mma_f16(c[mt][nt], af[mt], bf[nt]);
        }
    }

    if (EPI == 3) aux += (long long)z * sC;
    __half* Ch = (__half*)Cv + (long long)z * sC;
    float*  Cf = (float*)Cv + (long long)z * sC;

#pragma unroll
    for (int mt = 0; mt < 4; mt++) {
#pragma unroll
        for (int nt = 0; nt < 4; nt++) {
            int gm = bm + mt * 16 + row;
            int gn = bn + wn + nt * 8 + col * 2;
            if (gn >= N) continue;
#pragma unroll
            for (int hh = 0; hh < 2; hh++) {
                int g = gm + hh * 8;
                if (g >= M) continue;
                long long o = (long long)g * N + gn;
                float x0 = c[mt][nt][hh * 2], x1 = c[mt][nt][hh * 2 + 1];
                if (EPI == 0) {
                    *(__half2*)(Ch + o) = __halves2half2(__float2half_rn(x0), __float2half_rn(x1));
                } else {
                    float2 u = *(const float2*)(aux + o);
                    *(float2*)(Cf + o) = make_float2(x0 + u.x, x1 + u.y);
                }
            }
        }
    }
}

// ============ gemm16_tb1: fp16, B (N,K) row-major, fp32 out ============
#define STG1 20480
__global__ __launch_bounds__(256, 2)
void gemm16_tb1(const __half* __restrict__ A, const __half* __restrict__ Bm,
                float* __restrict__ C, int M, int N, int K,
                long long sA, long long sB, long long sC, int bInner)
{
    extern __shared__ __align__(16) char sm[];

    const int z = blockIdx.z;
    A  += (long long)z * sA;
    Bm += (long long)(z / bInner) * sB;
    C  += (long long)z * sC;

    const int tid  = threadIdx.x;
    const int lane = tid & 31;
    const int wid  = tid >> 5;
    const int wm   = (wid & 1) * 64;
    const int wn   = (wid >> 1) * 32;
    const int bm   = blockIdx.y * 128;
    const int bn   = blockIdx.x * 128;
    const int row  = lane >> 2, col = lane & 3;

    unsigned sbase = (unsigned)__cvta_generic_to_shared(sm);

    auto issue = [&](int st) {
        const int ktE = st * 32;
        const unsigned sb = sbase + (unsigned)((st & 3) * STG1);
#pragma unroll
        for (int j = 0; j < 2; j++) {
            int id = tid + j * 256;
            int r = id >> 2, c = id & 3;
            int gm = bm + r;
            const __half* gp = A + (long long)(gm < M ? gm : M - 1) * K + ktE + c * 8;
            unsigned dst = sb + (unsigned)(r * 80 + c * 16);
            int zf = (gm < M) ? 16 : 0;
            asm volatile("cp.async.cg.shared.global [%0], [%1], 16, %2;\n"
                         :: "r"(dst), "l"(gp), "r"(zf));
        }
#pragma unroll
        for (int j = 0; j < 2; j++) {
            int id = tid + j * 256;
            int r = id >> 2, c = id & 3;
            int gn = bn + r;
            const __half* gp = Bm + (long long)(gn < N ? gn : N - 1) * K + ktE + c * 8;
            unsigned dst = sb + (unsigned)(ASTB + r * 80 + c * 16);
            int zf = (gn < N) ? 16 : 0;
            asm volatile("cp.async.cg.shared.global [%0], [%1], 16, %2;\n"
                         :: "r"(dst), "l"(gp), "r"(zf));
        }
    };

    float c[4][4][4];
#pragma unroll
    for (int i = 0; i < 4; i++)
#pragma unroll
        for (int j = 0; j < 4; j++)
#pragma unroll
            for (int l = 0; l < 4; l++) c[i][j][l] = 0.f;

    const unsigned aoff = (unsigned)((((lane >> 3) & 1) * 8 + (lane & 7)) * 80 + (lane >> 4) * 16);
    // B x4 non-trans: matrices {n@k0-7, n@k8-15, n+8@k0-7, n+8@k8-15}
    const unsigned boff4 = (unsigned)(ASTB + ((lane & 7) + (lane >> 4) * 8 + wn) * 80
                                      + (((lane >> 3) & 1) * 16));

    const int nk = K / 32;
#pragma unroll 1
    for (int s = 0; s < 3; s++) { issue(s); asm volatile("cp.async.commit_group;\n"); }

#pragma unroll 1
    for (int kt = 0; kt < nk; kt++) {
        asm volatile("cp.async.wait_group 2;\n");
        __syncthreads();
        if (kt + 3 < nk) issue(kt + 3);
        asm volatile("cp.async.commit_group;\n");

        const unsigned stg = sbase + (unsigned)((kt & 3) * STG1);
#pragma unroll
        for (int sub = 0; sub < 2; sub++) {
            unsigned af[4][4], bf[4][2];
#pragma unroll
            for (int mt = 0; mt < 4; mt++) {
                unsigned ad = stg + (unsigned)((wm + mt * 16) * 80 + sub * 32) + aoff;
                asm volatile("ldmatrix.sync.aligned.m8n8.x4.shared.b16 {%0,%1,%2,%3}, [%4];"
                             : "=r"(af[mt][0]), "=r"(af[mt][1]), "=r"(af[mt][2]), "=r"(af[mt][3])
                             : "r"(ad));
            }
#pragma unroll
            for (int ntp = 0; ntp < 2; ntp++) {
                unsigned bd = stg + (unsigned)(ntp * 16 * 80 + sub * 32) + boff4;
                asm volatile("ldmatrix.sync.aligned.m8n8.x4.shared.b16 {%0,%1,%2,%3}, [%4];"
                             : "=r"(bf[2*ntp][0]), "=r"(bf[2*ntp][1]),
                               "=r"(bf[2*ntp+1][0]), "=r"(bf[2*ntp+1][1])
                             : "r"(bd));
            }
#pragma unroll
            for (int mt = 0; mt < 4; mt++)
#pragma unroll
                for (int nt = 0; nt < 4; nt++)
                    mma_f16(c[mt][nt], af[mt], bf[nt]);
        }
    }

#pragma unroll
    for (int mt = 0; mt < 4; mt++) {
#pragma unroll
        for (int nt = 0; nt < 4; nt++) {
            int gm = bm + wm + mt * 16 + row;
            int gn = bn + wn + nt * 8 + col * 2;
            if (gn < N) {
                if (gm < M)
                    *(float2*)(C + (long long)gm * N + gn) = make_float2(c[mt][nt][0], c[mt][nt][1]);
                if (gm + 8 < M)
                    *(float2*)(C + (long long)(gm + 8) * N + gn) = make_float2(c[mt][nt][2], c[mt][nt][3]);
            }
        }
    }
}

// ---------------- weight fp16 pre-convert ----------------
__global__ void round4(const float4* __restrict__ s, __half2* __restrict__ d, int n4)
{
    int i = blockIdx.x * 256 + threadIdx.x;
    if (i >= n4) return;
    float4 v = s[i];
    d[i * 2]     = __floats2half2_rn(v.x, v.y);
    d[i * 2 + 1] = __floats2half2_rn(v.z, v.w);
}

#define NW 13
struct RoundDesc {
    const float4* src[NW];
    long long dofs[NW];
    int blkStart[NW + 1];
};

__global__ void round_many(RoundDesc d, __half* __restrict__ wbuf)
{
    int b = blockIdx.x;
    int w = 0;
#pragma unroll
    for (int i = 0; i < NW; i++) if (b >= d.blkStart[i + 1]) w = i + 1;
    int lb = b - d.blkStart[w];
    const float4* s = d.src[w] + (long long)lb * 1024;
    __half2* o = (__half2*)(wbuf + d.dofs[w]) + (long long)lb * 2048;
    int t = threadIdx.x;
#pragma unroll
    for (int i = 0; i < 4; i++) {
        float4 v = s[t + i * 256];
        o[(t + i * 256) * 2]     = __floats2half2_rn(v.x, v.y);
        o[(t + i * 256) * 2 + 1] = __floats2half2_rn(v.z, v.w);
    }
}

// ---------------- row kernels ----------------
__device__ __forceinline__ float blockReduceSum(float v) {
    __shared__ float red[256];
    int t = threadIdx.x;
    red[t] = v; __syncthreads();
    for (int s = 128; s > 0; s >>= 1) {
        if (t < s) red[t] += red[t + s];
        __syncthreads();
    }
    float r = red[0];
    __syncthreads();
    return r;
}

__global__ void rms_scale(const float* __restrict__ x, const float* __restrict__ w,
                          __half* __restrict__ out, int W)
{
    long long base = (long long)blockIdx.x * W;
    float ss = 0.f;
    for (int c = threadIdx.x; c < W; c += 256) { float t = x[base + c]; ss += t * t; }
    float tot = blockReduceSum(ss);
    float inv = rsqrtf(tot / (float)W + EPS_);
    for (int c = threadIdx.x; c < W; c += 256)
        out[base + c] = __float2half_rn(x[base + c] * inv * (1.f + w[c]));
}

__global__ void rms_mod(const float* __restrict__ x, const float* __restrict__ mod,
                        __half* __restrict__ out, int W, int rowsPerB)
{
    long long base = (long long)blockIdx.x * W;
    int b = blockIdx.x / rowsPerB;
    const float* m = mod + (long long)b * 3 * W;
    float ss = 0.f;
    for (int c = threadIdx.x; c < W; c += 256) { float t = x[base + c]; ss += t * t; }
    float tot = blockReduceSum(ss);
    float inv = rsqrtf(tot / (float)W + EPS_);
    for (int c = threadIdx.x; c < W; c += 256)
        out[base + c] = __float2half_rn(x[base + c] * inv * (1.f + m[c]) + m[W + c]);
}

__global__ void modmm2(const float* __restrict__ cond, const float* __restrict__ W,
                       const float* __restrict__ bias, float* __restrict__ out)
{
    const int NT = 3 * W_E_;
    __shared__ float cs[W_E_];
    __shared__ float part[4][64];
    int bb = blockIdx.y;
    int tid = threadIdx.x;
    for (int i = tid; i < W_E_; i += 256) cs[i] = cond[bb * W_E_ + i];
    __syncthreads();
    int tx = tid & 63, ty = tid >> 6;
    int c = blockIdx.x * 64 + tx;
    const float* Wp = W + (long long)(ty * 256) * NT + c;
    const float* cp = cs + ty * 256;
    float s = 0.f;
#pragma unroll 4
    for (int k = 0; k < 256; k++) s += cp[k] * Wp[(long long)k * NT];
    part[ty][tx] = s;
    __syncthreads();
    if (ty == 0)
        out[(long long)bb * NT + c] = part[0][tx] + part[1][tx] + part[2][tx] + part[3][tx] + bias[c];
}

__global__ void rope4h(__half* __restrict__ x, const int* __restrict__ pos, int nh)
{
    int idx = blockIdx.x * blockDim.x + threadIdx.x;
    int total = B_ * S_ * nh * 32;
    if (idx >= total) return;
    int d4 = (idx & 31) << 2;
    int h = (idx >> 5) % nh;
    int s = (idx / (32 * nh)) % S_;
    int b = idx / (32 * nh * S_);
    float p = (float)pos[b * S_ + s];
    __half* base = x + (((long long)(b * S_ + s) * nh + h) << 8);
    __half2 x1a = *(__half2*)(base + d4),       x1b = *(__half2*)(base + d4 + 2);
    __half2 x2a = *(__half2*)(base + d4 + 128), x2b = *(__half2*)(base + d4 + 130);
    float r1[4] = {__low2float(x1a), __high2float(x1a), __low2float(x1b), __high2float(x1b)};
    float r2[4] = {__low2float(x2a), __high2float(x2a), __low2float(x2b), __high2float(x2b)};
#pragma unroll
    for (int j = 0; j < 4; j++) {
        float ang = p * powf(10000.f, -(float)(2 * (d4 + j)) / 256.f);
        float sn, cs2; sincosf(ang, &sn, &cs2);
        float a = r1[j], bb = r2[j];
        r1[j] = a * cs2 - bb * sn;
        r2[j] = bb * cs2 + a * sn;
    }
    *(__half2*)(base + d4)       = __floats2half2_rn(r1[0], r1[1]);
    *(__half2*)(base + d4 + 2)   = __floats2half2_rn(r1[2], r1[3]);
    *(__half2*)(base + d4 + 128) = __floats2half2_rn(r2[0], r2[1]);
    *(__half2*)(base + d4 + 130) = __floats2half2_rn(r2[2], r2[3]);
}

__global__ void q_to_bhsd8h(const uint4* __restrict__ q, uint4* __restrict__ qt)
{
    int idx = blockIdx.x * blockDim.x + threadIdx.x;
    int total = B_ * H_ * S_ * 32;
    if (idx >= total) return;
    int d = idx & 31;
    int s = (idx >> 5) % S_;
    int h = (idx / (32 * S_)) % H_;
    int b = idx / (32 * S_ * H_);
    qt[idx] = q[(((b * S_ + s) * H_ + h) * 32) + d];
}

__global__ void bhsd_to_bshd8h(const uint4* __restrict__ a, uint4* __restrict__ o)
{
    int idx = blockIdx.x * blockDim.x + threadIdx.x;
    int total = B_ * S_ * H_ * 32;
    if (idx >= total) return;
    int d = idx & 31;
    int h = (idx >> 5) % H_;
    int s = (idx / (32 * H_)) % S_;
    int b = idx / (32 * H_ * S_);
    o[idx] = a[(((b * H_ + h) * S_ + s) * 32) + d];
}

__global__ void softmax4h(const float* __restrict__ logits, const float* __restrict__ mask,
                          __half* __restrict__ probs)
{
    int rowid = blockIdx.x;
    int b = rowid / (H_ * S_);
    int q = rowid % S_;
    const float4* row = (const float4*)(logits + (long long)rowid * S_);
    const float4* m = (const float4*)(mask + ((long long)b * S_ + q) * S_);
    __half* prow = probs + (long long)rowid * S_;
    int t = threadIdx.x;
    const bool act = t < 208;
    float4 v = make_float4(-1e30f, -1e30f, -1e30f, -1e30f);
    if (act) {
        float4 lv = row[t], mv = m[t];
        v.x = lv.x * SCALE_ + mv.x; v.y = lv.y * SCALE_ + mv.y;
        v.z = lv.z * SCALE_ + mv.z; v.w = lv.w * SCALE_ + mv.w;
    }
    float mx = fmaxf(fmaxf(v.x, v.y), fmaxf(v.z, v.w));
    __shared__ float red[256];
    red[t] = mx; __syncthreads();
    for (int s = 128; s > 0; s >>= 1) { if (t < s) red[t] = fmaxf(red[t], red[t + s]); __syncthreads(); }
    mx = red[0]; __syncthreads();
    float sum = 0.f;
    if (act) {
        v.x = __expf(v.x - mx); v.y = __expf(v.y - mx);
        v.z = __expf(v.z - mx); v.w = __expf(v.w - mx);
        sum = v.x + v.y + v.z + v.w;
    }
    red[t] = sum; __syncthreads();
    for (int s = 128; s > 0; s >>= 1) { if (t < s) red[t] += red[t + s]; __syncthreads(); }
    float inv = 1.f / red[0];
    if (act) {
        *(__half2*)(prow + t * 4)     = __floats2half2_rn(v.x * inv, v.y * inv);
        *(__half2*)(prow + t * 4 + 2) = __floats2half2_rn(v.z * inv, v.w * inv);
    }
}

// ---------------- host launch ----------------
#define GETSYMF(var, sym) do { void* p__; cudaGetSymbolAddress(&p__, sym); var = (float*)p__; } while (0)
#define GETSYMH(var, sym) do { void* p__; cudaGetSymbolAddress(&p__, sym); var = (__half*)p__; } while (0)

extern "C" void kernel_launch(void* const* d_in, const int* in_sizes, int n_in,
                              void* d_out, int out_size)
{
    const float *embeds_vlm, *embeds_exp, *cond, *attn_mask;
    const int* pos;
    const float *vlm_ln1_w, *vlm_ln2_w, *vlm_q_w, *vlm_k_w, *vlm_v_w, *vlm_o_w;
    const float *vlm_gate_w, *vlm_up_w, *vlm_down_w;
    const float *exp_ln1_dw, *exp_ln1_db, *exp_ln2_dw, *exp_ln2_db;
    const float *exp_q_w, *exp_k_w, *exp_v_w, *exp_o_w, *exp_gate_w, *exp_up_w, *exp_down_w;

    if (in_sizes[3] == B_ * S_) {
        embeds_vlm = (const float*)d_in[0];  embeds_exp = (const float*)d_in[1];
        cond       = (const float*)d_in[2];  pos        = (const int*)  d_in[3];
        attn_mask  = (const float*)d_in[4];
        vlm_ln1_w  = (const float*)d_in[5];  vlm_ln2_w  = (const float*)d_in[6];
        vlm_q_w    = (const float*)d_in[7];  vlm_k_w    = (const float*)d_in[8];
        vlm_v_w    = (const float*)d_in[9];  vlm_o_w    = (const float*)d_in[10];
        vlm_gate_w = (const float*)d_in[11]; vlm_up_w   = (const float*)d_in[12];
        vlm_down_w = (const float*)d_in[13];
        exp_ln1_dw = (const float*)d_in[14]; exp_ln1_db = (const float*)d_in[15];
        exp_ln2_dw = (const float*)d_in[16]; exp_ln2_db = (const float*)d_in[17];
        exp_q_w    = (const float*)d_in[18]; exp_k_w    = (const float*)d_in[19];
        exp_v_w    = (const float*)d_in[20]; exp_o_w    = (const float*)d_in[21];
        exp_gate_w = (const float*)d_in[22]; exp_up_w   = (const float*)d_in[23];
        exp_down_w = (const float*)d_in[24];
    } else {
        embeds_vlm = (const float*)d_in[0];  embeds_exp = (const float*)d_in[1];
        cond       = (const float*)d_in[2];
        vlm_ln1_w  = (const float*)d_in[3];  vlm_ln2_w  = (const float*)d_in[4];
        vlm_q_w    = (const float*)d_in[5];  vlm_k_w    = (const float*)d_in[6];
        vlm_v_w    = (const float*)d_in[7];  vlm_o_w    = (const float*)d_in[8];
        vlm_gate_w = (const float*)d_in[9];  vlm_up_w   = (const float*)d_in[10];
        vlm_down_w = (const float*)d_in[11];
        exp_ln1_dw = (const float*)d_in[12]; exp_ln1_db = (const float*)d_in[13];
        exp_ln2_dw = (const float*)d_in[14]; exp_ln2_db = (const float*)d_in[15];
        exp_q_w    = (const float*)d_in[16]; exp_k_w    = (const float*)d_in[17];
        exp_v_w    = (const float*)d_in[18]; exp_o_w    = (const float*)d_in[19];
        exp_gate_w = (const float*)d_in[20]; exp_up_w   = (const float*)d_in[21];
        exp_down_w = (const float*)d_in[22];
        pos        = (const int*)  d_in[23];
        attn_mask  = (const float*)d_in[24];
    }

    __half *hv, *he, *q, *qt, *k, *v, *probs, *attnt, *attn, *mg, *mu, *eg, *eu, *wb;
    float *mod1, *mod2, *logits, *hv1, *he1;
    GETSYMH(hv, g_hv);   GETSYMH(he, g_he);   GETSYMF(mod1, g_mod1); GETSYMF(mod2, g_mod2);
    GETSYMH(q, g_q);     GETSYMH(qt, g_qt);   GETSYMH(k, g_k);       GETSYMH(v, g_v);
    GETSYMF(logits, g_logits); GETSYMH(probs, g_probs);
    GETSYMH(attnt, g_attnt);   GETSYMH(attn, g_attn);
    GETSYMF(hv1, g_hv1); GETSYMF(he1, g_he1);
    GETSYMH(mg, g_mg);   GETSYMH(mu, g_mu);
    GETSYMH(eg, g_eg);   GETSYMH(eu, g_eu);   GETSYMH(wb, g_wbuf);

    const long long n_vq = (long long)W_V_ * H_ * DH_;
    const float* srcs[NW] = {vlm_k_w, vlm_v_w, vlm_o_w, vlm_gate_w, vlm_up_w, vlm_down_w,
                             exp_q_w, exp_k_w, exp_v_w, exp_o_w, exp_gate_w, exp_up_w, exp_down_w};
    long long cnts[NW] = {
        (long long)W_V_*DH_, (long long)W_V_*DH_, (long long)H_*DH_*W_V_,
        (long long)W_V_*MLPV_, (long long)W_V_*MLPV_, (long long)MLPV_*W_V_,
        (long long)W_E_*H_*DH_, (long long)W_E_*DH_, (long long)W_E_*DH_, (long long)H_*DH_*W_E_,
        (long long)W_E_*MLPE_, (long long)W_E_*MLPE_, (long long)MLPE_*W_E_};
    RoundDesc rd;
    long long ofs = n_vq; int blk = 0;
    const __half* wptr[NW];
    for (int i = 0; i < NW; i++) {
        rd.src[i] = (const float4*)srcs[i];
        rd.dofs[i] = ofs;
        rd.blkStart[i] = blk;
        wptr[i] = wb + ofs;
        ofs += cnts[i];
        blk += (int)(cnts[i] / 4096);
    }
    rd.blkStart[NW] = blk;
    const __half* w_vq = wb;
    const __half *w_vk = wptr[0], *w_vv = wptr[1], *w_vo = wptr[2];
    const __half *w_vg = wptr[3], *w_vu = wptr[4], *w_vd = wptr[5];
    const __half *w_eq = wptr[6], *w_ek = wptr[7], *w_ev = wptr[8], *w_eo = wptr[9];
    const __half *w_egw = wptr[10], *w_euw = wptr[11], *w_ed = wptr[12];

    const int SMG  = 4 * STGB;
    const int SMT  = 4 * STG1;
    const int SM64 = 3 * STG64;
    cudaFuncSetAttribute(gemm16<0>, cudaFuncAttributeMaxDynamicSharedMemorySize, SMG);
    cudaFuncSetAttribute(gemm16<1>, cudaFuncAttributeMaxDynamicSharedMemorySize, SMG);
    cudaFuncSetAttribute(gemm16<3>, cudaFuncAttributeMaxDynamicSharedMemorySize, SMG);
    cudaFuncSetAttribute(gemm16<4>, cudaFuncAttributeMaxDynamicSharedMemorySize, SMG);
    cudaFuncSetAttribute(gemm16<5>, cudaFuncAttributeMaxDynamicSharedMemorySize, SMG);
    cudaFuncSetAttribute(gemm16_tb1, cudaFuncAttributeMaxDynamicSharedMemorySize, SMT);
    cudaFuncSetAttribute(gemm16m64<0>, cudaFuncAttributeMaxDynamicSharedMemorySize, SM64);
    cudaFuncSetAttribute(gemm16m64<3>, cudaFuncAttributeMaxDynamicSharedMemorySize, SM64);

    float* out_v = (float*)d_out;
    float* out_e = (float*)d_out + (long long)B_ * S_V_ * W_V_;

    long long sHv = (long long)S_V_ * W_V_, sHe = (long long)S_E_ * W_E_;
    long long sQ = (long long)S_ * H_ * DH_, sK = (long long)S_ * DH_;
    long long sL = (long long)S_ * S_;

    // L0..L2
    round4<<<(int)((n_vq / 4 + 255) / 256), 256>>>((const float4*)vlm_q_w, (__half2*)wb, (int)(n_vq / 4));
    rms_scale<<<B_ * S_V_, 256>>>(embeds_vlm, vlm_ln1_w, hv, W_V_);
    modmm2<<<dim3(48, B_), 256>>>(cond, exp_ln1_dw, exp_ln1_db, mod1);
    // L3: VLM Q projection (ncu target)
    gemm16m64<0><<<dim3(16, 12, B_), 128, SM64>>>(hv, w_vq, q, nullptr, S_V_, H_ * DH_, W_V_, sHv, sQ);
    // L4..L6
    round_many<<<blk, 256>>>(rd, wb);
    rms_mod<<<B_ * S_E_, 256>>>(embeds_exp, mod1, he, W_E_, S_E_);
    modmm2<<<dim3(48, B_), 256>>>(cond, exp_ln2_dw, exp_ln2_db, mod2);

    // QKV remainder
    gemm16<0><<<dim3(16, 1, B_), 256, SMG>>>(he, w_eq, q + (long long)S_V_ * H_ * DH_, nullptr, nullptr, S_E_, H_ * DH_, W_E_, sHe, 0, sQ, 1);
    gemm16<0><<<dim3(2, 6, B_), 256, SMG>>>(hv, w_vk, k, nullptr, nullptr, S_V_, DH_, W_V_, sHv, 0, sK, 1);
    gemm16<0><<<dim3(2, 1, B_), 256, SMG>>>(he, w_ek, k + S_V_ * DH_, nullptr, nullptr, S_E_, DH_, W_E_, sHe, 0, sK, 1);
    gemm16<0><<<dim3(2, 6, B_), 256, SMG>>>(hv, w_vv, v, nullptr, nullptr, S_V_, DH_, W_V_, sHv, 0, sK, 1);
    gemm16<0><<<dim3(2, 1, B_), 256, SMG>>>(he, w_ev, v + S_V_ * DH_, nullptr, nullptr, S_E_, DH_, W_E_, sHe, 0, sK, 1);

    // RoPE
    rope4h<<<(B_ * S_ * H_ * 32 + 255) / 256, 256>>>(q, pos, H_);
    rope4h<<<(B_ * S_ * 1 * 32 + 255) / 256, 256>>>(k, pos, 1);

    // attention
    {
        int nq8 = B_ * H_ * S_ * 32;
        q_to_bhsd8h<<<(nq8 + 255) / 256, 256>>>((const uint4*)q, (uint4*)qt);
        gemm16_tb1<<<dim3(7, 7, B_ * H_), 256, SMT>>>(qt, k, logits, S_, S_, DH_, sK, sK, sL, H_);
        softmax4h<<<B_ * H_ * S_, 256>>>(logits, attn_mask, probs);
        gemm16<0><<<dim3(2, 7, B_ * H_), 256, SMG>>>(probs, v, attnt, nullptr, nullptr, S_, DH_, S_, sL, sK, sK, H_);
        bhsd_to_bshd8h<<<(nq8 + 255) / 256, 256>>>((const uint4*)attnt, (uint4*)attn);
    }

    // output projections + residuals
    {
        long long sA = (long long)S_ * H_ * DH_;
        gemm16m64<3><<<dim3(16, 12, B_), 128, SM64>>>(attn, w_vo, hv1, embeds_vlm, S_V_, W_V_, H_ * DH_, sA, sHv);
        gemm16<4><<<dim3(8, 1, B_), 256, SMG>>>(attn + (long long)S_V_ * H_ * DH_, w_eo, he1, embeds_exp, mod1, S_E_, W_E_, H_ * DH_, sA, 0, sHe, 1);
    }

    // pre-MLP norms
    rms_scale<<<B_ * S_V_, 256>>>(hv1, vlm_ln2_w, hv, W_V_);
    rms_mod<<<B_ * S_E_, 256>>>(he1, mod2, he, W_E_, S_E_);

    // VLM MLP
    {
        int M = B_ * S_V_;
        gemm16<0><<<dim3(128, 24, 1), 256, SMG>>>(hv, w_vu, mu, nullptr, nullptr, M, MLPV_, W_V_, 0, 0, 0, 1);
        gemm16<5><<<dim3(128, 24, 1), 256, SMG>>>(hv, w_vg, mg, (const float*)(const void*)mu, nullptr, M, MLPV_, W_V_, 0, 0, 0, 1);
        gemm16m64<3><<<dim3(16, 48, 1), 128, SM64>>>(mg, w_vd, out_v, hv1, M, W_V_, MLPV_, 0, 0);
    }

    // expert MLP
    {
        int M = B_ * S_E_;
        gemm16<0><<<dim3(32, 2, 1), 256, SMG>>>(he, w_euw, eu, nullptr, nullptr, M, MLPE_, W_E_, 0, 0, 0, 1);
        gemm16<5><<<dim3(32, 2, 1), 256, SMG>>>(he, w_egw, eg, (const float*)(const void*)eu, nullptr, M, MLPE_, W_E_, 0, 0, 0, 1);
        gemm16<4><<<dim3(8, 2, 1), 256, SMG>>>(eg, w_ed, out_e, he1, mod2, M, W_E_, MLPE_, 0, 0, 0, 1);
    }
}

// round 13
// speedup vs baseline: 1.1744x; 1.0307x over previous
#include <cuda_runtime.h>
#include <cuda_fp16.h>
#include <cuda_bf16.h>
#include <math.h>

#define B_    4
#define S_V_  768
#define S_E_  64
#define S_    832
#define W_V_  2048
#define W_E_  1024
#define H_    8
#define DH_   256
#define MLPV_ 16384
#define MLPE_ 4096
#define EPS_  1e-6f
#define SCALE_ 0.0625f

// ---------------- scratch ----------------
__device__ __half g_hv   [B_*S_V_*W_V_];
__device__ __half g_he   [B_*S_E_*W_E_];
__device__ float  g_mod1 [B_*3*W_E_];
__device__ float  g_mod2 [B_*3*W_E_];
__device__ __half g_q    [(long long)B_*S_*H_*DH_];
__device__ __half g_qt   [(long long)B_*H_*S_*DH_];
__device__ __half g_k    [B_*S_*DH_];
__device__ __half g_v    [B_*S_*DH_];
__device__ float  g_logits[(long long)B_*H_*S_*S_];
__device__ __half g_probs[(long long)B_*H_*S_*S_];
__device__ __half g_attnt[(long long)B_*H_*S_*DH_];
__device__ __half g_attn [(long long)B_*S_*H_*DH_];
__device__ float  g_hv1  [B_*S_V_*W_V_];
__device__ float  g_he1  [B_*S_E_*W_E_];
__device__ __half g_mg   [(long long)B_*S_V_*MLPV_];
__device__ __half g_eg   [B_*S_E_*MLPE_];
__device__ __half g_wbuf [127401984];

__device__ __forceinline__ float gelu_t(float x) {
    return 0.5f * x * (1.f + tanhf(0.7978845608028654f * (x + 0.044715f * x * x * x)));
}

__device__ __forceinline__ void mma_f16(float* c, const unsigned* a, const unsigned* b) {
    asm volatile(
        "mma.sync.aligned.m16n8k16.row.col.f32.f16.f16.f32 "
        "{%0,%1,%2,%3}, {%4,%5,%6,%7}, {%8,%9}, {%0,%1,%2,%3};\n"
        : "+f"(c[0]), "+f"(c[1]), "+f"(c[2]), "+f"(c[3])
        : "r"(a[0]), "r"(a[1]), "r"(a[2]), "r"(a[3]), "r"(b[0]), "r"(b[1]));
}

// ============ gemm16: fp16 operands, fp32 accum, TB=0 ============
// Block 128x128, 256 thr, 8 warps (2m x 4n) of 64x32, K-tile 32, 4 stages.
// B frags via ldmatrix.x4.trans.
// EPI: 0 plain->fp16, 3 fp32(c+aux), 4 fp32 gated residual,
//      6 fused glu: pairs (even=up,odd=gate) -> fp16 gelu(x1)*x0 at N/2 stride
#define ASTB 10240
#define STGB 18944
template<int EPI>
__global__ __launch_bounds__(256, 2)
void gemm16(const __half* __restrict__ A, const __half* __restrict__ Bm,
            void* __restrict__ Cv, const float* __restrict__ aux,
            const float* __restrict__ modv,
            int M, int N, int K,
            long long sA, long long sB, long long sC, int bInner)
{
    extern __shared__ __align__(16) char sm[];

    const int z = blockIdx.z;
    A  += (long long)z * sA;
    Bm += (long long)(z / bInner) * sB;

    const int tid  = threadIdx.x;
    const int lane = tid & 31;
    const int wid  = tid >> 5;
    const int wm   = (wid & 1) * 64;
    const int wn   = (wid >> 1) * 32;
    const int bm   = blockIdx.y * 128;
    const int bn   = blockIdx.x * 128;
    const int row  = lane >> 2, col = lane & 3;

    unsigned sbase = (unsigned)__cvta_generic_to_shared(sm);

    auto issue = [&](int st) {
        const int ktE = st * 32;
        const unsigned sb = sbase + (unsigned)((st & 3) * STGB);
#pragma unroll
        for (int j = 0; j < 2; j++) {
            int id = tid + j * 256;
            int r = id >> 2, c = id & 3;
            int gm = bm + r;
            const __half* gp = A + (long long)(gm < M ? gm : M - 1) * K + ktE + c * 8;
            unsigned dst = sb + (unsigned)(r * 80 + c * 16);
            int zf = (gm < M) ? 16 : 0;
            asm volatile("cp.async.cg.shared.global [%0], [%1], 16, %2;\n"
                         :: "r"(dst), "l"(gp), "r"(zf));
        }
#pragma unroll
        for (int j = 0; j < 2; j++) {
            int id = tid + j * 256;
            int kr = id >> 4, c = id & 15;
            int gn = bn + c * 8;
            const __half* gp = Bm + (long long)(ktE + kr) * N + (gn < N ? gn : N - 8);
            unsigned dst = sb + (unsigned)(ASTB + kr * 272 + c * 16);
            int zf = (gn < N) ? 16 : 0;
            asm volatile("cp.async.cg.shared.global [%0], [%1], 16, %2;\n"
                         :: "r"(dst), "l"(gp), "r"(zf));
        }
    };

    float c[4][4][4];
#pragma unroll
    for (int i = 0; i < 4; i++)
#pragma unroll
        for (int j = 0; j < 4; j++)
#pragma unroll
            for (int l = 0; l < 4; l++) c[i][j][l] = 0.f;

    const unsigned aoff = (unsigned)((((lane >> 3) & 1) * 8 + (lane & 7)) * 80 + (lane >> 4) * 16);
    const unsigned boff4 = (unsigned)(ASTB + (((lane >> 3) & 1) * 8 + (lane & 7)) * 272
                                      + (lane >> 4) * 16 + wn * 2);

    const int nk = K / 32;
#pragma unroll 1
    for (int s = 0; s < 3; s++) { issue(s); asm volatile("cp.async.commit_group;\n"); }

#pragma unroll 1
    for (int kt = 0; kt < nk; kt++) {
        asm volatile("cp.async.wait_group 2;\n");
        __syncthreads();
        if (kt + 3 < nk) issue(kt + 3);
        asm volatile("cp.async.commit_group;\n");

        const unsigned stg = sbase + (unsigned)((kt & 3) * STGB);
#pragma unroll
        for (int sub = 0; sub < 2; sub++) {
            unsigned af[4][4], bf[4][2];
#pragma unroll
            for (int mt = 0; mt < 4; mt++) {
                unsigned ad = stg + (unsigned)((wm + mt * 16) * 80 + sub * 32) + aoff;
                asm volatile("ldmatrix.sync.aligned.m8n8.x4.shared.b16 {%0,%1,%2,%3}, [%4];"
                             : "=r"(af[mt][0]), "=r"(af[mt][1]), "=r"(af[mt][2]), "=r"(af[mt][3])
                             : "r"(ad));
            }
#pragma unroll
            for (int ntp = 0; ntp < 2; ntp++) {
                unsigned bd = stg + (unsigned)(sub * 16 * 272 + ntp * 32) + boff4;
                asm volatile("ldmatrix.sync.aligned.m8n8.x4.trans.shared.b16 {%0,%1,%2,%3}, [%4];"
                             : "=r"(bf[2*ntp][0]), "=r"(bf[2*ntp][1]),
                               "=r"(bf[2*ntp+1][0]), "=r"(bf[2*ntp+1][1])
                             : "r"(bd));
            }
#pragma unroll
            for (int mt = 0; mt < 4; mt++)
#pragma unroll
                for (int nt = 0; nt < 4; nt++)
                    mma_f16(c[mt][nt], af[mt], bf[nt]);
        }
    }

    if (EPI == 3 || EPI == 4) aux += (long long)z * sC;
    __half* Ch = (__half*)Cv + (long long)z * sC;
    float*  Cf = (float*)Cv + (long long)z * sC;

    auto epi_store = [&](int gm, int gn, float x0, float x1) {
        if (EPI == 6) {
            Ch[(long long)gm * (N >> 1) + (gn >> 1)] = __float2half_rn(gelu_t(x1) * x0);
            return;
        }
        long long o = (long long)gm * N + gn;
        if (EPI == 0) {
            *(__half2*)(Ch + o) = __halves2half2(__float2half_rn(x0), __float2half_rn(x1));
        } else if (EPI == 3) {
            float2 u = *(const float2*)(aux + o);
            *(float2*)(Cf + o) = make_float2(x0 + u.x, x1 + u.y);
        } else if (EPI == 4) {
            int bb = z + gm / S_E_;
            float g0 = modv[(long long)bb * 3 * W_E_ + 2 * W_E_ + gn];
            float g1 = modv[(long long)bb * 3 * W_E_ + 2 * W_E_ + gn + 1];
            float2 u = *(const float2*)(aux + o);
            *(float2*)(Cf + o) = make_float2(u.x + x0 * g0, u.y + x1 * g1);
        }
    };

#pragma unroll
    for (int mt = 0; mt < 4; mt++) {
#pragma unroll
        for (int nt = 0; nt < 4; nt++) {
            int gm = bm + wm + mt * 16 + row;
            int gn = bn + wn + nt * 8 + col * 2;
            if (gn < N) {
                if (gm < M)     epi_store(gm,     gn, c[mt][nt][0], c[mt][nt][1]);
                if (gm + 8 < M) epi_store(gm + 8, gn, c[mt][nt][2], c[mt][nt][3]);
            }
        }
    }
}

// ============ gemm16m64: 64x128 tile, 128 thr (4 warps 1m x 4n of 64x32), 3 stages ====
// EPI: 0 fp16, 3 fp32 c+aux. B batched via sB/bInner.
#define A64B 5120
#define STG64 (A64B + 8704)
template<int EPI>
__global__ __launch_bounds__(128, 4)
void gemm16m64(const __half* __restrict__ A, const __half* __restrict__ Bm,
               void* __restrict__ Cv, const float* __restrict__ aux,
               int M, int N, int K, long long sA, long long sB, long long sC, int bInner)
{
    extern __shared__ __align__(16) char sm[];

    const int z = blockIdx.z;
    A  += (long long)z * sA;
    Bm += (long long)(z / bInner) * sB;

    const int tid  = threadIdx.x;
    const int lane = tid & 31;
    const int wid  = tid >> 5;
    const int wn   = wid * 32;
    const int bm   = blockIdx.y * 64;
    const int bn   = blockIdx.x * 128;
    const int row  = lane >> 2, col = lane & 3;

    unsigned sbase = (unsigned)__cvta_generic_to_shared(sm);

    auto issue = [&](int st) {
        const int ktE = st * 32;
        const unsigned sb = sbase + (unsigned)((st % 3) * STG64);
#pragma unroll
        for (int j = 0; j < 2; j++) {
            int id = tid + j * 128;
            int r = id >> 2, c = id & 3;
            int gm = bm + r;
            const __half* gp = A + (long long)(gm < M ? gm : M - 1) * K + ktE + c * 8;
            unsigned dst = sb + (unsigned)(r * 80 + c * 16);
            int zf = (gm < M) ? 16 : 0;
            asm volatile("cp.async.cg.shared.global [%0], [%1], 16, %2;\n"
                         :: "r"(dst), "l"(gp), "r"(zf));
        }
#pragma unroll
        for (int j = 0; j < 4; j++) {
            int id = tid + j * 128;
            int kr = id >> 4, c = id & 15;
            int gn = bn + c * 8;
            const __half* gp = Bm + (long long)(ktE + kr) * N + (gn < N ? gn : N - 8);
            unsigned dst = sb + (unsigned)(A64B + kr * 272 + c * 16);
            int zf = (gn < N) ? 16 : 0;
            asm volatile("cp.async.cg.shared.global [%0], [%1], 16, %2;\n"
                         :: "r"(dst), "l"(gp), "r"(zf));
        }
    };

    float c[4][4][4];
#pragma unroll
    for (int i = 0; i < 4; i++)
#pragma unroll
        for (int j = 0; j < 4; j++)
#pragma unroll
            for (int l = 0; l < 4; l++) c[i][j][l] = 0.f;

    const unsigned aoff = (unsigned)((((lane >> 3) & 1) * 8 + (lane & 7)) * 80 + (lane >> 4) * 16);
    const unsigned boff4 = (unsigned)(A64B + (((lane >> 3) & 1) * 8 + (lane & 7)) * 272
                                      + (lane >> 4) * 16 + wn * 2);

    const int nk = K / 32;
    issue(0); asm volatile("cp.async.commit_group;\n");
    issue(1); asm volatile("cp.async.commit_group;\n");

#pragma unroll 1
    for (int kt = 0; kt < nk; kt++) {
        asm volatile("cp.async.wait_group 1;\n");
        __syncthreads();
        if (kt + 2 < nk) issue(kt + 2);
        asm volatile("cp.async.commit_group;\n");

        const unsigned stg = sbase + (unsigned)((kt % 3) * STG64);
#pragma unroll
        for (int sub = 0; sub < 2; sub++) {
            unsigned af[4][4], bf[4][2];
#pragma unroll
            for (int mt = 0; mt < 4; mt++) {
                unsigned ad = stg + (unsigned)((mt * 16) * 80 + sub * 32) + aoff;
                asm volatile("ldmatrix.sync.aligned.m8n8.x4.shared.b16 {%0,%1,%2,%3}, [%4];"
                             : "=r"(af[mt][0]), "=r"(af[mt][1]), "=r"(af[mt][2]), "=r"(af[mt][3])
                             : "r"(ad));
            }
#pragma unroll
            for (int ntp = 0; ntp < 2; ntp++) {
                unsigned bd = stg + (unsigned)(sub * 16 * 272 + ntp * 32) + boff4;
                asm volatile("ldmatrix.sync.aligned.m8n8.x4.trans.shared.b16 {%0,%1,%2,%3}, [%4];"
                             : "=r"(bf[2*ntp][0]), "=r"(bf[2*ntp][1]),
                               "=r"(bf[2*ntp+1][0]), "=r"(bf[2*ntp+1][1])
                             : "r"(bd));
            }
#pragma unroll
            for (int mt = 0; mt < 4; mt++)
#pragma unroll
                for (int nt = 0; nt < 4; nt++)
                    mma_f16(c[mt][nt], af[mt], bf[nt]);
        }
    }

    if (EPI == 3) aux += (long long)z * sC;
    __half* Ch = (__half*)Cv + (long long)z * sC;
    float*  Cf = (float*)Cv + (long long)z * sC;

#pragma unroll
    for (int mt = 0; mt < 4; mt++) {
#pragma unroll
        for (int nt = 0; nt < 4; nt++) {
            int gm = bm + mt * 16 + row;
            int gn = bn + wn + nt * 8 + col * 2;
            if (gn >= N) continue;
#pragma unroll
            for (int hh = 0; hh < 2; hh++) {
                int g = gm + hh * 8;
                if (g >= M) continue;
                long long o = (long long)g * N + gn;
                float x0 = c[mt][nt][hh * 2], x1 = c[mt][nt][hh * 2 + 1];
                if (EPI == 0) {
                    *(__half2*)(Ch + o) = __halves2half2(__float2half_rn(x0), __float2half_rn(x1));
                } else {
                    float2 u = *(const float2*)(aux + o);
                    *(float2*)(Cf + o) = make_float2(x0 + u.x, x1 + u.y);
                }
            }
        }
    }
}

// ============ gemm16_tb1: fp16, B (N,K) row-major, fp32 out ============
#define STG1 20480
__global__ __launch_bounds__(256, 2)
void gemm16_tb1(const __half* __restrict__ A, const __half* __restrict__ Bm,
                float* __restrict__ C, int M, int N, int K,
                long long sA, long long sB, long long sC, int bInner)
{
    extern __shared__ __align__(16) char sm[];

    const int z = blockIdx.z;
    A  += (long long)z * sA;
    Bm += (long long)(z / bInner) * sB;
    C  += (long long)z * sC;

    const int tid  = threadIdx.x;
    const int lane = tid & 31;
    const int wid  = tid >> 5;
    const int wm   = (wid & 1) * 64;
    const int wn   = (wid >> 1) * 32;
    const int bm   = blockIdx.y * 128;
    const int bn   = blockIdx.x * 128;
    const int row  = lane >> 2, col = lane & 3;

    unsigned sbase = (unsigned)__cvta_generic_to_shared(sm);

    auto issue = [&](int st) {
        const int ktE = st * 32;
        const unsigned sb = sbase + (unsigned)((st & 3) * STG1);
#pragma unroll
        for (int j = 0; j < 2; j++) {
            int id = tid + j * 256;
            int r = id >> 2, c = id & 3;
            int gm = bm + r;
            const __half* gp = A + (long long)(gm < M ? gm : M - 1) * K + ktE + c * 8;
            unsigned dst = sb + (unsigned)(r * 80 + c * 16);
            int zf = (gm < M) ? 16 : 0;
            asm volatile("cp.async.cg.shared.global [%0], [%1], 16, %2;\n"
                         :: "r"(dst), "l"(gp), "r"(zf));
        }
#pragma unroll
        for (int j = 0; j < 2; j++) {
            int id = tid + j * 256;
            int r = id >> 2, c = id & 3;
            int gn = bn + r;
            const __half* gp = Bm + (long long)(gn < N ? gn : N - 1) * K + ktE + c * 8;
            unsigned dst = sb + (unsigned)(ASTB + r * 80 + c * 16);
            int zf = (gn < N) ? 16 : 0;
            asm volatile("cp.async.cg.shared.global [%0], [%1], 16, %2;\n"
                         :: "r"(dst), "l"(gp), "r"(zf));
        }
    };

    float c[4][4][4];
#pragma unroll
    for (int i = 0; i < 4; i++)
#pragma unroll
        for (int j = 0; j < 4; j++)
#pragma unroll
            for (int l = 0; l < 4; l++) c[i][j][l] = 0.f;

    const unsigned aoff = (unsigned)((((lane >> 3) & 1) * 8 + (lane & 7)) * 80 + (lane >> 4) * 16);
    const unsigned boff4 = (unsigned)(ASTB + ((lane & 7) + (lane >> 4) * 8 + wn) * 80
                                      + (((lane >> 3) & 1) * 16));

    const int nk = K / 32;
#pragma unroll 1
    for (int s = 0; s < 3; s++) { issue(s); asm volatile("cp.async.commit_group;\n"); }

#pragma unroll 1
    for (int kt = 0; kt < nk; kt++) {
        asm volatile("cp.async.wait_group 2;\n");
        __syncthreads();
        if (kt + 3 < nk) issue(kt + 3);
        asm volatile("cp.async.commit_group;\n");

        const unsigned stg = sbase + (unsigned)((kt & 3) * STG1);
#pragma unroll
        for (int sub = 0; sub < 2; sub++) {
            unsigned af[4][4], bf[4][2];
#pragma unroll
            for (int mt = 0; mt < 4; mt++) {
                unsigned ad = stg + (unsigned)((wm + mt * 16) * 80 + sub * 32) + aoff;
                asm volatile("ldmatrix.sync.aligned.m8n8.x4.shared.b16 {%0,%1,%2,%3}, [%4];"
                             : "=r"(af[mt][0]), "=r"(af[mt][1]), "=r"(af[mt][2]), "=r"(af[mt][3])
                             : "r"(ad));
            }
#pragma unroll
            for (int ntp = 0; ntp < 2; ntp++) {
                unsigned bd = stg + (unsigned)(ntp * 16 * 80 + sub * 32) + boff4;
                asm volatile("ldmatrix.sync.aligned.m8n8.x4.shared.b16 {%0,%1,%2,%3}, [%4];"
                             : "=r"(bf[2*ntp][0]), "=r"(bf[2*ntp][1]),
                               "=r"(bf[2*ntp+1][0]), "=r"(bf[2*ntp+1][1])
                             : "r"(bd));
            }
#pragma unroll
            for (int mt = 0; mt < 4; mt++)
#pragma unroll
                for (int nt = 0; nt < 4; nt++)
                    mma_f16(c[mt][nt], af[mt], bf[nt]);
        }
    }

#pragma unroll
    for (int mt = 0; mt < 4; mt++) {
#pragma unroll
        for (int nt = 0; nt < 4; nt++) {
            int gm = bm + wm + mt * 16 + row;
            int gn = bn + wn + nt * 8 + col * 2;
            if (gn < N) {
                if (gm < M)
                    *(float2*)(C + (long long)gm * N + gn) = make_float2(c[mt][nt][0], c[mt][nt][1]);
                if (gm + 8 < M)
                    *(float2*)(C + (long long)(gm + 8) * N + gn) = make_float2(c[mt][nt][2], c[mt][nt][3]);
            }
        }
    }
}

// ---------------- weight staging ----------------
__global__ void round4(const float4* __restrict__ s, __half2* __restrict__ d, int n4)
{
    int i = blockIdx.x * 256 + threadIdx.x;
    if (i >= n4) return;
    float4 v = s[i];
    d[i * 2]     = __floats2half2_rn(v.x, v.y);
    d[i * 2 + 1] = __floats2half2_rn(v.z, v.w);
}

#define NW 9
struct RoundDesc {
    const float4* src[NW];
    long long dofs[NW];
    int blkStart[NW + 1];   // block = 4096 floats
};

__global__ void round_many(RoundDesc d, __half* __restrict__ wbuf)
{
    int b = blockIdx.x;
    int w = 0;
#pragma unroll
    for (int i = 0; i < NW; i++) if (b >= d.blkStart[i + 1]) w = i + 1;
    int lb = b - d.blkStart[w];
    const float4* s = d.src[w] + (long long)lb * 1024;
    __half2* o = (__half2*)(wbuf + d.dofs[w]) + (long long)lb * 2048;
    int t = threadIdx.x;
#pragma unroll
    for (int i = 0; i < 4; i++) {
        float4 v = s[t + i * 256];
        o[(t + i * 256) * 2]     = __floats2half2_rn(v.x, v.y);
        o[(t + i * 256) * 2 + 1] = __floats2half2_rn(v.z, v.w);
    }
}

// interleave up/gate columns: out half pairs [2c]=up, [2c+1]=gate
__global__ void interleave2(const float4* __restrict__ up, const float4* __restrict__ gate,
                            uint4* __restrict__ out, long long n4)
{
    long long i0 = (long long)blockIdx.x * 1024 + threadIdx.x;
#pragma unroll
    for (int j = 0; j < 4; j++) {
        long long i = i0 + j * 256;
        if (i >= n4) return;
        float4 u = up[i], g = gate[i];
        __half2 h0 = __floats2half2_rn(u.x, g.x);
        __half2 h1 = __floats2half2_rn(u.y, g.y);
        __half2 h2 = __floats2half2_rn(u.z, g.z);
        __half2 h3 = __floats2half2_rn(u.w, g.w);
        uint4 o;
        o.x = *(unsigned*)&h0; o.y = *(unsigned*)&h1;
        o.z = *(unsigned*)&h2; o.w = *(unsigned*)&h3;
        out[i] = o;
    }
}

// ---------------- row kernels ----------------
__device__ __forceinline__ float blockReduceSum(float v) {
    __shared__ float red[256];
    int t = threadIdx.x;
    red[t] = v; __syncthreads();
    for (int s = 128; s > 0; s >>= 1) {
        if (t < s) red[t] += red[t + s];
        __syncthreads();
    }
    float r = red[0];
    __syncthreads();
    return r;
}

__global__ void rms_scale(const float* __restrict__ x, const float* __restrict__ w,
                          __half* __restrict__ out, int W)
{
    long long base = (long long)blockIdx.x * W;
    float ss = 0.f;
    for (int c = threadIdx.x; c < W; c += 256) { float t = x[base + c]; ss += t * t; }
    float tot = blockReduceSum(ss);
    float inv = rsqrtf(tot / (float)W + EPS_);
    for (int c = threadIdx.x; c < W; c += 256)
        out[base + c] = __float2half_rn(x[base + c] * inv * (1.f + w[c]));
}

__global__ void rms_mod(const float* __restrict__ x, const float* __restrict__ mod,
                        __half* __restrict__ out, int W, int rowsPerB)
{
    long long base = (long long)blockIdx.x * W;
    int b = blockIdx.x / rowsPerB;
    const float* m = mod + (long long)b * 3 * W;
    float ss = 0.f;
    for (int c = threadIdx.x; c < W; c += 256) { float t = x[base + c]; ss += t * t; }
    float tot = blockReduceSum(ss);
    float inv = rsqrtf(tot / (float)W + EPS_);
    for (int c = threadIdx.x; c < W; c += 256)
        out[base + c] = __float2half_rn(x[base + c] * inv * (1.f + m[c]) + m[W + c]);
}

__global__ void modmm2(const float* __restrict__ cond, const float* __restrict__ W,
                       const float* __restrict__ bias, float* __restrict__ out)
{
    const int NT = 3 * W_E_;
    __shared__ float cs[W_E_];
    __shared__ float part[4][64];
    int bb = blockIdx.y;
    int tid = threadIdx.x;
    for (int i = tid; i < W_E_; i += 256) cs[i] = cond[bb * W_E_ + i];
    __syncthreads();
    int tx = tid & 63, ty = tid >> 6;
    int c = blockIdx.x * 64 + tx;
    const float* Wp = W + (long long)(ty * 256) * NT + c;
    const float* cp = cs + ty * 256;
    float s = 0.f;
#pragma unroll 4
    for (int k = 0; k < 256; k++) s += cp[k] * Wp[(long long)k * NT];
    part[ty][tx] = s;
    __syncthreads();
    if (ty == 0)
        out[(long long)bb * NT + c] = part[0][tx] + part[1][tx] + part[2][tx] + part[3][tx] + bias[c];
}

__global__ void rope4h(__half* __restrict__ x, const int* __restrict__ pos, int nh)
{
    int idx = blockIdx.x * blockDim.x + threadIdx.x;
    int total = B_ * S_ * nh * 32;
    if (idx >= total) return;
    int d4 = (idx & 31) << 2;
    int h = (idx >> 5) % nh;
    int s = (idx / (32 * nh)) % S_;
    int b = idx / (32 * nh * S_);
    float p = (float)pos[b * S_ + s];
    __half* base = x + (((long long)(b * S_ + s) * nh + h) << 8);
    __half2 x1a = *(__half2*)(base + d4),       x1b = *(__half2*)(base + d4 + 2);
    __half2 x2a = *(__half2*)(base + d4 + 128), x2b = *(__half2*)(base + d4 + 130);
    float r1[4] = {__low2float(x1a), __high2float(x1a), __low2float(x1b), __high2float(x1b)};
    float r2[4] = {__low2float(x2a), __high2float(x2a), __low2float(x2b), __high2float(x2b)};
#pragma unroll
    for (int j = 0; j < 4; j++) {
        float ang = p * powf(10000.f, -(float)(2 * (d4 + j)) / 256.f);
        float sn, cs2; sincosf(ang, &sn, &cs2);
        float a = r1[j], bb = r2[j];
        r1[j] = a * cs2 - bb * sn;
        r2[j] = bb * cs2 + a * sn;
    }
    *(__half2*)(base + d4)       = __floats2half2_rn(r1[0], r1[1]);
    *(__half2*)(base + d4 + 2)   = __floats2half2_rn(r1[2], r1[3]);
    *(__half2*)(base + d4 + 128) = __floats2half2_rn(r2[0], r2[1]);
    *(__half2*)(base + d4 + 130) = __floats2half2_rn(r2[2], r2[3]);
}

__global__ void q_to_bhsd8h(const uint4* __restrict__ q, uint4* __restrict__ qt)
{
    int idx = blockIdx.x * blockDim.x + threadIdx.x;
    int total = B_ * H_ * S_ * 32;
    if (idx >= total) return;
    int d = idx & 31;
    int s = (idx >> 5) % S_;
    int h = (idx / (32 * S_)) % H_;
    int b = idx / (32 * S_ * H_);
    qt[idx] = q[(((b * S_ + s) * H_ + h) * 32) + d];
}

__global__ void bhsd_to_bshd8h(const uint4* __restrict__ a, uint4* __restrict__ o)
{
    int idx = blockIdx.x * blockDim.x + threadIdx.x;
    int total = B_ * S_ * H_ * 32;
    if (idx >= total) return;
    int d = idx & 31;
    int h = (idx >> 5) % H_;
    int s = (idx / (32 * H_)) % S_;
    int b = idx / (32 * H_ * S_);
    o[idx] = a[(((b * H_ + h) * S_ + s) * 32) + d];
}

__global__ void softmax4h(const float* __restrict__ logits, const float* __restrict__ mask,
                          __half* __restrict__ probs)
{
    int rowid = blockIdx.x;
    int b = rowid / (H_ * S_);
    int q = rowid % S_;
    const float4* row = (const float4*)(logits + (long long)rowid * S_);
    const float4* m = (const float4*)(mask + ((long long)b * S_ + q) * S_);
    __half* prow = probs + (long long)rowid * S_;
    int t = threadIdx.x;
    const bool act = t < 208;
    float4 v = make_float4(-1e30f, -1e30f, -1e30f, -1e30f);
    if (act) {
        float4 lv = row[t], mv = m[t];
        v.x = lv.x * SCALE_ + mv.x; v.y = lv.y * SCALE_ + mv.y;
        v.z = lv.z * SCALE_ + mv.z; v.w = lv.w * SCALE_ + mv.w;
    }
    float mx = fmaxf(fmaxf(v.x, v.y), fmaxf(v.z, v.w));
    __shared__ float red[256];
    red[t] = mx; __syncthreads();
    for (int s = 128; s > 0; s >>= 1) { if (t < s) red[t] = fmaxf(red[t], red[t + s]); __syncthreads(); }
    mx = red[0]; __syncthreads();
    float sum = 0.f;
    if (act) {
        v.x = __expf(v.x - mx); v.y = __expf(v.y - mx);
        v.z = __expf(v.z - mx); v.w = __expf(v.w - mx);
        sum = v.x + v.y + v.z + v.w;
    }
    red[t] = sum; __syncthreads();
    for (int s = 128; s > 0; s >>= 1) { if (t < s) red[t] += red[t + s]; __syncthreads(); }
    float inv = 1.f / red[0];
    if (act) {
        *(__half2*)(prow + t * 4)     = __floats2half2_rn(v.x * inv, v.y * inv);
        *(__half2*)(prow + t * 4 + 2) = __floats2half2_rn(v.z * inv, v.w * inv);
    }
}

// ---------------- host launch ----------------
#define GETSYMF(var, sym) do { void* p__; cudaGetSymbolAddress(&p__, sym); var = (float*)p__; } while (0)
#define GETSYMH(var, sym) do { void* p__; cudaGetSymbolAddress(&p__, sym); var = (__half*)p__; } while (0)

extern "C" void kernel_launch(void* const* d_in, const int* in_sizes, int n_in,
                              void* d_out, int out_size)
{
    const float *embeds_vlm, *embeds_exp, *cond, *attn_mask;
    const int* pos;
    const float *vlm_ln1_w, *vlm_ln2_w, *vlm_q_w, *vlm_k_w, *vlm_v_w, *vlm_o_w;
    const float *vlm_gate_w, *vlm_up_w, *vlm_down_w;
    const float *exp_ln1_dw, *exp_ln1_db, *exp_ln2_dw, *exp_ln2_db;
    const float *exp_q_w, *exp_k_w, *exp_v_w, *exp_o_w, *exp_gate_w, *exp_up_w, *exp_down_w;

    if (in_sizes[3] == B_ * S_) {
        embeds_vlm = (const float*)d_in[0];  embeds_exp = (const float*)d_in[1];
        cond       = (const float*)d_in[2];  pos        = (const int*)  d_in[3];
        attn_mask  = (const float*)d_in[4];
        vlm_ln1_w  = (const float*)d_in[5];  vlm_ln2_w  = (const float*)d_in[6];
        vlm_q_w    = (const float*)d_in[7];  vlm_k_w    = (const float*)d_in[8];
        vlm_v_w    = (const float*)d_in[9];  vlm_o_w    = (const float*)d_in[10];
        vlm_gate_w = (const float*)d_in[11]; vlm_up_w   = (const float*)d_in[12];
        vlm_down_w = (const float*)d_in[13];
        exp_ln1_dw = (const float*)d_in[14]; exp_ln1_db = (const float*)d_in[15];
        exp_ln2_dw = (const float*)d_in[16]; exp_ln2_db = (const float*)d_in[17];
        exp_q_w    = (const float*)d_in[18]; exp_k_w    = (const float*)d_in[19];
        exp_v_w    = (const float*)d_in[20]; exp_o_w    = (const float*)d_in[21];
        exp_gate_w = (const float*)d_in[22]; exp_up_w   = (const float*)d_in[23];
        exp_down_w = (const float*)d_in[24];
    } else {
        embeds_vlm = (const float*)d_in[0];  embeds_exp = (const float*)d_in[1];
        cond       = (const float*)d_in[2];
        vlm_ln1_w  = (const float*)d_in[3];  vlm_ln2_w  = (const float*)d_in[4];
        vlm_q_w    = (const float*)d_in[5];  vlm_k_w    = (const float*)d_in[6];
        vlm_v_w    = (const float*)d_in[7];  vlm_o_w    = (const float*)d_in[8];
        vlm_gate_w = (const float*)d_in[9];  vlm_up_w   = (const float*)d_in[10];
        vlm_down_w = (const float*)d_in[11];
        exp_ln1_dw = (const float*)d_in[12]; exp_ln1_db = (const float*)d_in[13];
        exp_ln2_dw = (const float*)d_in[14]; exp_ln2_db = (const float*)d_in[15];
        exp_q_w    = (const float*)d_in[16]; exp_k_w    = (const float*)d_in[17];
        exp_v_w    = (const float*)d_in[18]; exp_o_w    = (const float*)d_in[19];
        exp_gate_w = (const float*)d_in[20]; exp_up_w   = (const float*)d_in[21];
        exp_down_w = (const float*)d_in[22];
        pos        = (const int*)  d_in[23];
        attn_mask  = (const float*)d_in[24];
    }

    __half *hv, *he, *q, *qt, *k, *v, *probs, *attnt, *attn, *mg, *eg, *wb;
    float *mod1, *mod2, *logits, *hv1, *he1;
    GETSYMH(hv, g_hv);   GETSYMH(he, g_he);   GETSYMF(mod1, g_mod1); GETSYMF(mod2, g_mod2);
    GETSYMH(q, g_q);     GETSYMH(qt, g_qt);   GETSYMH(k, g_k);       GETSYMH(v, g_v);
    GETSYMF(logits, g_logits); GETSYMH(probs, g_probs);
    GETSYMH(attnt, g_attnt);   GETSYMH(attn, g_attn);
    GETSYMF(hv1, g_hv1); GETSYMF(he1, g_he1);
    GETSYMH(mg, g_mg);   GETSYMH(eg, g_eg);   GETSYMH(wb, g_wbuf);

    // wbuf layout: vq | round_many(9) | vlm up+gate interleaved | exp up+gate interleaved
    const long long n_vq = (long long)W_V_ * H_ * DH_;
    const float* srcs[NW] = {vlm_k_w, vlm_v_w, vlm_o_w, vlm_down_w,
                             exp_q_w, exp_k_w, exp_v_w, exp_o_w, exp_down_w};
    long long cnts[NW] = {
        (long long)W_V_*DH_, (long long)W_V_*DH_, (long long)H_*DH_*W_V_, (long long)MLPV_*W_V_,
        (long long)W_E_*H_*DH_, (long long)W_E_*DH_, (long long)W_E_*DH_,
        (long long)H_*DH_*W_E_, (long long)MLPE_*W_E_};
    RoundDesc rd;
    long long ofs = n_vq; int blk = 0;
    const __half* wptr[NW];
    for (int i = 0; i < NW; i++) {
        rd.src[i] = (const float4*)srcs[i];
        rd.dofs[i] = ofs;
        rd.blkStart[i] = blk;
        wptr[i] = wb + ofs;
        ofs += cnts[i];
        blk += (int)(cnts[i] / 4096);
    }
    rd.blkStart[NW] = blk;
    const __half* w_vq = wb;
    const __half *w_vk = wptr[0], *w_vv = wptr[1], *w_vo = wptr[2], *w_vd = wptr[3];
    const __half *w_eq = wptr[4], *w_ek = wptr[5], *w_ev = wptr[6];
    const __half *w_eo = wptr[7], *w_ed = wptr[8];
    const __half* w_vug = wb + ofs;                       // vlm up/gate interleaved: K=2048, N'=32768
    ofs += (long long)W_V_ * 2 * MLPV_;
    const __half* w_eug = wb + ofs;                       // exp up/gate interleaved: K=1024, N'=8192
    ofs += (long long)W_E_ * 2 * MLPE_;

    const int SMG  = 4 * STGB;
    const int SMT  = 4 * STG1;
    const int SM64 = 3 * STG64;
    cudaFuncSetAttribute(gemm16<0>, cudaFuncAttributeMaxDynamicSharedMemorySize, SMG);
    cudaFuncSetAttribute(gemm16<4>, cudaFuncAttributeMaxDynamicSharedMemorySize, SMG);
    cudaFuncSetAttribute(gemm16<6>, cudaFuncAttributeMaxDynamicSharedMemorySize, SMG);
    cudaFuncSetAttribute(gemm16_tb1, cudaFuncAttributeMaxDynamicSharedMemorySize, SMT);
    cudaFuncSetAttribute(gemm16m64<0>, cudaFuncAttributeMaxDynamicSharedMemorySize, SM64);
    cudaFuncSetAttribute(gemm16m64<3>, cudaFuncAttributeMaxDynamicSharedMemorySize, SM64);

    float* out_v = (float*)d_out;
    float* out_e = (float*)d_out + (long long)B_ * S_V_ * W_V_;

    long long sHv = (long long)S_V_ * W_V_, sHe = (long long)S_E_ * W_E_;
    long long sQ = (long long)S_ * H_ * DH_, sK = (long long)S_ * DH_;
    long long sL = (long long)S_ * S_;

    // L0..L2
    round4<<<(int)((n_vq / 4 + 255) / 256), 256>>>((const float4*)vlm_q_w, (__half2*)wb, (int)(n_vq / 4));
    rms_scale<<<B_ * S_V_, 256>>>(embeds_vlm, vlm_ln1_w, hv, W_V_);
    modmm2<<<dim3(48, B_), 256>>>(cond, exp_ln1_dw, exp_ln1_db, mod1);
    // L3: VLM Q projection (ncu target)
    gemm16m64<0><<<dim3(16, 12, B_), 128, SM64>>>(hv, w_vq, q, nullptr, S_V_, H_ * DH_, W_V_, sHv, 0, sQ, 1);
    // staging remainder
    round_many<<<blk, 256>>>(rd, wb);
    {
        long long n4v = (long long)W_V_ * MLPV_ / 4;
        interleave2<<<(int)((n4v + 1023) / 1024), 256>>>((const float4*)vlm_up_w, (const float4*)vlm_gate_w, (uint4*)w_vug, n4v);
        long long n4e = (long long)W_E_ * MLPE_ / 4;
        interleave2<<<(int)((n4e + 1023) / 1024), 256>>>((const float4*)exp_up_w, (const float4*)exp_gate_w, (uint4*)w_eug, n4e);
    }
    rms_mod<<<B_ * S_E_, 256>>>(embeds_exp, mod1, he, W_E_, S_E_);
    modmm2<<<dim3(48, B_), 256>>>(cond, exp_ln2_dw, exp_ln2_db, mod2);

    // QKV remainder
    gemm16m64<0><<<dim3(16, 1, B_), 128, SM64>>>(he, w_eq, q + (long long)S_V_ * H_ * DH_, nullptr, S_E_, H_ * DH_, W_E_, sHe, 0, sQ, 1);
    gemm16<0><<<dim3(2, 6, B_), 256, SMG>>>(hv, w_vk, k, nullptr, nullptr, S_V_, DH_, W_V_, sHv, 0, sK, 1);
    gemm16<0><<<dim3(2, 1, B_), 256, SMG>>>(he, w_ek, k + S_V_ * DH_, nullptr, nullptr, S_E_, DH_, W_E_, sHe, 0, sK, 1);
    gemm16<0><<<dim3(2, 6, B_), 256, SMG>>>(hv, w_vv, v, nullptr, nullptr, S_V_, DH_, W_V_, sHv, 0, sK, 1);
    gemm16<0><<<dim3(2, 1, B_), 256, SMG>>>(he, w_ev, v + S_V_ * DH_, nullptr, nullptr, S_E_, DH_, W_E_, sHe, 0, sK, 1);

    // RoPE
    rope4h<<<(B_ * S_ * H_ * 32 + 255) / 256, 256>>>(q, pos, H_);
    rope4h<<<(B_ * S_ * 1 * 32 + 255) / 256, 256>>>(k, pos, 1);

    // attention
    {
        int nq8 = B_ * H_ * S_ * 32;
        q_to_bhsd8h<<<(nq8 + 255) / 256, 256>>>((const uint4*)q, (uint4*)qt);
        gemm16_tb1<<<dim3(7, 7, B_ * H_), 256, SMT>>>(qt, k, logits, S_, S_, DH_, sK, sK, sL, H_);
        softmax4h<<<B_ * H_ * S_, 256>>>(logits, attn_mask, probs);
        gemm16m64<0><<<dim3(2, 13, B_ * H_), 128, SM64>>>(probs, v, attnt, nullptr, S_, DH_, S_, sL, sK, sK, H_);
        bhsd_to_bshd8h<<<(nq8 + 255) / 256, 256>>>((const uint4*)attnt, (uint4*)attn);
    }

    // output projections + residuals
    {
        long long sA = (long long)S_ * H_ * DH_;
        gemm16m64<3><<<dim3(16, 12, B_), 128, SM64>>>(attn, w_vo, hv1, embeds_vlm, S_V_, W_V_, H_ * DH_, sA, 0, sHv, 1);
        gemm16<4><<<dim3(8, 1, B_), 256, SMG>>>(attn + (long long)S_V_ * H_ * DH_, w_eo, he1, embeds_exp, mod1, S_E_, W_E_, H_ * DH_, sA, 0, sHe, 1);
    }

    // pre-MLP norms
    rms_scale<<<B_ * S_V_, 256>>>(hv1, vlm_ln2_w, hv, W_V_);
    rms_mod<<<B_ * S_E_, 256>>>(he1, mod2, he, W_E_, S_E_);

    // VLM MLP: fused up+gate (interleaved weights) -> mg fp16, then down with residual
    {
        int M = B_ * S_V_;
        gemm16<6><<<dim3(256, 24, 1), 256, SMG>>>(hv, w_vug, mg, nullptr, nullptr, M, 2 * MLPV_, W_V_, 0, 0, 0, 1);
        gemm16m64<3><<<dim3(16, 48, 1), 128, SM64>>>(mg, w_vd, out_v, hv1, M, W_V_, MLPV_, 0, 0, 0, 1);
    }

    // expert MLP: fused up+gate, then gated-residual down
    {
        int M = B_ * S_E_;
        gemm16<6><<<dim3(64, 2, 1), 256, SMG>>>(he, w_eug, eg, nullptr, nullptr, M, 2 * MLPE_, W_E_, 0, 0, 0, 1);
        gemm16<4><<<dim3(8, 2, 1), 256, SMG>>>(eg, w_ed, out_e, he1, mod2, M, W_E_, MLPE_, 0, 0, 0, 1);
    }
}

// round 14
// speedup vs baseline: 1.1868x; 1.0106x over previous
#include <cuda_runtime.h>
#include <cuda_fp16.h>
#include <cuda_bf16.h>
#include <math.h>

#define B_    4
#define S_V_  768
#define S_E_  64
#define S_    832
#define W_V_  2048
#define W_E_  1024
#define H_    8
#define DH_   256
#define MLPV_ 16384
#define MLPE_ 4096
#define EPS_  1e-6f
#define SCALE_ 0.0625f

// ---------------- scratch ----------------
__device__ __half g_hv   [B_*S_V_*W_V_];
__device__ __half g_he   [B_*S_E_*W_E_];
__device__ float  g_mod1 [B_*3*W_E_];
__device__ float  g_mod2 [B_*3*W_E_];
__device__ __half g_q    [(long long)B_*S_*H_*DH_];
__device__ __half g_qt   [(long long)B_*H_*S_*DH_];
__device__ __half g_k    [B_*S_*DH_];
__device__ __half g_v    [B_*S_*DH_];
__device__ __half g_probs[(long long)B_*H_*S_*S_];
__device__ __half g_attnt[(long long)B_*H_*S_*DH_];
__device__ __half g_attn [(long long)B_*S_*H_*DH_];
__device__ float  g_hv1  [B_*S_V_*W_V_];
__device__ float  g_he1  [B_*S_E_*W_E_];
__device__ __half g_mg   [(long long)B_*S_V_*MLPV_];
__device__ __half g_eg   [B_*S_E_*MLPE_];
__device__ __half g_wbuf [127401984];

__device__ __forceinline__ float gelu_t(float x) {
    return 0.5f * x * (1.f + tanhf(0.7978845608028654f * (x + 0.044715f * x * x * x)));
}

__device__ __forceinline__ void mma_f16(float* c, const unsigned* a, const unsigned* b) {
    asm volatile(
        "mma.sync.aligned.m16n8k16.row.col.f32.f16.f16.f32 "
        "{%0,%1,%2,%3}, {%4,%5,%6,%7}, {%8,%9}, {%0,%1,%2,%3};\n"
        : "+f"(c[0]), "+f"(c[1]), "+f"(c[2]), "+f"(c[3])
        : "r"(a[0]), "r"(a[1]), "r"(a[2]), "r"(a[3]), "r"(b[0]), "r"(b[1]));
}

// ============ gemm16: fp16 operands, fp32 accum, TB=0 ============
// Block 128x128, 256 thr, 8 warps (2m x 4n) of 64x32, K-tile 32, 4 stages.
// EPI: 0 plain->fp16, 3 fp32(c+aux), 4 fp32 gated residual,
//      6 fused glu: pairs (even=up,odd=gate) -> fp16 gelu(x1)*x0 at N/2 stride
#define ASTB 10240
#define STGB 18944
template<int EPI>
__global__ __launch_bounds__(256, 2)
void gemm16(const __half* __restrict__ A, const __half* __restrict__ Bm,
            void* __restrict__ Cv, const float* __restrict__ aux,
            const float* __restrict__ modv,
            int M, int N, int K,
            long long sA, long long sB, long long sC, int bInner)
{
    extern __shared__ __align__(16) char sm[];

    const int z = blockIdx.z;
    A  += (long long)z * sA;
    Bm += (long long)(z / bInner) * sB;

    const int tid  = threadIdx.x;
    const int lane = tid & 31;
    const int wid  = tid >> 5;
    const int wm   = (wid & 1) * 64;
    const int wn   = (wid >> 1) * 32;
    const int bm   = blockIdx.y * 128;
    const int bn   = blockIdx.x * 128;
    const int row  = lane >> 2, col = lane & 3;

    unsigned sbase = (unsigned)__cvta_generic_to_shared(sm);

    auto issue = [&](int st) {
        const int ktE = st * 32;
        const unsigned sb = sbase + (unsigned)((st & 3) * STGB);
#pragma unroll
        for (int j = 0; j < 2; j++) {
            int id = tid + j * 256;
            int r = id >> 2, c = id & 3;
            int gm = bm + r;
            const __half* gp = A + (long long)(gm < M ? gm : M - 1) * K + ktE + c * 8;
            unsigned dst = sb + (unsigned)(r * 80 + c * 16);
            int zf = (gm < M) ? 16 : 0;
            asm volatile("cp.async.cg.shared.global [%0], [%1], 16, %2;\n"
                         :: "r"(dst), "l"(gp), "r"(zf));
        }
#pragma unroll
        for (int j = 0; j < 2; j++) {
            int id = tid + j * 256;
            int kr = id >> 4, c = id & 15;
            int gn = bn + c * 8;
            const __half* gp = Bm + (long long)(ktE + kr) * N + (gn < N ? gn : N - 8);
            unsigned dst = sb + (unsigned)(ASTB + kr * 272 + c * 16);
            int zf = (gn < N) ? 16 : 0;
            asm volatile("cp.async.cg.shared.global [%0], [%1], 16, %2;\n"
                         :: "r"(dst), "l"(gp), "r"(zf));
        }
    };

    float c[4][4][4];
#pragma unroll
    for (int i = 0; i < 4; i++)
#pragma unroll
        for (int j = 0; j < 4; j++)
#pragma unroll
            for (int l = 0; l < 4; l++) c[i][j][l] = 0.f;

    const unsigned aoff = (unsigned)((((lane >> 3) & 1) * 8 + (lane & 7)) * 80 + (lane >> 4) * 16);
    const unsigned boff4 = (unsigned)(ASTB + (((lane >> 3) & 1) * 8 + (lane & 7)) * 272
                                      + (lane >> 4) * 16 + wn * 2);

    const int nk = K / 32;
#pragma unroll 1
    for (int s = 0; s < 3; s++) { issue(s); asm volatile("cp.async.commit_group;\n"); }

#pragma unroll 1
    for (int kt = 0; kt < nk; kt++) {
        asm volatile("cp.async.wait_group 2;\n");
        __syncthreads();
        if (kt + 3 < nk) issue(kt + 3);
        asm volatile("cp.async.commit_group;\n");

        const unsigned stg = sbase + (unsigned)((kt & 3) * STGB);
#pragma unroll
        for (int sub = 0; sub < 2; sub++) {
            unsigned af[4][4], bf[4][2];
#pragma unroll
            for (int mt = 0; mt < 4; mt++) {
                unsigned ad = stg + (unsigned)((wm + mt * 16) * 80 + sub * 32) + aoff;
                asm volatile("ldmatrix.sync.aligned.m8n8.x4.shared.b16 {%0,%1,%2,%3}, [%4];"
                             : "=r"(af[mt][0]), "=r"(af[mt][1]), "=r"(af[mt][2]), "=r"(af[mt][3])
                             : "r"(ad));
            }
#pragma unroll
            for (int ntp = 0; ntp < 2; ntp++) {
                unsigned bd = stg + (unsigned)(sub * 16 * 272 + ntp * 32) + boff4;
                asm volatile("ldmatrix.sync.aligned.m8n8.x4.trans.shared.b16 {%0,%1,%2,%3}, [%4];"
                             : "=r"(bf[2*ntp][0]), "=r"(bf[2*ntp][1]),
                               "=r"(bf[2*ntp+1][0]), "=r"(bf[2*ntp+1][1])
                             : "r"(bd));
            }
#pragma unroll
            for (int mt = 0; mt < 4; mt++)
#pragma unroll
                for (int nt = 0; nt < 4; nt++)
                    mma_f16(c[mt][nt], af[mt], bf[nt]);
        }
    }

    if (EPI == 3 || EPI == 4) aux += (long long)z * sC;
    __half* Ch = (__half*)Cv + (long long)z * sC;
    float*  Cf = (float*)Cv + (long long)z * sC;

    auto epi_store = [&](int gm, int gn, float x0, float x1) {
        if (EPI == 6) {
            Ch[(long long)gm * (N >> 1) + (gn >> 1)] = __float2half_rn(gelu_t(x1) * x0);
            return;
        }
        long long o = (long long)gm * N + gn;
        if (EPI == 0) {
            *(__half2*)(Ch + o) = __halves2half2(__float2half_rn(x0), __float2half_rn(x1));
        } else if (EPI == 3) {
            float2 u = *(const float2*)(aux + o);
            *(float2*)(Cf + o) = make_float2(x0 + u.x, x1 + u.y);
        } else if (EPI == 4) {
            int bb = z + gm / S_E_;
            float g0 = modv[(long long)bb * 3 * W_E_ + 2 * W_E_ + gn];
            float g1 = modv[(long long)bb * 3 * W_E_ + 2 * W_E_ + gn + 1];
            float2 u = *(const float2*)(aux + o);
            *(float2*)(Cf + o) = make_float2(u.x + x0 * g0, u.y + x1 * g1);
        }
    };

#pragma unroll
    for (int mt = 0; mt < 4; mt++) {
#pragma unroll
        for (int nt = 0; nt < 4; nt++) {
            int gm = bm + wm + mt * 16 + row;
            int gn = bn + wn + nt * 8 + col * 2;
            if (gn < N) {
                if (gm < M)     epi_store(gm,     gn, c[mt][nt][0], c[mt][nt][1]);
                if (gm + 8 < M) epi_store(gm + 8, gn, c[mt][nt][2], c[mt][nt][3]);
            }
        }
    }
}

// ============ gemm16m64: 64x128 tile, 128 thr (4 warps 1m x 4n), 4 stages ====
#define A64B 5120
#define STG64 (A64B + 8704)
template<int EPI>
__global__ __launch_bounds__(128, 4)
void gemm16m64(const __half* __restrict__ A, const __half* __restrict__ Bm,
               void* __restrict__ Cv, const float* __restrict__ aux,
               int M, int N, int K, long long sA, long long sB, long long sC, int bInner)
{
    extern __shared__ __align__(16) char sm[];

    const int z = blockIdx.z;
    A  += (long long)z * sA;
    Bm += (long long)(z / bInner) * sB;

    const int tid  = threadIdx.x;
    const int lane = tid & 31;
    const int wid  = tid >> 5;
    const int wn   = wid * 32;
    const int bm   = blockIdx.y * 64;
    const int bn   = blockIdx.x * 128;
    const int row  = lane >> 2, col = lane & 3;

    unsigned sbase = (unsigned)__cvta_generic_to_shared(sm);

    auto issue = [&](int st) {
        const int ktE = st * 32;
        const unsigned sb = sbase + (unsigned)((st & 3) * STG64);
#pragma unroll
        for (int j = 0; j < 2; j++) {
            int id = tid + j * 128;
            int r = id >> 2, c = id & 3;
            int gm = bm + r;
            const __half* gp = A + (long long)(gm < M ? gm : M - 1) * K + ktE + c * 8;
            unsigned dst = sb + (unsigned)(r * 80 + c * 16);
            int zf = (gm < M) ? 16 : 0;
            asm volatile("cp.async.cg.shared.global [%0], [%1], 16, %2;\n"
                         :: "r"(dst), "l"(gp), "r"(zf));
        }
#pragma unroll
        for (int j = 0; j < 4; j++) {
            int id = tid + j * 128;
            int kr = id >> 4, c = id & 15;
            int gn = bn + c * 8;
            const __half* gp = Bm + (long long)(ktE + kr) * N + (gn < N ? gn : N - 8);
            unsigned dst = sb + (unsigned)(A64B + kr * 272 + c * 16);
            int zf = (gn < N) ? 16 : 0;
            asm volatile("cp.async.cg.shared.global [%0], [%1], 16, %2;\n"
                         :: "r"(dst), "l"(gp), "r"(zf));
        }
    };

    float c[4][4][4];
#pragma unroll
    for (int i = 0; i < 4; i++)
#pragma unroll
        for (int j = 0; j < 4; j++)
#pragma unroll
            for (int l = 0; l < 4; l++) c[i][j][l] = 0.f;

    const unsigned aoff = (unsigned)((((lane >> 3) & 1) * 8 + (lane & 7)) * 80 + (lane >> 4) * 16);
    const unsigned boff4 = (unsigned)(A64B + (((lane >> 3) & 1) * 8 + (lane & 7)) * 272
                                      + (lane >> 4) * 16 + wn * 2);

    const int nk = K / 32;
#pragma unroll 1
    for (int s = 0; s < 3; s++) { issue(s); asm volatile("cp.async.commit_group;\n"); }

#pragma unroll 1
    for (int kt = 0; kt < nk; kt++) {
        asm volatile("cp.async.wait_group 2;\n");
        __syncthreads();
        if (kt + 3 < nk) issue(kt + 3);
        asm volatile("cp.async.commit_group;\n");

        const unsigned stg = sbase + (unsigned)((kt & 3) * STG64);
#pragma unroll
        for (int sub = 0; sub < 2; sub++) {
            unsigned af[4][4], bf[4][2];
#pragma unroll
            for (int mt = 0; mt < 4; mt++) {
                unsigned ad = stg + (unsigned)((mt * 16) * 80 + sub * 32) + aoff;
                asm volatile("ldmatrix.sync.aligned.m8n8.x4.shared.b16 {%0,%1,%2,%3}, [%4];"
                             : "=r"(af[mt][0]), "=r"(af[mt][1]), "=r"(af[mt][2]), "=r"(af[mt][3])
                             : "r"(ad));
            }
#pragma unroll
            for (int ntp = 0; ntp < 2; ntp++) {
                unsigned bd = stg + (unsigned)(sub * 16 * 272 + ntp * 32) + boff4;
                asm volatile("ldmatrix.sync.aligned.m8n8.x4.trans.shared.b16 {%0,%1,%2,%3}, [%4];"
                             : "=r"(bf[2*ntp][0]), "=r"(bf[2*ntp][1]),
                               "=r"(bf[2*ntp+1][0]), "=r"(bf[2*ntp+1][1])
                             : "r"(bd));
            }
#pragma unroll
            for (int mt = 0; mt < 4; mt++)
#pragma unroll
                for (int nt = 0; nt < 4; nt++)
                    mma_f16(c[mt][nt], af[mt], bf[nt]);
        }
    }

    if (EPI == 3) aux += (long long)z * sC;
    __half* Ch = (__half*)Cv + (long long)z * sC;
    float*  Cf = (float*)Cv + (long long)z * sC;

#pragma unroll
    for (int mt = 0; mt < 4; mt++) {
#pragma unroll
        for (int nt = 0; nt < 4; nt++) {
            int gm = bm + mt * 16 + row;
            int gn = bn + wn + nt * 8 + col * 2;
            if (gn >= N) continue;
#pragma unroll
            for (int hh = 0; hh < 2; hh++) {
                int g = gm + hh * 8;
                if (g >= M) continue;
                long long o = (long long)g * N + gn;
                float x0 = c[mt][nt][hh * 2], x1 = c[mt][nt][hh * 2 + 1];
                if (EPI == 0) {
                    *(__half2*)(Ch + o) = __halves2half2(__float2half_rn(x0), __float2half_rn(x1));
                } else {
                    float2 u = *(const float2*)(aux + o);
                    *(float2*)(Cf + o) = make_float2(x0 + u.x, x1 + u.y);
                }
            }
        }
    }
}

// ============ gemm16_tb1: QK^T, fused scale+mask -> fp16 probs buffer ============
#define STG1 20480
__global__ __launch_bounds__(256, 2)
void gemm16_tb1(const __half* __restrict__ A, const __half* __restrict__ Bm,
                __half* __restrict__ C, const float* __restrict__ mask,
                int M, int N, int K,
                long long sA, long long sB, long long sC, int bInner)
{
    extern __shared__ __align__(16) char sm[];

    const int z = blockIdx.z;
    A  += (long long)z * sA;
    Bm += (long long)(z / bInner) * sB;
    C  += (long long)z * sC;
    const float* mrow = mask + (long long)(z >> 3) * S_ * S_;

    const int tid  = threadIdx.x;
    const int lane = tid & 31;
    const int wid  = tid >> 5;
    const int wm   = (wid & 1) * 64;
    const int wn   = (wid >> 1) * 32;
    const int bm   = blockIdx.y * 128;
    const int bn   = blockIdx.x * 128;
    const int row  = lane >> 2, col = lane & 3;

    unsigned sbase = (unsigned)__cvta_generic_to_shared(sm);

    auto issue = [&](int st) {
        const int ktE = st * 32;
        const unsigned sb = sbase + (unsigned)((st & 3) * STG1);
#pragma unroll
        for (int j = 0; j < 2; j++) {
            int id = tid + j * 256;
            int r = id >> 2, c = id & 3;
            int gm = bm + r;
            const __half* gp = A + (long long)(gm < M ? gm : M - 1) * K + ktE + c * 8;
            unsigned dst = sb + (unsigned)(r * 80 + c * 16);
            int zf = (gm < M) ? 16 : 0;
            asm volatile("cp.async.cg.shared.global [%0], [%1], 16, %2;\n"
                         :: "r"(dst), "l"(gp), "r"(zf));
        }
#pragma unroll
        for (int j = 0; j < 2; j++) {
            int id = tid + j * 256;
            int r = id >> 2, c = id & 3;
            int gn = bn + r;
            const __half* gp = Bm + (long long)(gn < N ? gn : N - 1) * K + ktE + c * 8;
            unsigned dst = sb + (unsigned)(ASTB + r * 80 + c * 16);
            int zf = (gn < N) ? 16 : 0;
            asm volatile("cp.async.cg.shared.global [%0], [%1], 16, %2;\n"
                         :: "r"(dst), "l"(gp), "r"(zf));
        }
    };

    float c[4][4][4];
#pragma unroll
    for (int i = 0; i < 4; i++)
#pragma unroll
        for (int j = 0; j < 4; j++)
#pragma unroll
            for (int l = 0; l < 4; l++) c[i][j][l] = 0.f;

    const unsigned aoff = (unsigned)((((lane >> 3) & 1) * 8 + (lane & 7)) * 80 + (lane >> 4) * 16);
    const unsigned boff4 = (unsigned)(ASTB + ((lane & 7) + (lane >> 4) * 8 + wn) * 80
                                      + (((lane >> 3) & 1) * 16));

    const int nk = K / 32;
#pragma unroll 1
    for (int s = 0; s < 3; s++) { issue(s); asm volatile("cp.async.commit_group;\n"); }

#pragma unroll 1
    for (int kt = 0; kt < nk; kt++) {
        asm volatile("cp.async.wait_group 2;\n");
        __syncthreads();
        if (kt + 3 < nk) issue(kt + 3);
        asm volatile("cp.async.commit_group;\n");

        const unsigned stg = sbase + (unsigned)((kt & 3) * STG1);
#pragma unroll
        for (int sub = 0; sub < 2; sub++) {
            unsigned af[4][4], bf[4][2];
#pragma unroll
            for (int mt = 0; mt < 4; mt++) {
                unsigned ad = stg + (unsigned)((wm + mt * 16) * 80 + sub * 32) + aoff;
                asm volatile("ldmatrix.sync.aligned.m8n8.x4.shared.b16 {%0,%1,%2,%3}, [%4];"
                             : "=r"(af[mt][0]), "=r"(af[mt][1]), "=r"(af[mt][2]), "=r"(af[mt][3])
                             : "r"(ad));
            }
#pragma unroll
            for (int ntp = 0; ntp < 2; ntp++) {
                unsigned bd = stg + (unsigned)(ntp * 16 * 80 + sub * 32) + boff4;
                asm volatile("ldmatrix.sync.aligned.m8n8.x4.shared.b16 {%0,%1,%2,%3}, [%4];"
                             : "=r"(bf[2*ntp][0]), "=r"(bf[2*ntp][1]),
                               "=r"(bf[2*ntp+1][0]), "=r"(bf[2*ntp+1][1])
                             : "r"(bd));
            }
#pragma unroll
            for (int mt = 0; mt < 4; mt++)
#pragma unroll
                for (int nt = 0; nt < 4; nt++)
                    mma_f16(c[mt][nt], af[mt], bf[nt]);
        }
    }

#pragma unroll
    for (int mt = 0; mt < 4; mt++) {
#pragma unroll
        for (int nt = 0; nt < 4; nt++) {
            int gm = bm + wm + mt * 16 + row;
            int gn = bn + wn + nt * 8 + col * 2;
            if (gn >= N) continue;
#pragma unroll
            for (int hh = 0; hh < 2; hh++) {
                int g = gm + hh * 8;
                if (g >= M) continue;
                float2 mv = *(const float2*)(mrow + (long long)g * S_ + gn);
                float x0 = c[mt][nt][hh * 2] * SCALE_ + mv.x;
                float x1 = c[mt][nt][hh * 2 + 1] * SCALE_ + mv.y;
                *(__half2*)(C + (long long)g * N + gn) = __floats2half2_rn(x0, x1);
            }
        }
    }
}

// ---------------- weight staging ----------------
__global__ void round4(const float4* __restrict__ s, __half2* __restrict__ d, int n4)
{
    int i = blockIdx.x * 256 + threadIdx.x;
    if (i >= n4) return;
    float4 v = s[i];
    d[i * 2]     = __floats2half2_rn(v.x, v.y);
    d[i * 2 + 1] = __floats2half2_rn(v.z, v.w);
}

#define NW 9
struct RoundDesc {
    const float4* src[NW];
    long long dofs[NW];
    int blkStart[NW + 1];
};

__global__ void round_many(RoundDesc d, __half* __restrict__ wbuf)
{
    int b = blockIdx.x;
    int w = 0;
#pragma unroll
    for (int i = 0; i < NW; i++) if (b >= d.blkStart[i + 1]) w = i + 1;
    int lb = b - d.blkStart[w];
    const float4* s = d.src[w] + (long long)lb * 1024;
    __half2* o = (__half2*)(wbuf + d.dofs[w]) + (long long)lb * 2048;
    int t = threadIdx.x;
#pragma unroll
    for (int i = 0; i < 4; i++) {
        float4 v = s[t + i * 256];
        o[(t + i * 256) * 2]     = __floats2half2_rn(v.x, v.y);
        o[(t + i * 256) * 2 + 1] = __floats2half2_rn(v.z, v.w);
    }
}

__global__ void interleave2(const float4* __restrict__ up, const float4* __restrict__ gate,
                            uint4* __restrict__ out, long long n4)
{
    long long i0 = (long long)blockIdx.x * 1024 + threadIdx.x;
#pragma unroll
    for (int j = 0; j < 4; j++) {
        long long i = i0 + j * 256;
        if (i >= n4) return;
        float4 u = up[i], g = gate[i];
        __half2 h0 = __floats2half2_rn(u.x, g.x);
        __half2 h1 = __floats2half2_rn(u.y, g.y);
        __half2 h2 = __floats2half2_rn(u.z, g.z);
        __half2 h3 = __floats2half2_rn(u.w, g.w);
        uint4 o;
        o.x = *(unsigned*)&h0; o.y = *(unsigned*)&h1;
        o.z = *(unsigned*)&h2; o.w = *(unsigned*)&h3;
        out[i] = o;
    }
}

// ---------------- row kernels ----------------
__device__ __forceinline__ float blockReduceSum(float v) {
    __shared__ float red[256];
    int t = threadIdx.x;
    red[t] = v; __syncthreads();
    for (int s = 128; s > 0; s >>= 1) {
        if (t < s) red[t] += red[t + s];
        __syncthreads();
    }
    float r = red[0];
    __syncthreads();
    return r;
}

__global__ void rms_scale(const float* __restrict__ x, const float* __restrict__ w,
                          __half* __restrict__ out, int W)
{
    long long base = (long long)blockIdx.x * W;
    float ss = 0.f;
    for (int c = threadIdx.x; c < W; c += 256) { float t = x[base + c]; ss += t * t; }
    float tot = blockReduceSum(ss);
    float inv = rsqrtf(tot / (float)W + EPS_);
    for (int c = threadIdx.x; c < W; c += 256)
        out[base + c] = __float2half_rn(x[base + c] * inv * (1.f + w[c]));
}

__global__ void rms_mod(const float* __restrict__ x, const float* __restrict__ mod,
                        __half* __restrict__ out, int W, int rowsPerB)
{
    long long base = (long long)blockIdx.x * W;
    int b = blockIdx.x / rowsPerB;
    const float* m = mod + (long long)b * 3 * W;
    float ss = 0.f;
    for (int c = threadIdx.x; c < W; c += 256) { float t = x[base + c]; ss += t * t; }
    float tot = blockReduceSum(ss);
    float inv = rsqrtf(tot / (float)W + EPS_);
    for (int c = threadIdx.x; c < W; c += 256)
        out[base + c] = __float2half_rn(x[base + c] * inv * (1.f + m[c]) + m[W + c]);
}

__global__ void modmm2(const float* __restrict__ cond, const float* __restrict__ W,
                       const float* __restrict__ bias, float* __restrict__ out)
{
    const int NT = 3 * W_E_;
    __shared__ float cs[W_E_];
    __shared__ float part[4][64];
    int bb = blockIdx.y;
    int tid = threadIdx.x;
    for (int i = tid; i < W_E_; i += 256) cs[i] = cond[bb * W_E_ + i];
    __syncthreads();
    int tx = tid & 63, ty = tid >> 6;
    int c = blockIdx.x * 64 + tx;
    const float* Wp = W + (long long)(ty * 256) * NT + c;
    const float* cp = cs + ty * 256;
    float s = 0.f;
#pragma unroll 4
    for (int k = 0; k < 256; k++) s += cp[k] * Wp[(long long)k * NT];
    part[ty][tx] = s;
    __syncthreads();
    if (ty == 0)
        out[(long long)bb * NT + c] = part[0][tx] + part[1][tx] + part[2][tx] + part[3][tx] + bias[c];
}

// in-place RoPE for k (b,s,1,256)
__global__ void rope4h(__half* __restrict__ x, const int* __restrict__ pos, int nh)
{
    int idx = blockIdx.x * blockDim.x + threadIdx.x;
    int total = B_ * S_ * nh * 32;
    if (idx >= total) return;
    int d4 = (idx & 31) << 2;
    int h = (idx >> 5) % nh;
    int s = (idx / (32 * nh)) % S_;
    int b = idx / (32 * nh * S_);
    float p = (float)pos[b * S_ + s];
    __half* base = x + (((long long)(b * S_ + s) * nh + h) << 8);
    __half2 x1a = *(__half2*)(base + d4),       x1b = *(__half2*)(base + d4 + 2);
    __half2 x2a = *(__half2*)(base + d4 + 128), x2b = *(__half2*)(base + d4 + 130);
    float r1[4] = {__low2float(x1a), __high2float(x1a), __low2float(x1b), __high2float(x1b)};
    float r2[4] = {__low2float(x2a), __high2float(x2a), __low2float(x2b), __high2float(x2b)};
#pragma unroll
    for (int j = 0; j < 4; j++) {
        float ang = p * powf(10000.f, -(float)(2 * (d4 + j)) / 256.f);
        float sn, cs2; sincosf(ang, &sn, &cs2);
        float a = r1[j], bb = r2[j];
        r1[j] = a * cs2 - bb * sn;
        r2[j] = bb * cs2 + a * sn;
    }
    *(__half2*)(base + d4)       = __floats2half2_rn(r1[0], r1[1]);
    *(__half2*)(base + d4 + 2)   = __floats2half2_rn(r1[2], r1[3]);
    *(__half2*)(base + d4 + 128) = __floats2half2_rn(r2[0], r2[1]);
    *(__half2*)(base + d4 + 130) = __floats2half2_rn(r2[2], r2[3]);
}

// RoPE for q fused with (b,s,h,d) -> (b,h,s,d) transpose
__global__ void rope4h_t(const __half* __restrict__ q, __half* __restrict__ qt,
                         const int* __restrict__ pos)
{
    int idx = blockIdx.x * blockDim.x + threadIdx.x;
    int total = B_ * S_ * H_ * 32;
    if (idx >= total) return;
    int d4 = (idx & 31) << 2;
    int h = (idx >> 5) % H_;
    int s = (idx / (32 * H_)) % S_;
    int b = idx / (32 * H_ * S_);
    float p = (float)pos[b * S_ + s];
    const __half* src = q + (((long long)(b * S_ + s) * H_ + h) << 8);
    __half* dst = qt + (((long long)(b * H_ + h) * S_ + s) << 8);
    __half2 x1a = *(const __half2*)(src + d4),       x1b = *(const __half2*)(src + d4 + 2);
    __half2 x2a = *(const __half2*)(src + d4 + 128), x2b = *(const __half2*)(src + d4 + 130);
    float r1[4] = {__low2float(x1a), __high2float(x1a), __low2float(x1b), __high2float(x1b)};
    float r2[4] = {__low2float(x2a), __high2float(x2a), __low2float(x2b), __high2float(x2b)};
#pragma unroll
    for (int j = 0; j < 4; j++) {
        float ang = p * powf(10000.f, -(float)(2 * (d4 + j)) / 256.f);
        float sn, cs2; sincosf(ang, &sn, &cs2);
        float a = r1[j], bb = r2[j];
        r1[j] = a * cs2 - bb * sn;
        r2[j] = bb * cs2 + a * sn;
    }
    *(__half2*)(dst + d4)       = __floats2half2_rn(r1[0], r1[1]);
    *(__half2*)(dst + d4 + 2)   = __floats2half2_rn(r1[2], r1[3]);
    *(__half2*)(dst + d4 + 128) = __floats2half2_rn(r2[0], r2[1]);
    *(__half2*)(dst + d4 + 130) = __floats2half2_rn(r2[2], r2[3]);
}

__global__ void bhsd_to_bshd8h(const uint4* __restrict__ a, uint4* __restrict__ o)
{
    int idx = blockIdx.x * blockDim.x + threadIdx.x;
    int total = B_ * S_ * H_ * 32;
    if (idx >= total) return;
    int d = idx & 31;
    int h = (idx >> 5) % H_;
    int s = (idx / (32 * H_)) % S_;
    int b = idx / (32 * H_ * S_);
    o[idx] = a[(((b * H_ + h) * S_ + s) * 32) + d];
}

// in-place fp16 softmax over 832-wide rows (mask/scale already applied)
__global__ __launch_bounds__(128)
void softmax8h(__half* __restrict__ probs)
{
    long long rowid = blockIdx.x;
    __half* row = probs + rowid * S_;
    int t = threadIdx.x;
    const bool act = t < 104;   // 104 * 8 = 832
    float v[8];
    if (act) {
        uint4 raw = *(const uint4*)(row + t * 8);
        const __half2* hp = (const __half2*)&raw;
#pragma unroll
        for (int j = 0; j < 4; j++) {
            v[2 * j]     = __low2float(hp[j]);
            v[2 * j + 1] = __high2float(hp[j]);
        }
    } else {
#pragma unroll
        for (int j = 0; j < 8; j++) v[j] = -1e30f;
    }
    float mx = v[0];
#pragma unroll
    for (int j = 1; j < 8; j++) mx = fmaxf(mx, v[j]);
    __shared__ float red[128];
    red[t] = mx; __syncthreads();
    for (int s = 64; s > 0; s >>= 1) { if (t < s) red[t] = fmaxf(red[t], red[t + s]); __syncthreads(); }
    mx = red[0]; __syncthreads();
    float sum = 0.f;
    if (act) {
#pragma unroll
        for (int j = 0; j < 8; j++) { v[j] = __expf(v[j] - mx); sum += v[j]; }
    }
    red[t] = sum; __syncthreads();
    for (int s = 64; s > 0; s >>= 1) { if (t < s) red[t] += red[t + s]; __syncthreads(); }
    float inv = 1.f / red[0];
    if (act) {
        uint4 out;
        __half2* op = (__half2*)&out;
#pragma unroll
        for (int j = 0; j < 4; j++)
            op[j] = __floats2half2_rn(v[2 * j] * inv, v[2 * j + 1] * inv);
        *(uint4*)(row + t * 8) = out;
    }
}

// ---------------- host launch ----------------
#define GETSYMF(var, sym) do { void* p__; cudaGetSymbolAddress(&p__, sym); var = (float*)p__; } while (0)
#define GETSYMH(var, sym) do { void* p__; cudaGetSymbolAddress(&p__, sym); var = (__half*)p__; } while (0)

extern "C" void kernel_launch(void* const* d_in, const int* in_sizes, int n_in,
                              void* d_out, int out_size)
{
    const float *embeds_vlm, *embeds_exp, *cond, *attn_mask;
    const int* pos;
    const float *vlm_ln1_w, *vlm_ln2_w, *vlm_q_w, *vlm_k_w, *vlm_v_w, *vlm_o_w;
    const float *vlm_gate_w, *vlm_up_w, *vlm_down_w;
    const float *exp_ln1_dw, *exp_ln1_db, *exp_ln2_dw, *exp_ln2_db;
    const float *exp_q_w, *exp_k_w, *exp_v_w, *exp_o_w, *exp_gate_w, *exp_up_w, *exp_down_w;

    if (in_sizes[3] == B_ * S_) {
        embeds_vlm = (const float*)d_in[0];  embeds_exp = (const float*)d_in[1];
        cond       = (const float*)d_in[2];  pos        = (const int*)  d_in[3];
        attn_mask  = (const float*)d_in[4];
        vlm_ln1_w  = (const float*)d_in[5];  vlm_ln2_w  = (const float*)d_in[6];
        vlm_q_w    = (const float*)d_in[7];  vlm_k_w    = (const float*)d_in[8];
        vlm_v_w    = (const float*)d_in[9];  vlm_o_w    = (const float*)d_in[10];
        vlm_gate_w = (const float*)d_in[11]; vlm_up_w   = (const float*)d_in[12];
        vlm_down_w = (const float*)d_in[13];
        exp_ln1_dw = (const float*)d_in[14]; exp_ln1_db = (const float*)d_in[15];
        exp_ln2_dw = (const float*)d_in[16]; exp_ln2_db = (const float*)d_in[17];
        exp_q_w    = (const float*)d_in[18]; exp_k_w    = (const float*)d_in[19];
        exp_v_w    = (const float*)d_in[20]; exp_o_w    = (const float*)d_in[21];
        exp_gate_w = (const float*)d_in[22]; exp_up_w   = (const float*)d_in[23];
        exp_down_w = (const float*)d_in[24];
    } else {
        embeds_vlm = (const float*)d_in[0];  embeds_exp = (const float*)d_in[1];
        cond       = (const float*)d_in[2];
        vlm_ln1_w  = (const float*)d_in[3];  vlm_ln2_w  = (const float*)d_in[4];
        vlm_q_w    = (const float*)d_in[5];  vlm_k_w    = (const float*)d_in[6];
        vlm_v_w    = (const float*)d_in[7];  vlm_o_w    = (const float*)d_in[8];
        vlm_gate_w = (const float*)d_in[9];  vlm_up_w   = (const float*)d_in[10];
        vlm_down_w = (const float*)d_in[11];
        exp_ln1_dw = (const float*)d_in[12]; exp_ln1_db = (const float*)d_in[13];
        exp_ln2_dw = (const float*)d_in[14]; exp_ln2_db = (const float*)d_in[15];
        exp_q_w    = (const float*)d_in[16]; exp_k_w    = (const float*)d_in[17];
        exp_v_w    = (const float*)d_in[18]; exp_o_w    = (const float*)d_in[19];
        exp_gate_w = (const float*)d_in[20]; exp_up_w   = (const float*)d_in[21];
        exp_down_w = (const float*)d_in[22];
        pos        = (const int*)  d_in[23];
        attn_mask  = (const float*)d_in[24];
    }

    __half *hv, *he, *q, *qt, *k, *v, *probs, *attnt, *attn, *mg, *eg, *wb;
    float *mod1, *mod2, *hv1, *he1;
    GETSYMH(hv, g_hv);   GETSYMH(he, g_he);   GETSYMF(mod1, g_mod1); GETSYMF(mod2, g_mod2);
    GETSYMH(q, g_q);     GETSYMH(qt, g_qt);   GETSYMH(k, g_k);       GETSYMH(v, g_v);
    GETSYMH(probs, g_probs);
    GETSYMH(attnt, g_attnt);   GETSYMH(attn, g_attn);
    GETSYMF(hv1, g_hv1); GETSYMF(he1, g_he1);
    GETSYMH(mg, g_mg);   GETSYMH(eg, g_eg);   GETSYMH(wb, g_wbuf);

    const long long n_vq = (long long)W_V_ * H_ * DH_;
    const float* srcs[NW] = {vlm_k_w, vlm_v_w, vlm_o_w, vlm_down_w,
                             exp_q_w, exp_k_w, exp_v_w, exp_o_w, exp_down_w};
    long long cnts[NW] = {
        (long long)W_V_*DH_, (long long)W_V_*DH_, (long long)H_*DH_*W_V_, (long long)MLPV_*W_V_,
        (long long)W_E_*H_*DH_, (long long)W_E_*DH_, (long long)W_E_*DH_,
        (long long)H_*DH_*W_E_, (long long)MLPE_*W_E_};
    RoundDesc rd;
    long long ofs = n_vq; int blk = 0;
    const __half* wptr[NW];
    for (int i = 0; i < NW; i++) {
        rd.src[i] = (const float4*)srcs[i];
        rd.dofs[i] = ofs;
        rd.blkStart[i] = blk;
        wptr[i] = wb + ofs;
        ofs += cnts[i];
        blk += (int)(cnts[i] / 4096);
    }
    rd.blkStart[NW] = blk;
    const __half* w_vq = wb;
    const __half *w_vk = wptr[0], *w_vv = wptr[1], *w_vo = wptr[2], *w_vd = wptr[3];
    const __half *w_eq = wptr[4], *w_ek = wptr[5], *w_ev = wptr[6];
    const __half *w_eo = wptr[7], *w_ed = wptr[8];
    const __half* w_vug = wb + ofs;
    ofs += (long long)W_V_ * 2 * MLPV_;
    const __half* w_eug = wb + ofs;
    ofs += (long long)W_E_ * 2 * MLPE_;

    const int SMG  = 4 * STGB;
    const int SMT  = 4 * STG1;
    const int SM64 = 4 * STG64;
    cudaFuncSetAttribute(gemm16<0>, cudaFuncAttributeMaxDynamicSharedMemorySize, SMG);
    cudaFuncSetAttribute(gemm16<4>, cudaFuncAttributeMaxDynamicSharedMemorySize, SMG);
    cudaFuncSetAttribute(gemm16<6>, cudaFuncAttributeMaxDynamicSharedMemorySize, SMG);
    cudaFuncSetAttribute(gemm16_tb1, cudaFuncAttributeMaxDynamicSharedMemorySize, SMT);
    cudaFuncSetAttribute(gemm16m64<0>, cudaFuncAttributeMaxDynamicSharedMemorySize, SM64);
    cudaFuncSetAttribute(gemm16m64<3>, cudaFuncAttributeMaxDynamicSharedMemorySize, SM64);

    float* out_v = (float*)d_out;
    float* out_e = (float*)d_out + (long long)B_ * S_V_ * W_V_;

    long long sHv = (long long)S_V_ * W_V_, sHe = (long long)S_E_ * W_E_;
    long long sQ = (long long)S_ * H_ * DH_, sK = (long long)S_ * DH_;
    long long sL = (long long)S_ * S_;

    // L0..L2
    round4<<<(int)((n_vq / 4 + 255) / 256), 256>>>((const float4*)vlm_q_w, (__half2*)wb, (int)(n_vq / 4));
    rms_scale<<<B_ * S_V_, 256>>>(embeds_vlm, vlm_ln1_w, hv, W_V_);
    modmm2<<<dim3(48, B_), 256>>>(cond, exp_ln1_dw, exp_ln1_db, mod1);
    // L3: VLM Q projection (ncu target)
    gemm16m64<0><<<dim3(16, 12, B_), 128, SM64>>>(hv, w_vq, q, nullptr, S_V_, H_ * DH_, W_V_, sHv, 0, sQ, 1);
    // staging remainder
    round_many<<<blk, 256>>>(rd, wb);
    {
        long long n4v = (long long)W_V_ * MLPV_ / 4;
        interleave2<<<(int)((n4v + 1023) / 1024), 256>>>((const float4*)vlm_up_w, (const float4*)vlm_gate_w, (uint4*)w_vug, n4v);
        long long n4e = (long long)W_E_ * MLPE_ / 4;
        interleave2<<<(int)((n4e + 1023) / 1024), 256>>>((const float4*)exp_up_w, (const float4*)exp_gate_w, (uint4*)w_eug, n4e);
    }
    rms_mod<<<B_ * S_E_, 256>>>(embeds_exp, mod1, he, W_E_, S_E_);
    modmm2<<<dim3(48, B_), 256>>>(cond, exp_ln2_dw, exp_ln2_db, mod2);

    // QKV remainder
    gemm16m64<0><<<dim3(16, 1, B_), 128, SM64>>>(he, w_eq, q + (long long)S_V_ * H_ * DH_, nullptr, S_E_, H_ * DH_, W_E_, sHe, 0, sQ, 1);
    gemm16<0><<<dim3(2, 6, B_), 256, SMG>>>(hv, w_vk, k, nullptr, nullptr, S_V_, DH_, W_V_, sHv, 0, sK, 1);
    gemm16<0><<<dim3(2, 1, B_), 256, SMG>>>(he, w_ek, k + S_V_ * DH_, nullptr, nullptr, S_E_, DH_, W_E_, sHe, 0, sK, 1);
    gemm16<0><<<dim3(2, 6, B_), 256, SMG>>>(hv, w_vv, v, nullptr, nullptr, S_V_, DH_, W_V_, sHv, 0, sK, 1);
    gemm16<0><<<dim3(2, 1, B_), 256, SMG>>>(he, w_ev, v + S_V_ * DH_, nullptr, nullptr, S_E_, DH_, W_E_, sHe, 0, sK, 1);

    // RoPE (q fused with transpose -> qt; k in place)
    rope4h_t<<<(B_ * S_ * H_ * 32 + 255) / 256, 256>>>(q, qt, pos);
    rope4h<<<(B_ * S_ * 1 * 32 + 255) / 256, 256>>>(k, pos, 1);

    // attention
    {
        gemm16_tb1<<<dim3(7, 7, B_ * H_), 256, SMT>>>(qt, k, probs, attn_mask, S_, S_, DH_, sK, sK, sL, H_);
        softmax8h<<<B_ * H_ * S_, 128>>>(probs);
        gemm16m64<0><<<dim3(2, 13, B_ * H_), 128, SM64>>>(probs, v, attnt, nullptr, S_, DH_, S_, sL, sK, sK, H_);
        int nq8 = B_ * H_ * S_ * 32;
        bhsd_to_bshd8h<<<(nq8 + 255) / 256, 256>>>((const uint4*)attnt, (uint4*)attn);
    }

    // output projections + residuals
    {
        long long sA = (long long)S_ * H_ * DH_;
        gemm16m64<3><<<dim3(16, 12, B_), 128, SM64>>>(attn, w_vo, hv1, embeds_vlm, S_V_, W_V_, H_ * DH_, sA, 0, sHv, 1);
        gemm16<4><<<dim3(8, 1, B_), 256, SMG>>>(attn + (long long)S_V_ * H_ * DH_, w_eo, he1, embeds_exp, mod1, S_E_, W_E_, H_ * DH_, sA, 0, sHe, 1);
    }

    // pre-MLP norms
    rms_scale<<<B_ * S_V_, 256>>>(hv1, vlm_ln2_w, hv, W_V_);
    rms_mod<<<B_ * S_E_, 256>>>(he1, mod2, he, W_E_, S_E_);

    // VLM MLP
    {
        int M = B_ * S_V_;
        gemm16<6><<<dim3(256, 24, 1), 256, SMG>>>(hv, w_vug, mg, nullptr, nullptr, M, 2 * MLPV_, W_V_, 0, 0, 0, 1);
        gemm16m64<3><<<dim3(16, 48, 1), 128, SM64>>>(mg, w_vd, out_v, hv1, M, W_V_, MLPV_, 0, 0, 0, 1);
    }

    // expert MLP
    {
        int M = B_ * S_E_;
        gemm16<6><<<dim3(64, 2, 1), 256, SMG>>>(he, w_eug, eg, nullptr, nullptr, M, 2 * MLPE_, W_E_, 0, 0, 0, 1);
        gemm16<4><<<dim3(8, 2, 1), 256, SMG>>>(eg, w_ed, out_e, he1, mod2, M, W_E_, MLPE_, 0, 0, 0, 1);
    }
}

// round 15
// speedup vs baseline: 1.2184x; 1.0266x over previous
#include <cuda_runtime.h>
#include <cuda_fp16.h>
#include <cuda_bf16.h>
#include <math.h>

#define B_    4
#define S_V_  768
#define S_E_  64
#define S_    832
#define W_V_  2048
#define W_E_  1024
#define H_    8
#define DH_   256
#define MLPV_ 16384
#define MLPE_ 4096
#define EPS_  1e-6f
#define SCALE_ 0.0625f

// ---------------- scratch ----------------
__device__ __half g_hv   [B_*S_V_*W_V_];
__device__ __half g_he   [B_*S_E_*W_E_];
__device__ float  g_mod1 [B_*3*W_E_];
__device__ float  g_mod2 [B_*3*W_E_];
__device__ __half g_q    [(long long)B_*S_*H_*DH_];
__device__ __half g_qt   [(long long)B_*H_*S_*DH_];
__device__ __half g_kv   [(long long)B_*S_*512];
__device__ __half g_probs[(long long)B_*H_*S_*S_];
__device__ __half g_attnt[(long long)B_*H_*S_*DH_];
__device__ __half g_attne[B_*S_E_*H_*DH_];
__device__ float  g_hv1  [B_*S_V_*W_V_];
__device__ float  g_he1  [B_*S_E_*W_E_];
__device__ __half g_mg   [(long long)B_*S_V_*MLPV_];
__device__ __half g_eg   [B_*S_E_*MLPE_];
__device__ __half g_wbuf [127401984];

__device__ __forceinline__ float gelu_t(float x) {
    return 0.5f * x * (1.f + tanhf(0.7978845608028654f * (x + 0.044715f * x * x * x)));
}

__device__ __forceinline__ void mma_f16(float* c, const unsigned* a, const unsigned* b) {
    asm volatile(
        "mma.sync.aligned.m16n8k16.row.col.f32.f16.f16.f32 "
        "{%0,%1,%2,%3}, {%4,%5,%6,%7}, {%8,%9}, {%0,%1,%2,%3};\n"
        : "+f"(c[0]), "+f"(c[1]), "+f"(c[2]), "+f"(c[3])
        : "r"(a[0]), "r"(a[1]), "r"(a[2]), "r"(a[3]), "r"(b[0]), "r"(b[1]));
}

// ============ gemm16: fp16 operands, fp32 accum, TB=0 ============
// Block 128x128, 256 thr, 8 warps (2m x 4n) of 64x32, K-tile 32, 4 stages.
// EPI: 0 plain->fp16, 3 fp32(c+aux), 4 fp32 gated residual,
//      6 fused glu: pairs (even=up,odd=gate) -> fp16 gelu(x1)*x0 at N/2 stride
#define ASTB 10240
#define STGB 18944
template<int EPI>
__global__ __launch_bounds__(256, 2)
void gemm16(const __half* __restrict__ A, const __half* __restrict__ Bm,
            void* __restrict__ Cv, const float* __restrict__ aux,
            const float* __restrict__ modv,
            int M, int N, int K,
            long long sA, long long sB, long long sC, int bInner)
{
    extern __shared__ __align__(16) char sm[];

    const int z = blockIdx.z;
    A  += (long long)z * sA;
    Bm += (long long)(z / bInner) * sB;

    const int tid  = threadIdx.x;
    const int lane = tid & 31;
    const int wid  = tid >> 5;
    const int wm   = (wid & 1) * 64;
    const int wn   = (wid >> 1) * 32;
    const int bm   = blockIdx.y * 128;
    const int bn   = blockIdx.x * 128;
    const int row  = lane >> 2, col = lane & 3;

    unsigned sbase = (unsigned)__cvta_generic_to_shared(sm);

    auto issue = [&](int st) {
        const int ktE = st * 32;
        const unsigned sb = sbase + (unsigned)((st & 3) * STGB);
#pragma unroll
        for (int j = 0; j < 2; j++) {
            int id = tid + j * 256;
            int r = id >> 2, c = id & 3;
            int gm = bm + r;
            const __half* gp = A + (long long)(gm < M ? gm : M - 1) * K + ktE + c * 8;
            unsigned dst = sb + (unsigned)(r * 80 + c * 16);
            int zf = (gm < M) ? 16 : 0;
            asm volatile("cp.async.cg.shared.global [%0], [%1], 16, %2;\n"
                         :: "r"(dst), "l"(gp), "r"(zf));
        }
#pragma unroll
        for (int j = 0; j < 2; j++) {
            int id = tid + j * 256;
            int kr = id >> 4, c = id & 15;
            int gn = bn + c * 8;
            const __half* gp = Bm + (long long)(ktE + kr) * N + (gn < N ? gn : N - 8);
            unsigned dst = sb + (unsigned)(ASTB + kr * 272 + c * 16);
            int zf = (gn < N) ? 16 : 0;
            asm volatile("cp.async.cg.shared.global [%0], [%1], 16, %2;\n"
                         :: "r"(dst), "l"(gp), "r"(zf));
        }
    };

    float c[4][4][4];
#pragma unroll
    for (int i = 0; i < 4; i++)
#pragma unroll
        for (int j = 0; j < 4; j++)
#pragma unroll
            for (int l = 0; l < 4; l++) c[i][j][l] = 0.f;

    const unsigned aoff = (unsigned)((((lane >> 3) & 1) * 8 + (lane & 7)) * 80 + (lane >> 4) * 16);
    const unsigned boff4 = (unsigned)(ASTB + (((lane >> 3) & 1) * 8 + (lane & 7)) * 272
                                      + (lane >> 4) * 16 + wn * 2);

    const int nk = K / 32;
#pragma unroll 1
    for (int s = 0; s < 3; s++) { issue(s); asm volatile("cp.async.commit_group;\n"); }

#pragma unroll 1
    for (int kt = 0; kt < nk; kt++) {
        asm volatile("cp.async.wait_group 2;\n");
        __syncthreads();
        if (kt + 3 < nk) issue(kt + 3);
        asm volatile("cp.async.commit_group;\n");

        const unsigned stg = sbase + (unsigned)((kt & 3) * STGB);
#pragma unroll
        for (int sub = 0; sub < 2; sub++) {
            unsigned af[4][4], bf[4][2];
#pragma unroll
            for (int mt = 0; mt < 4; mt++) {
                unsigned ad = stg + (unsigned)((wm + mt * 16) * 80 + sub * 32) + aoff;
                asm volatile("ldmatrix.sync.aligned.m8n8.x4.shared.b16 {%0,%1,%2,%3}, [%4];"
                             : "=r"(af[mt][0]), "=r"(af[mt][1]), "=r"(af[mt][2]), "=r"(af[mt][3])
                             : "r"(ad));
            }
#pragma unroll
            for (int ntp = 0; ntp < 2; ntp++) {
                unsigned bd = stg + (unsigned)(sub * 16 * 272 + ntp * 32) + boff4;
                asm volatile("ldmatrix.sync.aligned.m8n8.x4.trans.shared.b16 {%0,%1,%2,%3}, [%4];"
                             : "=r"(bf[2*ntp][0]), "=r"(bf[2*ntp][1]),
                               "=r"(bf[2*ntp+1][0]), "=r"(bf[2*ntp+1][1])
                             : "r"(bd));
            }
#pragma unroll
            for (int mt = 0; mt < 4; mt++)
#pragma unroll
                for (int nt = 0; nt < 4; nt++)
                    mma_f16(c[mt][nt], af[mt], bf[nt]);
        }
    }

    if (EPI == 3 || EPI == 4) aux += (long long)z * sC;
    __half* Ch = (__half*)Cv + (long long)z * sC;
    float*  Cf = (float*)Cv + (long long)z * sC;

    auto epi_store = [&](int gm, int gn, float x0, float x1) {
        if (EPI == 6) {
            Ch[(long long)gm * (N >> 1) + (gn >> 1)] = __float2half_rn(gelu_t(x1) * x0);
            return;
        }
        long long o = (long long)gm * N + gn;
        if (EPI == 0) {
            *(__half2*)(Ch + o) = __halves2half2(__float2half_rn(x0), __float2half_rn(x1));
        } else if (EPI == 3) {
            float2 u = *(const float2*)(aux + o);
            *(float2*)(Cf + o) = make_float2(x0 + u.x, x1 + u.y);
        } else if (EPI == 4) {
            int bb = z + gm / S_E_;
            float g0 = modv[(long long)bb * 3 * W_E_ + 2 * W_E_ + gn];
            float g1 = modv[(long long)bb * 3 * W_E_ + 2 * W_E_ + gn + 1];
            float2 u = *(const float2*)(aux + o);
            *(float2*)(Cf + o) = make_float2(u.x + x0 * g0, u.y + x1 * g1);
        }
    };

#pragma unroll
    for (int mt = 0; mt < 4; mt++) {
#pragma unroll
        for (int nt = 0; nt < 4; nt++) {
            int gm = bm + wm + mt * 16 + row;
            int gn = bn + wn + nt * 8 + col * 2;
            if (gn < N) {
                if (gm < M)     epi_store(gm,     gn, c[mt][nt][0], c[mt][nt][1]);
                if (gm + 8 < M) epi_store(gm + 8, gn, c[mt][nt][2], c[mt][nt][3]);
            }
        }
    }
}

// ============ gemm16m64: 64x128 tile, 128 thr (4 warps 1m x 4n), 4 stages ====
// EPI: 0 fp16, 3 fp32 c+aux. GA: A gathered from attnt (B,H,S,256), row gm=s, K=2048.
// ldb: B row stride (normally N).
#define A64B 5120
#define STG64 (A64B + 8704)
template<int EPI, int GA>
__global__ __launch_bounds__(128, 4)
void gemm16m64(const __half* __restrict__ A, const __half* __restrict__ Bm,
               void* __restrict__ Cv, const float* __restrict__ aux,
               int M, int N, int K, long long sA, long long sB, long long sC,
               int bInner, int ldb)
{
    extern __shared__ __align__(16) char sm[];

    const int z = blockIdx.z;
    if (!GA) A += (long long)z * sA;
    Bm += (long long)(z / bInner) * sB;

    const int tid  = threadIdx.x;
    const int lane = tid & 31;
    const int wid  = tid >> 5;
    const int wn   = wid * 32;
    const int bm   = blockIdx.y * 64;
    const int bn   = blockIdx.x * 128;
    const int row  = lane >> 2, col = lane & 3;

    unsigned sbase = (unsigned)__cvta_generic_to_shared(sm);

    auto issue = [&](int st) {
        const int ktE = st * 32;
        const unsigned sb = sbase + (unsigned)((st & 3) * STG64);
#pragma unroll
        for (int j = 0; j < 2; j++) {
            int id = tid + j * 128;
            int r = id >> 2, c = id & 3;
            int gm = bm + r;
            const __half* gp;
            if (GA) {
                int kc = ktE + c * 8;
                int gmc = gm < M ? gm : M - 1;
                gp = A + ((long long)(z * H_ + (kc >> 8)) * S_ + gmc) * 256 + (kc & 255);
            } else {
                gp = A + (long long)(gm < M ? gm : M - 1) * K + ktE + c * 8;
            }
            unsigned dst = sb + (unsigned)(r * 80 + c * 16);
            int zf = (gm < M) ? 16 : 0;
            asm volatile("cp.async.cg.shared.global [%0], [%1], 16, %2;\n"
                         :: "r"(dst), "l"(gp), "r"(zf));
        }
#pragma unroll
        for (int j = 0; j < 4; j++) {
            int id = tid + j * 128;
            int kr = id >> 4, c = id & 15;
            int gn = bn + c * 8;
            const __half* gp = Bm + (long long)(ktE + kr) * ldb + (gn < N ? gn : N - 8);
            unsigned dst = sb + (unsigned)(A64B + kr * 272 + c * 16);
            int zf = (gn < N) ? 16 : 0;
            asm volatile("cp.async.cg.shared.global [%0], [%1], 16, %2;\n"
                         :: "r"(dst), "l"(gp), "r"(zf));
        }
    };

    float c[4][4][4];
#pragma unroll
    for (int i = 0; i < 4; i++)
#pragma unroll
        for (int j = 0; j < 4; j++)
#pragma unroll
            for (int l = 0; l < 4; l++) c[i][j][l] = 0.f;

    const unsigned aoff = (unsigned)((((lane >> 3) & 1) * 8 + (lane & 7)) * 80 + (lane >> 4) * 16);
    const unsigned boff4 = (unsigned)(A64B + (((lane >> 3) & 1) * 8 + (lane & 7)) * 272
                                      + (lane >> 4) * 16 + wn * 2);

    const int nk = K / 32;
#pragma unroll 1
    for (int s = 0; s < 3; s++) { issue(s); asm volatile("cp.async.commit_group;\n"); }

#pragma unroll 1
    for (int kt = 0; kt < nk; kt++) {
        asm volatile("cp.async.wait_group 2;\n");
        __syncthreads();
        if (kt + 3 < nk) issue(kt + 3);
        asm volatile("cp.async.commit_group;\n");

        const unsigned stg = sbase + (unsigned)((kt & 3) * STG64);
#pragma unroll
        for (int sub = 0; sub < 2; sub++) {
            unsigned af[4][4], bf[4][2];
#pragma unroll
            for (int mt = 0; mt < 4; mt++) {
                unsigned ad = stg + (unsigned)((mt * 16) * 80 + sub * 32) + aoff;
                asm volatile("ldmatrix.sync.aligned.m8n8.x4.shared.b16 {%0,%1,%2,%3}, [%4];"
                             : "=r"(af[mt][0]), "=r"(af[mt][1]), "=r"(af[mt][2]), "=r"(af[mt][3])
                             : "r"(ad));
            }
#pragma unroll
            for (int ntp = 0; ntp < 2; ntp++) {
                unsigned bd = stg + (unsigned)(sub * 16 * 272 + ntp * 32) + boff4;
                asm volatile("ldmatrix.sync.aligned.m8n8.x4.trans.shared.b16 {%0,%1,%2,%3}, [%4];"
                             : "=r"(bf[2*ntp][0]), "=r"(bf[2*ntp][1]),
                               "=r"(bf[2*ntp+1][0]), "=r"(bf[2*ntp+1][1])
                             : "r"(bd));
            }
#pragma unroll
            for (int mt = 0; mt < 4; mt++)
#pragma unroll
                for (int nt = 0; nt < 4; nt++)
                    mma_f16(c[mt][nt], af[mt], bf[nt]);
        }
    }

    if (EPI == 3) aux += (long long)z * sC;
    __half* Ch = (__half*)Cv + (long long)z * sC;
    float*  Cf = (float*)Cv + (long long)z * sC;

#pragma unroll
    for (int mt = 0; mt < 4; mt++) {
#pragma unroll
        for (int nt = 0; nt < 4; nt++) {
            int gm = bm + mt * 16 + row;
            int gn = bn + wn + nt * 8 + col * 2;
            if (gn >= N) continue;
#pragma unroll
            for (int hh = 0; hh < 2; hh++) {
                int g = gm + hh * 8;
                if (g >= M) continue;
                long long o = (long long)g * N + gn;
                float x0 = c[mt][nt][hh * 2], x1 = c[mt][nt][hh * 2 + 1];
                if (EPI == 0) {
                    *(__half2*)(Ch + o) = __halves2half2(__float2half_rn(x0), __float2half_rn(x1));
                } else {
                    float2 u = *(const float2*)(aux + o);
                    *(float2*)(Cf + o) = make_float2(x0 + u.x, x1 + u.y);
                }
            }
        }
    }
}

// ============ gemm16_tb1: QK^T, fused scale+mask -> fp16 probs, ldb B stride ============
#define STG1 20480
__global__ __launch_bounds__(256, 2)
void gemm16_tb1(const __half* __restrict__ A, const __half* __restrict__ Bm,
                __half* __restrict__ C, const float* __restrict__ mask,
                int M, int N, int K,
                long long sA, long long sB, long long sC, int bInner, int ldb)
{
    extern __shared__ __align__(16) char sm[];

    const int z = blockIdx.z;
    A  += (long long)z * sA;
    Bm += (long long)(z / bInner) * sB;
    C  += (long long)z * sC;
    const float* mrow = mask + (long long)(z >> 3) * S_ * S_;

    const int tid  = threadIdx.x;
    const int lane = tid & 31;
    const int wid  = tid >> 5;
    const int wm   = (wid & 1) * 64;
    const int wn   = (wid >> 1) * 32;
    const int bm   = blockIdx.y * 128;
    const int bn   = blockIdx.x * 128;
    const int row  = lane >> 2, col = lane & 3;

    unsigned sbase = (unsigned)__cvta_generic_to_shared(sm);

    auto issue = [&](int st) {
        const int ktE = st * 32;
        const unsigned sb = sbase + (unsigned)((st & 3) * STG1);
#pragma unroll
        for (int j = 0; j < 2; j++) {
            int id = tid + j * 256;
            int r = id >> 2, c = id & 3;
            int gm = bm + r;
            const __half* gp = A + (long long)(gm < M ? gm : M - 1) * K + ktE + c * 8;
            unsigned dst = sb + (unsigned)(r * 80 + c * 16);
            int zf = (gm < M) ? 16 : 0;
            asm volatile("cp.async.cg.shared.global [%0], [%1], 16, %2;\n"
                         :: "r"(dst), "l"(gp), "r"(zf));
        }
#pragma unroll
        for (int j = 0; j < 2; j++) {
            int id = tid + j * 256;
            int r = id >> 2, c = id & 3;
            int gn = bn + r;
            const __half* gp = Bm + (long long)(gn < N ? gn : N - 1) * ldb + ktE + c * 8;
            unsigned dst = sb + (unsigned)(ASTB + r * 80 + c * 16);
            int zf = (gn < N) ? 16 : 0;
            asm volatile("cp.async.cg.shared.global [%0], [%1], 16, %2;\n"
                         :: "r"(dst), "l"(gp), "r"(zf));
        }
    };

    float c[4][4][4];
#pragma unroll
    for (int i = 0; i < 4; i++)
#pragma unroll
        for (int j = 0; j < 4; j++)
#pragma unroll
            for (int l = 0; l < 4; l++) c[i][j][l] = 0.f;

    const unsigned aoff = (unsigned)((((lane >> 3) & 1) * 8 + (lane & 7)) * 80 + (lane >> 4) * 16);
    const unsigned boff4 = (unsigned)(ASTB + ((lane & 7) + (lane >> 4) * 8 + wn) * 80
                                      + (((lane >> 3) & 1) * 16));

    const int nk = K / 32;
#pragma unroll 1
    for (int s = 0; s < 3; s++) { issue(s); asm volatile("cp.async.commit_group;\n"); }

#pragma unroll 1
    for (int kt = 0; kt < nk; kt++) {
        asm volatile("cp.async.wait_group 2;\n");
        __syncthreads();
        if (kt + 3 < nk) issue(kt + 3);
        asm volatile("cp.async.commit_group;\n");

        const unsigned stg = sbase + (unsigned)((kt & 3) * STG1);
#pragma unroll
        for (int sub = 0; sub < 2; sub++) {
            unsigned af[4][4], bf[4][2];
#pragma unroll
            for (int mt = 0; mt < 4; mt++) {
                unsigned ad = stg + (unsigned)((wm + mt * 16) * 80 + sub * 32) + aoff;
                asm volatile("ldmatrix.sync.aligned.m8n8.x4.shared.b16 {%0,%1,%2,%3}, [%4];"
                             : "=r"(af[mt][0]), "=r"(af[mt][1]), "=r"(af[mt][2]), "=r"(af[mt][3])
                             : "r"(ad));
            }
#pragma unroll
            for (int ntp = 0; ntp < 2; ntp++) {
                unsigned bd = stg + (unsigned)(ntp * 16 * 80 + sub * 32) + boff4;
                asm volatile("ldmatrix.sync.aligned.m8n8.x4.shared.b16 {%0,%1,%2,%3}, [%4];"
                             : "=r"(bf[2*ntp][0]), "=r"(bf[2*ntp][1]),
                               "=r"(bf[2*ntp+1][0]), "=r"(bf[2*ntp+1][1])
                             : "r"(bd));
            }
#pragma unroll
            for (int mt = 0; mt < 4; mt++)
#pragma unroll
                for (int nt = 0; nt < 4; nt++)
                    mma_f16(c[mt][nt], af[mt], bf[nt]);
        }
    }

#pragma unroll
    for (int mt = 0; mt < 4; mt++) {
#pragma unroll
        for (int nt = 0; nt < 4; nt++) {
            int gm = bm + wm + mt * 16 + row;
            int gn = bn + wn + nt * 8 + col * 2;
            if (gn >= N) continue;
#pragma unroll
            for (int hh = 0; hh < 2; hh++) {
                int g = gm + hh * 8;
                if (g >= M) continue;
                float2 mv = *(const float2*)(mrow + (long long)g * S_ + gn);
                float x0 = c[mt][nt][hh * 2] * SCALE_ + mv.x;
                float x1 = c[mt][nt][hh * 2 + 1] * SCALE_ + mv.y;
                *(__half2*)(C + (long long)g * N + gn) = __floats2half2_rn(x0, x1);
            }
        }
    }
}

// ---------------- weight staging ----------------
__global__ void round4(const float4* __restrict__ s, __half2* __restrict__ d, int n4)
{
    int i = blockIdx.x * 256 + threadIdx.x;
    if (i >= n4) return;
    float4 v = s[i];
    d[i * 2]     = __floats2half2_rn(v.x, v.y);
    d[i * 2 + 1] = __floats2half2_rn(v.z, v.w);
}

#define NW 5
struct RoundDesc {
    const float4* src[NW];
    long long dofs[NW];
    int blkStart[NW + 1];
};

__global__ void round_many(RoundDesc d, __half* __restrict__ wbuf)
{
    int b = blockIdx.x;
    int w = 0;
#pragma unroll
    for (int i = 0; i < NW; i++) if (b >= d.blkStart[i + 1]) w = i + 1;
    int lb = b - d.blkStart[w];
    const float4* s = d.src[w] + (long long)lb * 1024;
    __half2* o = (__half2*)(wbuf + d.dofs[w]) + (long long)lb * 2048;
    int t = threadIdx.x;
#pragma unroll
    for (int i = 0; i < 4; i++) {
        float4 v = s[t + i * 256];
        o[(t + i * 256) * 2]     = __floats2half2_rn(v.x, v.y);
        o[(t + i * 256) * 2 + 1] = __floats2half2_rn(v.z, v.w);
    }
}

__global__ void interleave2(const float4* __restrict__ up, const float4* __restrict__ gate,
                            uint4* __restrict__ out, long long n4)
{
    long long i0 = (long long)blockIdx.x * 1024 + threadIdx.x;
#pragma unroll
    for (int j = 0; j < 4; j++) {
        long long i = i0 + j * 256;
        if (i >= n4) return;
        float4 u = up[i], g = gate[i];
        __half2 h0 = __floats2half2_rn(u.x, g.x);
        __half2 h1 = __floats2half2_rn(u.y, g.y);
        __half2 h2 = __floats2half2_rn(u.z, g.z);
        __half2 h3 = __floats2half2_rn(u.w, g.w);
        uint4 o;
        o.x = *(unsigned*)&h0; o.y = *(unsigned*)&h1;
        o.z = *(unsigned*)&h2; o.w = *(unsigned*)&h3;
        out[i] = o;
    }
}

// concat Wk|Wv columns: dst (R,512) halfs, from Wk,Wv (R,256) floats
__global__ void concat_kv(const float4* __restrict__ Wk, const float4* __restrict__ Wv,
                          __half2* __restrict__ dst, int R)
{
    int i = blockIdx.x * 256 + threadIdx.x;
    int total = R * 64;
    if (i >= total) return;
    int r = i >> 6, c4 = i & 63;
    float4 a = Wk[i], b = Wv[i];
    __half2* dk = dst + (r * 512 + c4 * 4) / 2;
    dk[0] = __floats2half2_rn(a.x, a.y);
    dk[1] = __floats2half2_rn(a.z, a.w);
    __half2* dv = dst + (r * 512 + 256 + c4 * 4) / 2;
    dv[0] = __floats2half2_rn(b.x, b.y);
    dv[1] = __floats2half2_rn(b.z, b.w);
}

// gather exp attn slice: out (B,64,2048) from attnt (B,H,S,256)
__global__ void exp_gather(const uint4* __restrict__ in, uint4* __restrict__ out)
{
    int idx = blockIdx.x * 256 + threadIdx.x;
    int total = B_ * 64 * 256;
    if (idx >= total) return;
    int d8 = idx & 31;
    int h = (idx >> 5) & 7;
    int j = (idx >> 8) & 63;
    int b = idx >> 14;
    out[((b * 64 + j) * 2048 + h * 256 + d8 * 8) >> 3] =
        in[(((long long)(b * H_ + h) * S_ + S_V_ + j) * 256 + d8 * 8) >> 3];
}

// ---------------- row kernels ----------------
__device__ __forceinline__ float blockReduceSum(float v) {
    __shared__ float red[256];
    int t = threadIdx.x;
    red[t] = v; __syncthreads();
    for (int s = 128; s > 0; s >>= 1) {
        if (t < s) red[t] += red[t + s];
        __syncthreads();
    }
    float r = red[0];
    __syncthreads();
    return r;
}

__global__ void rms_scale(const float* __restrict__ x, const float* __restrict__ w,
                          __half* __restrict__ out, int W)
{
    long long base = (long long)blockIdx.x * W;
    float ss = 0.f;
    for (int c = threadIdx.x; c < W; c += 256) { float t = x[base + c]; ss += t * t; }
    float tot = blockReduceSum(ss);
    float inv = rsqrtf(tot / (float)W + EPS_);
    for (int c = threadIdx.x; c < W; c += 256)
        out[base + c] = __float2half_rn(x[base + c] * inv * (1.f + w[c]));
}

__global__ void rms_mod(const float* __restrict__ x, const float* __restrict__ mod,
                        __half* __restrict__ out, int W, int rowsPerB)
{
    long long base = (long long)blockIdx.x * W;
    int b = blockIdx.x / rowsPerB;
    const float* m = mod + (long long)b * 3 * W;
    float ss = 0.f;
    for (int c = threadIdx.x; c < W; c += 256) { float t = x[base + c]; ss += t * t; }
    float tot = blockReduceSum(ss);
    float inv = rsqrtf(tot / (float)W + EPS_);
    for (int c = threadIdx.x; c < W; c += 256)
        out[base + c] = __float2half_rn(x[base + c] * inv * (1.f + m[c]) + m[W + c]);
}

// dual modulation GEMV: z=0 -> (W1,b1,o1); z=1 -> (W2,b2,o2)
__global__ void modmm2d(const float* __restrict__ cond,
                        const float* __restrict__ W1, const float* __restrict__ b1, float* __restrict__ o1,
                        const float* __restrict__ W2, const float* __restrict__ b2, float* __restrict__ o2)
{
    const int NT = 3 * W_E_;
    const float* W = blockIdx.z ? W2 : W1;
    const float* bias = blockIdx.z ? b2 : b1;
    float* out = blockIdx.z ? o2 : o1;
    __shared__ float cs[W_E_];
    __shared__ float part[4][64];
    int bb = blockIdx.y;
    int tid = threadIdx.x;
    for (int i = tid; i < W_E_; i += 256) cs[i] = cond[bb * W_E_ + i];
    __syncthreads();
    int tx = tid & 63, ty = tid >> 6;
    int c = blockIdx.x * 64 + tx;
    const float* Wp = W + (long long)(ty * 256) * NT + c;
    const float* cp = cs + ty * 256;
    float s = 0.f;
#pragma unroll 4
    for (int k = 0; k < 256; k++) s += cp[k] * Wp[(long long)k * NT];
    part[ty][tx] = s;
    __syncthreads();
    if (ty == 0)
        out[(long long)bb * NT + c] = part[0][tx] + part[1][tx] + part[2][tx] + part[3][tx] + bias[c];
}

// RoPE for k stored in kv (stride 512, first 256 halves)
__global__ void rope_k_kv(__half* __restrict__ kv, const int* __restrict__ pos)
{
    int idx = blockIdx.x * blockDim.x + threadIdx.x;
    int total = B_ * S_ * 32;
    if (idx >= total) return;
    int d4 = (idx & 31) << 2;
    int s = (idx >> 5) % S_;
    int b = idx / (32 * S_);
    float p = (float)pos[b * S_ + s];
    __half* base = kv + (long long)(b * S_ + s) * 512;
    __half2 x1a = *(__half2*)(base + d4),       x1b = *(__half2*)(base + d4 + 2);
    __half2 x2a = *(__half2*)(base + d4 + 128), x2b = *(__half2*)(base + d4 + 130);
    float r1[4] = {__low2float(x1a), __high2float(x1a), __low2float(x1b), __high2float(x1b)};
    float r2[4] = {__low2float(x2a), __high2float(x2a), __low2float(x2b), __high2float(x2b)};
#pragma unroll
    for (int j = 0; j < 4; j++) {
        float ang = p * powf(10000.f, -(float)(2 * (d4 + j)) / 256.f);
        float sn, cs2; sincosf(ang, &sn, &cs2);
        float a = r1[j], bb = r2[j];
        r1[j] = a * cs2 - bb * sn;
        r2[j] = bb * cs2 + a * sn;
    }
    *(__half2*)(base + d4)       = __floats2half2_rn(r1[0], r1[1]);
    *(__half2*)(base + d4 + 2)   = __floats2half2_rn(r1[2], r1[3]);
    *(__half2*)(base + d4 + 128) = __floats2half2_rn(r2[0], r2[1]);
    *(__half2*)(base + d4 + 130) = __floats2half2_rn(r2[2], r2[3]);
}

// RoPE for q fused with (b,s,h,d) -> (b,h,s,d) transpose
__global__ void rope4h_t(const __half* __restrict__ q, __half* __restrict__ qt,
                         const int* __restrict__ pos)
{
    int idx = blockIdx.x * blockDim.x + threadIdx.x;
    int total = B_ * S_ * H_ * 32;
    if (idx >= total) return;
    int d4 = (idx & 31) << 2;
    int h = (idx >> 5) % H_;
    int s = (idx / (32 * H_)) % S_;
    int b = idx / (32 * H_ * S_);
    float p = (float)pos[b * S_ + s];
    const __half* src = q + (((long long)(b * S_ + s) * H_ + h) << 8);
    __half* dst = qt + (((long long)(b * H_ + h) * S_ + s) << 8);
    __half2 x1a = *(const __half2*)(src + d4),       x1b = *(const __half2*)(src + d4 + 2);
    __half2 x2a = *(const __half2*)(src + d4 + 128), x2b = *(const __half2*)(src + d4 + 130);
    float r1[4] = {__low2float(x1a), __high2float(x1a), __low2float(x1b), __high2float(x1b)};
    float r2[4] = {__low2float(x2a), __high2float(x2a), __low2float(x2b), __high2float(x2b)};
#pragma unroll
    for (int j = 0; j < 4; j++) {
        float ang = p * powf(10000.f, -(float)(2 * (d4 + j)) / 256.f);
        float sn, cs2; sincosf(ang, &sn, &cs2);
        float a = r1[j], bb = r2[j];
        r1[j] = a * cs2 - bb * sn;
        r2[j] = bb * cs2 + a * sn;
    }
    *(__half2*)(dst + d4)       = __floats2half2_rn(r1[0], r1[1]);
    *(__half2*)(dst + d4 + 2)   = __floats2half2_rn(r1[2], r1[3]);
    *(__half2*)(dst + d4 + 128) = __floats2half2_rn(r2[0], r2[1]);
    *(__half2*)(dst + d4 + 130) = __floats2half2_rn(r2[2], r2[3]);
}

// in-place fp16 softmax over 832-wide rows
__global__ __launch_bounds__(128)
void softmax8h(__half* __restrict__ probs)
{
    long long rowid = blockIdx.x;
    __half* row = probs + rowid * S_;
    int t = threadIdx.x;
    const bool act = t < 104;
    float v[8];
    if (act) {
        uint4 raw = *(const uint4*)(row + t * 8);
        const __half2* hp = (const __half2*)&raw;
#pragma unroll
        for (int j = 0; j < 4; j++) {
            v[2 * j]     = __low2float(hp[j]);
            v[2 * j + 1] = __high2float(hp[j]);
        }
    } else {
#pragma unroll
        for (int j = 0; j < 8; j++) v[j] = -1e30f;
    }
    float mx = v[0];
#pragma unroll
    for (int j = 1; j < 8; j++) mx = fmaxf(mx, v[j]);
    __shared__ float red[128];
    red[t] = mx; __syncthreads();
    for (int s = 64; s > 0; s >>= 1) { if (t < s) red[t] = fmaxf(red[t], red[t + s]); __syncthreads(); }
    mx = red[0]; __syncthreads();
    float sum = 0.f;
    if (act) {
#pragma unroll
        for (int j = 0; j < 8; j++) { v[j] = __expf(v[j] - mx); sum += v[j]; }
    }
    red[t] = sum; __syncthreads();
    for (int s = 64; s > 0; s >>= 1) { if (t < s) red[t] += red[t + s]; __syncthreads(); }
    float inv = 1.f / red[0];
    if (act) {
        uint4 out;
        __half2* op = (__half2*)&out;
#pragma unroll
        for (int j = 0; j < 4; j++)
            op[j] = __floats2half2_rn(v[2 * j] * inv, v[2 * j + 1] * inv);
        *(uint4*)(row + t * 8) = out;
    }
}

// ---------------- host launch ----------------
#define GETSYMF(var, sym) do { void* p__; cudaGetSymbolAddress(&p__, sym); var = (float*)p__; } while (0)
#define GETSYMH(var, sym) do { void* p__; cudaGetSymbolAddress(&p__, sym); var = (__half*)p__; } while (0)

extern "C" void kernel_launch(void* const* d_in, const int* in_sizes, int n_in,
                              void* d_out, int out_size)
{
    const float *embeds_vlm, *embeds_exp, *cond, *attn_mask;
    const int* pos;
    const float *vlm_ln1_w, *vlm_ln2_w, *vlm_q_w, *vlm_k_w, *vlm_v_w, *vlm_o_w;
    const float *vlm_gate_w, *vlm_up_w, *vlm_down_w;
    const float *exp_ln1_dw, *exp_ln1_db, *exp_ln2_dw, *exp_ln2_db;
    const float *exp_q_w, *exp_k_w, *exp_v_w, *exp_o_w, *exp_gate_w, *exp_up_w, *exp_down_w;

    if (in_sizes[3] == B_ * S_) {
        embeds_vlm = (const float*)d_in[0];  embeds_exp = (const float*)d_in[1];
        cond       = (const float*)d_in[2];  pos        = (const int*)  d_in[3];
        attn_mask  = (const float*)d_in[4];
        vlm_ln1_w  = (const float*)d_in[5];  vlm_ln2_w  = (const float*)d_in[6];
        vlm_q_w    = (const float*)d_in[7];  vlm_k_w    = (const float*)d_in[8];
        vlm_v_w    = (const float*)d_in[9];  vlm_o_w    = (const float*)d_in[10];
        vlm_gate_w = (const float*)d_in[11]; vlm_up_w   = (const float*)d_in[12];
        vlm_down_w = (const float*)d_in[13];
        exp_ln1_dw = (const float*)d_in[14]; exp_ln1_db = (const float*)d_in[15];
        exp_ln2_dw = (const float*)d_in[16]; exp_ln2_db = (const float*)d_in[17];
        exp_q_w    = (const float*)d_in[18]; exp_k_w    = (const float*)d_in[19];
        exp_v_w    = (const float*)d_in[20]; exp_o_w    = (const float*)d_in[21];
        exp_gate_w = (const float*)d_in[22]; exp_up_w   = (const float*)d_in[23];
        exp_down_w = (const float*)d_in[24];
    } else {
        embeds_vlm = (const float*)d_in[0];  embeds_exp = (const float*)d_in[1];
        cond       = (const float*)d_in[2];
        vlm_ln1_w  = (const float*)d_in[3];  vlm_ln2_w  = (const float*)d_in[4];
        vlm_q_w    = (const float*)d_in[5];  vlm_k_w    = (const float*)d_in[6];
        vlm_v_w    = (const float*)d_in[7];  vlm_o_w    = (const float*)d_in[8];
        vlm_gate_w = (const float*)d_in[9];  vlm_up_w   = (const float*)d_in[10];
        vlm_down_w = (const float*)d_in[11];
        exp_ln1_dw = (const float*)d_in[12]; exp_ln1_db = (const float*)d_in[13];
        exp_ln2_dw = (const float*)d_in[14]; exp_ln2_db = (const float*)d_in[15];
        exp_q_w    = (const float*)d_in[16]; exp_k_w    = (const float*)d_in[17];
        exp_v_w    = (const float*)d_in[18]; exp_o_w    = (const float*)d_in[19];
        exp_gate_w = (const float*)d_in[20]; exp_up_w   = (const float*)d_in[21];
        exp_down_w = (const float*)d_in[22];
        pos        = (const int*)  d_in[23];
        attn_mask  = (const float*)d_in[24];
    }

    __half *hv, *he, *q, *qt, *kv, *probs, *attnt, *attne, *mg, *eg, *wb;
    float *mod1, *mod2, *hv1, *he1;
    GETSYMH(hv, g_hv);   GETSYMH(he, g_he);   GETSYMF(mod1, g_mod1); GETSYMF(mod2, g_mod2);
    GETSYMH(q, g_q);     GETSYMH(qt, g_qt);   GETSYMH(kv, g_kv);
    GETSYMH(probs, g_probs);
    GETSYMH(attnt, g_attnt);   GETSYMH(attne, g_attne);
    GETSYMF(hv1, g_hv1); GETSYMF(he1, g_he1);
    GETSYMH(mg, g_mg);   GETSYMH(eg, g_eg);   GETSYMH(wb, g_wbuf);

    // wbuf layout: vq | round_many(5) | vkv | ekv | vug | eug
    const long long n_vq = (long long)W_V_ * H_ * DH_;
    const float* srcs[NW] = {vlm_o_w, vlm_down_w, exp_q_w, exp_o_w, exp_down_w};
    long long cnts[NW] = {
        (long long)H_*DH_*W_V_, (long long)MLPV_*W_V_,
        (long long)W_E_*H_*DH_, (long long)H_*DH_*W_E_, (long long)MLPE_*W_E_};
    RoundDesc rd;
    long long ofs = n_vq; int blk = 0;
    const __half* wptr[NW];
    for (int i = 0; i < NW; i++) {
        rd.src[i] = (const float4*)srcs[i];
        rd.dofs[i] = ofs;
        rd.blkStart[i] = blk;
        wptr[i] = wb + ofs;
        ofs += cnts[i];
        blk += (int)(cnts[i] / 4096);
    }
    rd.blkStart[NW] = blk;
    const __half* w_vq = wb;
    const __half *w_vo = wptr[0], *w_vd = wptr[1];
    const __half *w_eq = wptr[2], *w_eo = wptr[3], *w_ed = wptr[4];
    __half* w_vkv = wb + ofs;  ofs += (long long)W_V_ * 512;
    __half* w_ekv = wb + ofs;  ofs += (long long)W_E_ * 512;
    __half* w_vug = wb + ofs;  ofs += (long long)W_V_ * 2 * MLPV_;
    __half* w_eug = wb + ofs;  ofs += (long long)W_E_ * 2 * MLPE_;

    const int SMG  = 4 * STGB;
    const int SMT  = 4 * STG1;
    const int SM64 = 4 * STG64;
    cudaFuncSetAttribute(gemm16<4>, cudaFuncAttributeMaxDynamicSharedMemorySize, SMG);
    cudaFuncSetAttribute(gemm16<6>, cudaFuncAttributeMaxDynamicSharedMemorySize, SMG);
    cudaFuncSetAttribute(gemm16_tb1, cudaFuncAttributeMaxDynamicSharedMemorySize, SMT);
    cudaFuncSetAttribute((gemm16m64<0,0>), cudaFuncAttributeMaxDynamicSharedMemorySize, SM64);
    cudaFuncSetAttribute((gemm16m64<3,0>), cudaFuncAttributeMaxDynamicSharedMemorySize, SM64);
    cudaFuncSetAttribute((gemm16m64<3,1>), cudaFuncAttributeMaxDynamicSharedMemorySize, SM64);

    float* out_v = (float*)d_out;
    float* out_e = (float*)d_out + (long long)B_ * S_V_ * W_V_;

    long long sHv = (long long)S_V_ * W_V_, sHe = (long long)S_E_ * W_E_;
    long long sQ = (long long)S_ * H_ * DH_;
    long long sKV = (long long)S_ * 512;
    long long sL = (long long)S_ * S_;
    long long sQt = (long long)S_ * DH_;

    // L0..L2
    round4<<<(int)((n_vq / 4 + 255) / 256), 256>>>((const float4*)vlm_q_w, (__half2*)wb, (int)(n_vq / 4));
    rms_scale<<<B_ * S_V_, 256>>>(embeds_vlm, vlm_ln1_w, hv, W_V_);
    modmm2d<<<dim3(48, B_, 2), 256>>>(cond, exp_ln1_dw, exp_ln1_db, mod1,
                                      exp_ln2_dw, exp_ln2_db, mod2);
    // L3: VLM Q projection (ncu target)
    gemm16m64<0,0><<<dim3(16, 12, B_), 128, SM64>>>(hv, w_vq, q, nullptr, S_V_, H_ * DH_, W_V_, sHv, 0, sQ, 1, H_ * DH_);
    // staging remainder
    round_many<<<blk, 256>>>(rd, wb);
    concat_kv<<<(W_V_ * 64 + 255) / 256, 256>>>((const float4*)vlm_k_w, (const float4*)vlm_v_w, (__half2*)w_vkv, W_V_);
    concat_kv<<<(W_E_ * 64 + 255) / 256, 256>>>((const float4*)exp_k_w, (const float4*)exp_v_w, (__half2*)w_ekv, W_E_);
    {
        long long n4v = (long long)W_V_ * MLPV_ / 4;
        interleave2<<<(int)((n4v + 1023) / 1024), 256>>>((const float4*)vlm_up_w, (const float4*)vlm_gate_w, (uint4*)w_vug, n4v);
        long long n4e = (long long)W_E_ * MLPE_ / 4;
        interleave2<<<(int)((n4e + 1023) / 1024), 256>>>((const float4*)exp_up_w, (const float4*)exp_gate_w, (uint4*)w_eug, n4e);
    }
    rms_mod<<<B_ * S_E_, 256>>>(embeds_exp, mod1, he, W_E_, S_E_);

    // exp Q + fused KV projections
    gemm16m64<0,0><<<dim3(16, 1, B_), 128, SM64>>>(he, w_eq, q + (long long)S_V_ * H_ * DH_, nullptr, S_E_, H_ * DH_, W_E_, sHe, 0, sQ, 1, H_ * DH_);
    gemm16m64<0,0><<<dim3(4, 12, B_), 128, SM64>>>(hv, w_vkv, kv, nullptr, S_V_, 512, W_V_, sHv, 0, sKV, 1, 512);
    gemm16m64<0,0><<<dim3(4, 1, B_), 128, SM64>>>(he, w_ekv, kv + S_V_ * 512, nullptr, S_E_, 512, W_E_, sHe, 0, sKV, 1, 512);

    // RoPE
    rope4h_t<<<(B_ * S_ * H_ * 32 + 255) / 256, 256>>>(q, qt, pos);
    rope_k_kv<<<(B_ * S_ * 32 + 255) / 256, 256>>>(kv, pos);

    // attention
    {
        gemm16_tb1<<<dim3(7, 7, B_ * H_), 256, SMT>>>(qt, kv, probs, attn_mask, S_, S_, DH_, sQt, sKV, sL, H_, 512);
        softmax8h<<<B_ * H_ * S_, 128>>>(probs);
        gemm16m64<0,0><<<dim3(2, 13, B_ * H_), 128, SM64>>>(probs, kv + 256, attnt, nullptr, S_, DH_, S_, sL, sKV, sQt, H_, 512);
        exp_gather<<<(B_ * 64 * 256 + 255) / 256, 256>>>((const uint4*)attnt, (uint4*)attne);
    }

    // output projections + residuals
    gemm16m64<3,1><<<dim3(16, 12, B_), 128, SM64>>>(attnt, w_vo, hv1, embeds_vlm, S_V_, W_V_, H_ * DH_, 0, 0, sHv, 1, W_V_);
    gemm16<4><<<dim3(8, 1, B_), 256, SMG>>>(attne, w_eo, he1, embeds_exp, mod1, S_E_, W_E_, H_ * DH_, (long long)S_E_ * H_ * DH_, 0, sHe, 1);

    // pre-MLP norms
    rms_scale<<<B_ * S_V_, 256>>>(hv1, vlm_ln2_w, hv, W_V_);
    rms_mod<<<B_ * S_E_, 256>>>(he1, mod2, he, W_E_, S_E_);

    // VLM MLP
    {
        int M = B_ * S_V_;
        gemm16<6><<<dim3(256, 24, 1), 256, SMG>>>(hv, w_vug, mg, nullptr, nullptr, M, 2 * MLPV_, W_V_, 0, 0, 0, 1);
        gemm16m64<3,0><<<dim3(16, 48, 1), 128, SM64>>>(mg, w_vd, out_v, hv1, M, W_V_, MLPV_, 0, 0, 0, 1, W_V_);
    }

    // expert MLP
    {
        int M = B_ * S_E_;
        gemm16<6><<<dim3(64, 2, 1), 256, SMG>>>(he, w_eug, eg, nullptr, nullptr, M, 2 * MLPE_, W_E_, 0, 0, 0, 1);
        gemm16<4><<<dim3(8, 2, 1), 256, SMG>>>(eg, w_ed, out_e, he1, mod2, M, W_E_, MLPE_, 0, 0, 0, 1);
    }
}

// round 16
// speedup vs baseline: 1.2374x; 1.0156x over previous
#include <cuda_runtime.h>
#include <cuda_fp16.h>
#include <cuda_bf16.h>
#include <math.h>

#define B_    4
#define S_V_  768
#define S_E_  64
#define S_    832
#define W_V_  2048
#define W_E_  1024
#define H_    8
#define DH_   256
#define MLPV_ 16384
#define MLPE_ 4096
#define EPS_  1e-6f
#define SCALE_ 0.0625f

// ---------------- scratch ----------------
__device__ __half g_hv   [B_*S_V_*W_V_];
__device__ __half g_he   [B_*S_E_*W_E_];
__device__ float  g_mod1 [B_*3*W_E_];
__device__ float  g_mod2 [B_*3*W_E_];
__device__ __half g_q    [(long long)B_*S_*H_*DH_];
__device__ __half g_qt   [(long long)B_*H_*S_*DH_];
__device__ __half g_kv   [(long long)B_*S_*512];
__device__ __half g_probs[(long long)B_*H_*S_*S_];
__device__ __half g_attnt[(long long)B_*H_*S_*DH_];
__device__ __half g_attne[B_*S_E_*H_*DH_];
__device__ float  g_hv1  [B_*S_V_*W_V_];
__device__ float  g_he1  [B_*S_E_*W_E_];
__device__ __half g_mg   [(long long)B_*S_V_*MLPV_];
__device__ __half g_eg   [B_*S_E_*MLPE_];
__device__ __half g_wbuf [127401984];

// ---------------- static streams/events (created at load, before baseline) ----
struct GpuStreams {
    cudaStream_t s2 = 0;
    cudaEvent_t evF = 0, evVQ = 0, evKV = 0, evRM = 0, evIL = 0;
    bool ok = false;
    GpuStreams() {
        if (cudaStreamCreateWithFlags(&s2, cudaStreamNonBlocking) != cudaSuccess) return;
        if (cudaEventCreateWithFlags(&evF,  cudaEventDisableTiming) != cudaSuccess) return;
        if (cudaEventCreateWithFlags(&evVQ, cudaEventDisableTiming) != cudaSuccess) return;
        if (cudaEventCreateWithFlags(&evKV, cudaEventDisableTiming) != cudaSuccess) return;
        if (cudaEventCreateWithFlags(&evRM, cudaEventDisableTiming) != cudaSuccess) return;
        if (cudaEventCreateWithFlags(&evIL, cudaEventDisableTiming) != cudaSuccess) return;
        ok = true;
    }
};
static GpuStreams g_si;

__device__ __forceinline__ float gelu_t(float x) {
    return 0.5f * x * (1.f + tanhf(0.7978845608028654f * (x + 0.044715f * x * x * x)));
}

__device__ __forceinline__ void mma_f16(float* c, const unsigned* a, const unsigned* b) {
    asm volatile(
        "mma.sync.aligned.m16n8k16.row.col.f32.f16.f16.f32 "
        "{%0,%1,%2,%3}, {%4,%5,%6,%7}, {%8,%9}, {%0,%1,%2,%3};\n"
        : "+f"(c[0]), "+f"(c[1]), "+f"(c[2]), "+f"(c[3])
        : "r"(a[0]), "r"(a[1]), "r"(a[2]), "r"(a[3]), "r"(b[0]), "r"(b[1]));
}

// ============ gemm16: fp16 operands, fp32 accum, TB=0 ============
#define ASTB 10240
#define STGB 18944
template<int EPI>
__global__ __launch_bounds__(256, 2)
void gemm16(const __half* __restrict__ A, const __half* __restrict__ Bm,
            void* __restrict__ Cv, const float* __restrict__ aux,
            const float* __restrict__ modv,
            int M, int N, int K,
            long long sA, long long sB, long long sC, int bInner)
{
    extern __shared__ __align__(16) char sm[];

    const int z = blockIdx.z;
    A  += (long long)z * sA;
    Bm += (long long)(z / bInner) * sB;

    const int tid  = threadIdx.x;
    const int lane = tid & 31;
    const int wid  = tid >> 5;
    const int wm   = (wid & 1) * 64;
    const int wn   = (wid >> 1) * 32;
    const int bm   = blockIdx.y * 128;
    const int bn   = blockIdx.x * 128;
    const int row  = lane >> 2, col = lane & 3;

    unsigned sbase = (unsigned)__cvta_generic_to_shared(sm);

    auto issue = [&](int st) {
        const int ktE = st * 32;
        const unsigned sb = sbase + (unsigned)((st & 3) * STGB);
#pragma unroll
        for (int j = 0; j < 2; j++) {
            int id = tid + j * 256;
            int r = id >> 2, c = id & 3;
            int gm = bm + r;
            const __half* gp = A + (long long)(gm < M ? gm : M - 1) * K + ktE + c * 8;
            unsigned dst = sb + (unsigned)(r * 80 + c * 16);
            int zf = (gm < M) ? 16 : 0;
            asm volatile("cp.async.cg.shared.global [%0], [%1], 16, %2;\n"
                         :: "r"(dst), "l"(gp), "r"(zf));
        }
#pragma unroll
        for (int j = 0; j < 2; j++) {
            int id = tid + j * 256;
            int kr = id >> 4, c = id & 15;
            int gn = bn + c * 8;
            const __half* gp = Bm + (long long)(ktE + kr) * N + (gn < N ? gn : N - 8);
            unsigned dst = sb + (unsigned)(ASTB + kr * 272 + c * 16);
            int zf = (gn < N) ? 16 : 0;
            asm volatile("cp.async.cg.shared.global [%0], [%1], 16, %2;\n"
                         :: "r"(dst), "l"(gp), "r"(zf));
        }
    };

    float c[4][4][4];
#pragma unroll
    for (int i = 0; i < 4; i++)
#pragma unroll
        for (int j = 0; j < 4; j++)
#pragma unroll
            for (int l = 0; l < 4; l++) c[i][j][l] = 0.f;

    const unsigned aoff = (unsigned)((((lane >> 3) & 1) * 8 + (lane & 7)) * 80 + (lane >> 4) * 16);
    const unsigned boff4 = (unsigned)(ASTB + (((lane >> 3) & 1) * 8 + (lane & 7)) * 272
                                      + (lane >> 4) * 16 + wn * 2);

    const int nk = K / 32;
#pragma unroll 1
    for (int s = 0; s < 3; s++) { issue(s); asm volatile("cp.async.commit_group;\n"); }

#pragma unroll 1
    for (int kt = 0; kt < nk; kt++) {
        asm volatile("cp.async.wait_group 2;\n");
        __syncthreads();
        if (kt + 3 < nk) issue(kt + 3);
        asm volatile("cp.async.commit_group;\n");

        const unsigned stg = sbase + (unsigned)((kt & 3) * STGB);
#pragma unroll
        for (int sub = 0; sub < 2; sub++) {
            unsigned af[4][4], bf[4][2];
#pragma unroll
            for (int mt = 0; mt < 4; mt++) {
                unsigned ad = stg + (unsigned)((wm + mt * 16) * 80 + sub * 32) + aoff;
                asm volatile("ldmatrix.sync.aligned.m8n8.x4.shared.b16 {%0,%1,%2,%3}, [%4];"
                             : "=r"(af[mt][0]), "=r"(af[mt][1]), "=r"(af[mt][2]), "=r"(af[mt][3])
                             : "r"(ad));
            }
#pragma unroll
            for (int ntp = 0; ntp < 2; ntp++) {
                unsigned bd = stg + (unsigned)(sub * 16 * 272 + ntp * 32) + boff4;
                asm volatile("ldmatrix.sync.aligned.m8n8.x4.trans.shared.b16 {%0,%1,%2,%3}, [%4];"
                             : "=r"(bf[2*ntp][0]), "=r"(bf[2*ntp][1]),
                               "=r"(bf[2*ntp+1][0]), "=r"(bf[2*ntp+1][1])
                             : "r"(bd));
            }
#pragma unroll
            for (int mt = 0; mt < 4; mt++)
#pragma unroll
                for (int nt = 0; nt < 4; nt++)
                    mma_f16(c[mt][nt], af[mt], bf[nt]);
        }
    }

    if (EPI == 3 || EPI == 4) aux += (long long)z * sC;
    __half* Ch = (__half*)Cv + (long long)z * sC;
    float*  Cf = (float*)Cv + (long long)z * sC;

    auto epi_store = [&](int gm, int gn, float x0, float x1) {
        if (EPI == 6) {
            Ch[(long long)gm * (N >> 1) + (gn >> 1)] = __float2half_rn(gelu_t(x1) * x0);
            return;
        }
        long long o = (long long)gm * N + gn;
        if (EPI == 0) {
            *(__half2*)(Ch + o) = __halves2half2(__float2half_rn(x0), __float2half_rn(x1));
        } else if (EPI == 3) {
            float2 u = *(const float2*)(aux + o);
            *(float2*)(Cf + o) = make_float2(x0 + u.x, x1 + u.y);
        } else if (EPI == 4) {
            int bb = z + gm / S_E_;
            float g0 = modv[(long long)bb * 3 * W_E_ + 2 * W_E_ + gn];
            float g1 = modv[(long long)bb * 3 * W_E_ + 2 * W_E_ + gn + 1];
            float2 u = *(const float2*)(aux + o);
            *(float2*)(Cf + o) = make_float2(u.x + x0 * g0, u.y + x1 * g1);
        }
    };

#pragma unroll
    for (int mt = 0; mt < 4; mt++) {
#pragma unroll
        for (int nt = 0; nt < 4; nt++) {
            int gm = bm + wm + mt * 16 + row;
            int gn = bn + wn + nt * 8 + col * 2;
            if (gn < N) {
                if (gm < M)     epi_store(gm,     gn, c[mt][nt][0], c[mt][nt][1]);
                if (gm + 8 < M) epi_store(gm + 8, gn, c[mt][nt][2], c[mt][nt][3]);
            }
        }
    }
}

// ============ gemm16m64: 64x128 tile, 128 thr, 4 stages ====
#define A64B 5120
#define STG64 (A64B + 8704)
template<int EPI, int GA>
__global__ __launch_bounds__(128, 4)
void gemm16m64(const __half* __restrict__ A, const __half* __restrict__ Bm,
               void* __restrict__ Cv, const float* __restrict__ aux,
               int M, int N, int K, long long sA, long long sB, long long sC,
               int bInner, int ldb)
{
    extern __shared__ __align__(16) char sm[];

    const int z = blockIdx.z;
    if (!GA) A += (long long)z * sA;
    Bm += (long long)(z / bInner) * sB;

    const int tid  = threadIdx.x;
    const int lane = tid & 31;
    const int wid  = tid >> 5;
    const int wn   = wid * 32;
    const int bm   = blockIdx.y * 64;
    const int bn   = blockIdx.x * 128;
    const int row  = lane >> 2, col = lane & 3;

    unsigned sbase = (unsigned)__cvta_generic_to_shared(sm);

    auto issue = [&](int st) {
        const int ktE = st * 32;
        const unsigned sb = sbase + (unsigned)((st & 3) * STG64);
#pragma unroll
        for (int j = 0; j < 2; j++) {
            int id = tid + j * 128;
            int r = id >> 2, c = id & 3;
            int gm = bm + r;
            const __half* gp;
            if (GA) {
                int kc = ktE + c * 8;
                int gmc = gm < M ? gm : M - 1;
                gp = A + ((long long)(z * H_ + (kc >> 8)) * S_ + gmc) * 256 + (kc & 255);
            } else {
                gp = A + (long long)(gm < M ? gm : M - 1) * K + ktE + c * 8;
            }
            unsigned dst = sb + (unsigned)(r * 80 + c * 16);
            int zf = (gm < M) ? 16 : 0;
            asm volatile("cp.async.cg.shared.global [%0], [%1], 16, %2;\n"
                         :: "r"(dst), "l"(gp), "r"(zf));
        }
#pragma unroll
        for (int j = 0; j < 4; j++) {
            int id = tid + j * 128;
            int kr = id >> 4, c = id & 15;
            int gn = bn + c * 8;
            const __half* gp = Bm + (long long)(ktE + kr) * ldb + (gn < N ? gn : N - 8);
            unsigned dst = sb + (unsigned)(A64B + kr * 272 + c * 16);
            int zf = (gn < N) ? 16 : 0;
            asm volatile("cp.async.cg.shared.global [%0], [%1], 16, %2;\n"
                         :: "r"(dst), "l"(gp), "r"(zf));
        }
    };

    float c[4][4][4];
#pragma unroll
    for (int i = 0; i < 4; i++)
#pragma unroll
        for (int j = 0; j < 4; j++)
#pragma unroll
            for (int l = 0; l < 4; l++) c[i][j][l] = 0.f;

    const unsigned aoff = (unsigned)((((lane >> 3) & 1) * 8 + (lane & 7)) * 80 + (lane >> 4) * 16);
    const unsigned boff4 = (unsigned)(A64B + (((lane >> 3) & 1) * 8 + (lane & 7)) * 272
                                      + (lane >> 4) * 16 + wn * 2);

    const int nk = K / 32;
#pragma unroll 1
    for (int s = 0; s < 3; s++) { issue(s); asm volatile("cp.async.commit_group;\n"); }

#pragma unroll 1
    for (int kt = 0; kt < nk; kt++) {
        asm volatile("cp.async.wait_group 2;\n");
        __syncthreads();
        if (kt + 3 < nk) issue(kt + 3);
        asm volatile("cp.async.commit_group;\n");

        const unsigned stg = sbase + (unsigned)((kt & 3) * STG64);
#pragma unroll
        for (int sub = 0; sub < 2; sub++) {
            unsigned af[4][4], bf[4][2];
#pragma unroll
            for (int mt = 0; mt < 4; mt++) {
                unsigned ad = stg + (unsigned)((mt * 16) * 80 + sub * 32) + aoff;
                asm volatile("ldmatrix.sync.aligned.m8n8.x4.shared.b16 {%0,%1,%2,%3}, [%4];"
                             : "=r"(af[mt][0]), "=r"(af[mt][1]), "=r"(af[mt][2]), "=r"(af[mt][3])
                             : "r"(ad));
            }
#pragma unroll
            for (int ntp = 0; ntp < 2; ntp++) {
                unsigned bd = stg + (unsigned)(sub * 16 * 272 + ntp * 32) + boff4;
                asm volatile("ldmatrix.sync.aligned.m8n8.x4.trans.shared.b16 {%0,%1,%2,%3}, [%4];"
                             : "=r"(bf[2*ntp][0]), "=r"(bf[2*ntp][1]),
                               "=r"(bf[2*ntp+1][0]), "=r"(bf[2*ntp+1][1])
                             : "r"(bd));
            }
#pragma unroll
            for (int mt = 0; mt < 4; mt++)
#pragma unroll
                for (int nt = 0; nt < 4; nt++)
                    mma_f16(c[mt][nt], af[mt], bf[nt]);
        }
    }

    if (EPI == 3) aux += (long long)z * sC;
    __half* Ch = (__half*)Cv + (long long)z * sC;
    float*  Cf = (float*)Cv + (long long)z * sC;

#pragma unroll
    for (int mt = 0; mt < 4; mt++) {
#pragma unroll
        for (int nt = 0; nt < 4; nt++) {
            int gm = bm + mt * 16 + row;
            int gn = bn + wn + nt * 8 + col * 2;
            if (gn >= N) continue;
#pragma unroll
            for (int hh = 0; hh < 2; hh++) {
                int g = gm + hh * 8;
                if (g >= M) continue;
                long long o = (long long)g * N + gn;
                float x0 = c[mt][nt][hh * 2], x1 = c[mt][nt][hh * 2 + 1];
                if (EPI == 0) {
                    *(__half2*)(Ch + o) = __halves2half2(__float2half_rn(x0), __float2half_rn(x1));
                } else {
                    float2 u = *(const float2*)(aux + o);
                    *(float2*)(Cf + o) = make_float2(x0 + u.x, x1 + u.y);
                }
            }
        }
    }
}

// ============ gemm16_tb1: QK^T, fused scale+mask -> fp16 probs, ldb B stride ============
#define STG1 20480
__global__ __launch_bounds__(256, 2)
void gemm16_tb1(const __half* __restrict__ A, const __half* __restrict__ Bm,
                __half* __restrict__ C, const float* __restrict__ mask,
                int M, int N, int K,
                long long sA, long long sB, long long sC, int bInner, int ldb)
{
    extern __shared__ __align__(16) char sm[];

    const int z = blockIdx.z;
    A  += (long long)z * sA;
    Bm += (long long)(z / bInner) * sB;
    C  += (long long)z * sC;
    const float* mrow = mask + (long long)(z >> 3) * S_ * S_;

    const int tid  = threadIdx.x;
    const int lane = tid & 31;
    const int wid  = tid >> 5;
    const int wm   = (wid & 1) * 64;
    const int wn   = (wid >> 1) * 32;
    const int bm   = blockIdx.y * 128;
    const int bn   = blockIdx.x * 128;
    const int row  = lane >> 2, col = lane & 3;

    unsigned sbase = (unsigned)__cvta_generic_to_shared(sm);

    auto issue = [&](int st) {
        const int ktE = st * 32;
        const unsigned sb = sbase + (unsigned)((st & 3) * STG1);
#pragma unroll
        for (int j = 0; j < 2; j++) {
            int id = tid + j * 256;
            int r = id >> 2, c = id & 3;
            int gm = bm + r;
            const __half* gp = A + (long long)(gm < M ? gm : M - 1) * K + ktE + c * 8;
            unsigned dst = sb + (unsigned)(r * 80 + c * 16);
            int zf = (gm < M) ? 16 : 0;
            asm volatile("cp.async.cg.shared.global [%0], [%1], 16, %2;\n"
                         :: "r"(dst), "l"(gp), "r"(zf));
        }
#pragma unroll
        for (int j = 0; j < 2; j++) {
            int id = tid + j * 256;
            int r = id >> 2, c = id & 3;
            int gn = bn + r;
            const __half* gp = Bm + (long long)(gn < N ? gn : N - 1) * ldb + ktE + c * 8;
            unsigned dst = sb + (unsigned)(ASTB + r * 80 + c * 16);
            int zf = (gn < N) ? 16 : 0;
            asm volatile("cp.async.cg.shared.global [%0], [%1], 16, %2;\n"
                         :: "r"(dst), "l"(gp), "r"(zf));
        }
    };

    float c[4][4][4];
#pragma unroll
    for (int i = 0; i < 4; i++)
#pragma unroll
        for (int j = 0; j < 4; j++)
#pragma unroll
            for (int l = 0; l < 4; l++) c[i][j][l] = 0.f;

    const unsigned aoff = (unsigned)((((lane >> 3) & 1) * 8 + (lane & 7)) * 80 + (lane >> 4) * 16);
    const unsigned boff4 = (unsigned)(ASTB + ((lane & 7) + (lane >> 4) * 8 + wn) * 80
                                      + (((lane >> 3) & 1) * 16));

    const int nk = K / 32;
#pragma unroll 1
    for (int s = 0; s < 3; s++) { issue(s); asm volatile("cp.async.commit_group;\n"); }

#pragma unroll 1
    for (int kt = 0; kt < nk; kt++) {
        asm volatile("cp.async.wait_group 2;\n");
        __syncthreads();
        if (kt + 3 < nk) issue(kt + 3);
        asm volatile("cp.async.commit_group;\n");

        const unsigned stg = sbase + (unsigned)((kt & 3) * STG1);
#pragma unroll
        for (int sub = 0; sub < 2; sub++) {
            unsigned af[4][4], bf[4][2];
#pragma unroll
            for (int mt = 0; mt < 4; mt++) {
                unsigned ad = stg + (unsigned)((wm + mt * 16) * 80 + sub * 32) + aoff;
                asm volatile("ldmatrix.sync.aligned.m8n8.x4.shared.b16 {%0,%1,%2,%3}, [%4];"
                             : "=r"(af[mt][0]), "=r"(af[mt][1]), "=r"(af[mt][2]), "=r"(af[mt][3])
                             : "r"(ad));
            }
#pragma unroll
            for (int ntp = 0; ntp < 2; ntp++) {
                unsigned bd = stg + (unsigned)(ntp * 16 * 80 + sub * 32) + boff4;
                asm volatile("ldmatrix.sync.aligned.m8n8.x4.shared.b16 {%0,%1,%2,%3}, [%4];"
                             : "=r"(bf[2*ntp][0]), "=r"(bf[2*ntp][1]),
                               "=r"(bf[2*ntp+1][0]), "=r"(bf[2*ntp+1][1])
                             : "r"(bd));
            }
#pragma unroll
            for (int mt = 0; mt < 4; mt++)
#pragma unroll
                for (int nt = 0; nt < 4; nt++)
                    mma_f16(c[mt][nt], af[mt], bf[nt]);
        }
    }

#pragma unroll
    for (int mt = 0; mt < 4; mt++) {
#pragma unroll
        for (int nt = 0; nt < 4; nt++) {
            int gm = bm + wm + mt * 16 + row;
            int gn = bn + wn + nt * 8 + col * 2;
            if (gn >= N) continue;
#pragma unroll
            for (int hh = 0; hh < 2; hh++) {
                int g = gm + hh * 8;
                if (g >= M) continue;
                float2 mv = *(const float2*)(mrow + (long long)g * S_ + gn);
                float x0 = c[mt][nt][hh * 2] * SCALE_ + mv.x;
                float x1 = c[mt][nt][hh * 2 + 1] * SCALE_ + mv.y;
                *(__half2*)(C + (long long)g * N + gn) = __floats2half2_rn(x0, x1);
            }
        }
    }
}

// ---------------- weight staging ----------------
__global__ void round4(const float4* __restrict__ s, __half2* __restrict__ d, int n4)
{
    int i = blockIdx.x * 256 + threadIdx.x;
    if (i >= n4) return;
    float4 v = s[i];
    d[i * 2]     = __floats2half2_rn(v.x, v.y);
    d[i * 2 + 1] = __floats2half2_rn(v.z, v.w);
}

#define NW 5
struct RoundDesc {
    const float4* src[NW];
    long long dofs[NW];
    int blkStart[NW + 1];
};

__global__ void round_many(RoundDesc d, __half* __restrict__ wbuf)
{
    int b = blockIdx.x;
    int w = 0;
#pragma unroll
    for (int i = 0; i < NW; i++) if (b >= d.blkStart[i + 1]) w = i + 1;
    int lb = b - d.blkStart[w];
    const float4* s = d.src[w] + (long long)lb * 1024;
    __half2* o = (__half2*)(wbuf + d.dofs[w]) + (long long)lb * 2048;
    int t = threadIdx.x;
#pragma unroll
    for (int i = 0; i < 4; i++) {
        float4 v = s[t + i * 256];
        o[(t + i * 256) * 2]     = __floats2half2_rn(v.x, v.y);
        o[(t + i * 256) * 2 + 1] = __floats2half2_rn(v.z, v.w);
    }
}

__global__ void interleave2(const float4* __restrict__ up, const float4* __restrict__ gate,
                            uint4* __restrict__ out, long long n4)
{
    long long i0 = (long long)blockIdx.x * 1024 + threadIdx.x;
#pragma unroll
    for (int j = 0; j < 4; j++) {
        long long i = i0 + j * 256;
        if (i >= n4) return;
        float4 u = up[i], g = gate[i];
        __half2 h0 = __floats2half2_rn(u.x, g.x);
        __half2 h1 = __floats2half2_rn(u.y, g.y);
        __half2 h2 = __floats2half2_rn(u.z, g.z);
        __half2 h3 = __floats2half2_rn(u.w, g.w);
        uint4 o;
        o.x = *(unsigned*)&h0; o.y = *(unsigned*)&h1;
        o.z = *(unsigned*)&h2; o.w = *(unsigned*)&h3;
        out[i] = o;
    }
}

__global__ void concat_kv(const float4* __restrict__ Wk, const float4* __restrict__ Wv,
                          __half2* __restrict__ dst, int R)
{
    int i = blockIdx.x * 256 + threadIdx.x;
    int total = R * 64;
    if (i >= total) return;
    int r = i >> 6, c4 = i & 63;
    float4 a = Wk[i], b = Wv[i];
    __half2* dk = dst + (r * 512 + c4 * 4) / 2;
    dk[0] = __floats2half2_rn(a.x, a.y);
    dk[1] = __floats2half2_rn(a.z, a.w);
    __half2* dv = dst + (r * 512 + 256 + c4 * 4) / 2;
    dv[0] = __floats2half2_rn(b.x, b.y);
    dv[1] = __floats2half2_rn(b.z, b.w);
}

__global__ void exp_gather(const uint4* __restrict__ in, uint4* __restrict__ out)
{
    int idx = blockIdx.x * 256 + threadIdx.x;
    int total = B_ * 64 * 256;
    if (idx >= total) return;
    int d8 = idx & 31;
    int h = (idx >> 5) & 7;
    int j = (idx >> 8) & 63;
    int b = idx >> 14;
    out[((b * 64 + j) * 2048 + h * 256 + d8 * 8) >> 3] =
        in[(((long long)(b * H_ + h) * S_ + S_V_ + j) * 256 + d8 * 8) >> 3];
}

// ---------------- row kernels ----------------
__device__ __forceinline__ float blockReduceSum(float v) {
    __shared__ float red[256];
    int t = threadIdx.x;
    red[t] = v; __syncthreads();
    for (int s = 128; s > 0; s >>= 1) {
        if (t < s) red[t] += red[t + s];
        __syncthreads();
    }
    float r = red[0];
    __syncthreads();
    return r;
}

__global__ void rms_scale(const float* __restrict__ x, const float* __restrict__ w,
                          __half* __restrict__ out, int W)
{
    long long base = (long long)blockIdx.x * W;
    float ss = 0.f;
    for (int c = threadIdx.x; c < W; c += 256) { float t = x[base + c]; ss += t * t; }
    float tot = blockReduceSum(ss);
    float inv = rsqrtf(tot / (float)W + EPS_);
    for (int c = threadIdx.x; c < W; c += 256)
        out[base + c] = __float2half_rn(x[base + c] * inv * (1.f + w[c]));
}

__global__ void rms_mod(const float* __restrict__ x, const float* __restrict__ mod,
                        __half* __restrict__ out, int W, int rowsPerB)
{
    long long base = (long long)blockIdx.x * W;
    int b = blockIdx.x / rowsPerB;
    const float* m = mod + (long long)b * 3 * W;
    float ss = 0.f;
    for (int c = threadIdx.x; c < W; c += 256) { float t = x[base + c]; ss += t * t; }
    float tot = blockReduceSum(ss);
    float inv = rsqrtf(tot / (float)W + EPS_);
    for (int c = threadIdx.x; c < W; c += 256)
        out[base + c] = __float2half_rn(x[base + c] * inv * (1.f + m[c]) + m[W + c]);
}

__global__ void modmm2d(const float* __restrict__ cond,
                        const float* __restrict__ W1, const float* __restrict__ b1, float* __restrict__ o1,
                        const float* __restrict__ W2, const float* __restrict__ b2, float* __restrict__ o2)
{
    const int NT = 3 * W_E_;
    const float* W = blockIdx.z ? W2 : W1;
    const float* bias = blockIdx.z ? b2 : b1;
    float* out = blockIdx.z ? o2 : o1;
    __shared__ float cs[W_E_];
    __shared__ float part[4][64];
    int bb = blockIdx.y;
    int tid = threadIdx.x;
    for (int i = tid; i < W_E_; i += 256) cs[i] = cond[bb * W_E_ + i];
    __syncthreads();
    int tx = tid & 63, ty = tid >> 6;
    int c = blockIdx.x * 64 + tx;
    const float* Wp = W + (long long)(ty * 256) * NT + c;
    const float* cp = cs + ty * 256;
    float s = 0.f;
#pragma unroll 4
    for (int k = 0; k < 256; k++) s += cp[k] * Wp[(long long)k * NT];
    part[ty][tx] = s;
    __syncthreads();
    if (ty == 0)
        out[(long long)bb * NT + c] = part[0][tx] + part[1][tx] + part[2][tx] + part[3][tx] + bias[c];
}

__global__ void rope_k_kv(__half* __restrict__ kv, const int* __restrict__ pos)
{
    int idx = blockIdx.x * blockDim.x + threadIdx.x;
    int total = B_ * S_ * 32;
    if (idx >= total) return;
    int d4 = (idx & 31) << 2;
    int s = (idx >> 5) % S_;
    int b = idx / (32 * S_);
    float p = (float)pos[b * S_ + s];
    __half* base = kv + (long long)(b * S_ + s) * 512;
    __half2 x1a = *(__half2*)(base + d4),       x1b = *(__half2*)(base + d4 + 2);
    __half2 x2a = *(__half2*)(base + d4 + 128), x2b = *(__half2*)(base + d4 + 130);
    float r1[4] = {__low2float(x1a), __high2float(x1a), __low2float(x1b), __high2float(x1b)};
    float r2[4] = {__low2float(x2a), __high2float(x2a), __low2float(x2b), __high2float(x2b)};
#pragma unroll
    for (int j = 0; j < 4; j++) {
        float ang = p * powf(10000.f, -(float)(2 * (d4 + j)) / 256.f);
        float sn, cs2; sincosf(ang, &sn, &cs2);
        float a = r1[j], bb = r2[j];
        r1[j] = a * cs2 - bb * sn;
        r2[j] = bb * cs2 + a * sn;
    }
    *(__half2*)(base + d4)       = __floats2half2_rn(r1[0], r1[1]);
    *(__half2*)(base + d4 + 2)   = __floats2half2_rn(r1[2], r1[3]);
    *(__half2*)(base + d4 + 128) = __floats2half2_rn(r2[0], r2[1]);
    *(__half2*)(base + d4 + 130) = __floats2half2_rn(r2[2], r2[3]);
}

__global__ void rope4h_t(const __half* __restrict__ q, __half* __restrict__ qt,
                         const int* __restrict__ pos)
{
    int idx = blockIdx.x * blockDim.x + threadIdx.x;
    int total = B_ * S_ * H_ * 32;
    if (idx >= total) return;
    int d4 = (idx & 31) << 2;
    int h = (idx >> 5) % H_;
    int s = (idx / (32 * H_)) % S_;
    int b = idx / (32 * H_ * S_);
    float p = (float)pos[b * S_ + s];
    const __half* src = q + (((long long)(b * S_ + s) * H_ + h) << 8);
    __half* dst = qt + (((long long)(b * H_ + h) * S_ + s) << 8);
    __half2 x1a = *(const __half2*)(src + d4),       x1b = *(const __half2*)(src + d4 + 2);
    __half2 x2a = *(const __half2*)(src + d4 + 128), x2b = *(const __half2*)(src + d4 + 130);
    float r1[4] = {__low2float(x1a), __high2float(x1a), __low2float(x1b), __high2float(x1b)};
    float r2[4] = {__low2float(x2a), __high2float(x2a), __low2float(x2b), __high2float(x2b)};
#pragma unroll
    for (int j = 0; j < 4; j++) {
        float ang = p * powf(10000.f, -(float)(2 * (d4 + j)) / 256.f);
        float sn, cs2; sincosf(ang, &sn, &cs2);
        float a = r1[j], bb = r2[j];
        r1[j] = a * cs2 - bb * sn;
        r2[j] = bb * cs2 + a * sn;
    }
    *(__half2*)(dst + d4)       = __floats2half2_rn(r1[0], r1[1]);
    *(__half2*)(dst + d4 + 2)   = __floats2half2_rn(r1[2], r1[3]);
    *(__half2*)(dst + d4 + 128) = __floats2half2_rn(r2[0], r2[1]);
    *(__half2*)(dst + d4 + 130) = __floats2half2_rn(r2[2], r2[3]);
}

__global__ __launch_bounds__(128)
void softmax8h(__half* __restrict__ probs)
{
    long long rowid = blockIdx.x;
    __half* row = probs + rowid * S_;
    int t = threadIdx.x;
    const bool act = t < 104;
    float v[8];
    if (act) {
        uint4 raw = *(const uint4*)(row + t * 8);
        const __half2* hp = (const __half2*)&raw;
#pragma unroll
        for (int j = 0; j < 4; j++) {
            v[2 * j]     = __low2float(hp[j]);
            v[2 * j + 1] = __high2float(hp[j]);
        }
    } else {
#pragma unroll
        for (int j = 0; j < 8; j++) v[j] = -1e30f;
    }
    float mx = v[0];
#pragma unroll
    for (int j = 1; j < 8; j++) mx = fmaxf(mx, v[j]);
    __shared__ float red[128];
    red[t] = mx; __syncthreads();
    for (int s = 64; s > 0; s >>= 1) { if (t < s) red[t] = fmaxf(red[t], red[t + s]); __syncthreads(); }
    mx = red[0]; __syncthreads();
    float sum = 0.f;
    if (act) {
#pragma unroll
        for (int j = 0; j < 8; j++) { v[j] = __expf(v[j] - mx); sum += v[j]; }
    }
    red[t] = sum; __syncthreads();
    for (int s = 64; s > 0; s >>= 1) { if (t < s) red[t] += red[t + s]; __syncthreads(); }
    float inv = 1.f / red[0];
    if (act) {
        uint4 out;
        __half2* op = (__half2*)&out;
#pragma unroll
        for (int j = 0; j < 4; j++)
            op[j] = __floats2half2_rn(v[2 * j] * inv, v[2 * j + 1] * inv);
        *(uint4*)(row + t * 8) = out;
    }
}

// ---------------- host launch ----------------
#define GETSYMF(var, sym) do { void* p__; cudaGetSymbolAddress(&p__, sym); var = (float*)p__; } while (0)
#define GETSYMH(var, sym) do { void* p__; cudaGetSymbolAddress(&p__, sym); var = (__half*)p__; } while (0)

extern "C" void kernel_launch(void* const* d_in, const int* in_sizes, int n_in,
                              void* d_out, int out_size)
{
    const float *embeds_vlm, *embeds_exp, *cond, *attn_mask;
    const int* pos;
    const float *vlm_ln1_w, *vlm_ln2_w, *vlm_q_w, *vlm_k_w, *vlm_v_w, *vlm_o_w;
    const float *vlm_gate_w, *vlm_up_w, *vlm_down_w;
    const float *exp_ln1_dw, *exp_ln1_db, *exp_ln2_dw, *exp_ln2_db;
    const float *exp_q_w, *exp_k_w, *exp_v_w, *exp_o_w, *exp_gate_w, *exp_up_w, *exp_down_w;

    if (in_sizes[3] == B_ * S_) {
        embeds_vlm = (const float*)d_in[0];  embeds_exp = (const float*)d_in[1];
        cond       = (const float*)d_in[2];  pos        = (const int*)  d_in[3];
        attn_mask  = (const float*)d_in[4];
        vlm_ln1_w  = (const float*)d_in[5];  vlm_ln2_w  = (const float*)d_in[6];
        vlm_q_w    = (const float*)d_in[7];  vlm_k_w    = (const float*)d_in[8];
        vlm_v_w    = (const float*)d_in[9];  vlm_o_w    = (const float*)d_in[10];
        vlm_gate_w = (const float*)d_in[11]; vlm_up_w   = (const float*)d_in[12];
        vlm_down_w = (const float*)d_in[13];
        exp_ln1_dw = (const float*)d_in[14]; exp_ln1_db = (const float*)d_in[15];
        exp_ln2_dw = (const float*)d_in[16]; exp_ln2_db = (const float*)d_in[17];
        exp_q_w    = (const float*)d_in[18]; exp_k_w    = (const float*)d_in[19];
        exp_v_w    = (const float*)d_in[20]; exp_o_w    = (const float*)d_in[21];
        exp_gate_w = (const float*)d_in[22]; exp_up_w   = (const float*)d_in[23];
        exp_down_w = (const float*)d_in[24];
    } else {
        embeds_vlm = (const float*)d_in[0];  embeds_exp = (const float*)d_in[1];
        cond       = (const float*)d_in[2];
        vlm_ln1_w  = (const float*)d_in[3];  vlm_ln2_w  = (const float*)d_in[4];
        vlm_q_w    = (const float*)d_in[5];  vlm_k_w    = (const float*)d_in[6];
        vlm_v_w    = (const float*)d_in[7];  vlm_o_w    = (const float*)d_in[8];
        vlm_gate_w = (const float*)d_in[9];  vlm_up_w   = (const float*)d_in[10];
        vlm_down_w = (const float*)d_in[11];
        exp_ln1_dw = (const float*)d_in[12]; exp_ln1_db = (const float*)d_in[13];
        exp_ln2_dw = (const float*)d_in[14]; exp_ln2_db = (const float*)d_in[15];
        exp_q_w    = (const float*)d_in[16]; exp_k_w    = (const float*)d_in[17];
        exp_v_w    = (const float*)d_in[18]; exp_o_w    = (const float*)d_in[19];
        exp_gate_w = (const float*)d_in[20]; exp_up_w   = (const float*)d_in[21];
        exp_down_w = (const float*)d_in[22];
        pos        = (const int*)  d_in[23];
        attn_mask  = (const float*)d_in[24];
    }

    __half *hv, *he, *q, *qt, *kv, *probs, *attnt, *attne, *mg, *eg, *wb;
    float *mod1, *mod2, *hv1, *he1;
    GETSYMH(hv, g_hv);   GETSYMH(he, g_he);   GETSYMF(mod1, g_mod1); GETSYMF(mod2, g_mod2);
    GETSYMH(q, g_q);     GETSYMH(qt, g_qt);   GETSYMH(kv, g_kv);
    GETSYMH(probs, g_probs);
    GETSYMH(attnt, g_attnt);   GETSYMH(attne, g_attne);
    GETSYMF(hv1, g_hv1); GETSYMF(he1, g_he1);
    GETSYMH(mg, g_mg);   GETSYMH(eg, g_eg);   GETSYMH(wb, g_wbuf);

    // wbuf layout: vq | round_many(5) | vkv | ekv | vug | eug
    const long long n_vq = (long long)W_V_ * H_ * DH_;
    const float* srcs[NW] = {vlm_o_w, vlm_down_w, exp_q_w, exp_o_w, exp_down_w};
    long long cnts[NW] = {
        (long long)H_*DH_*W_V_, (long long)MLPV_*W_V_,
        (long long)W_E_*H_*DH_, (long long)H_*DH_*W_E_, (long long)MLPE_*W_E_};
    RoundDesc rd;
    long long ofs = n_vq; int blk = 0;
    const __half* wptr[NW];
    for (int i = 0; i < NW; i++) {
        rd.src[i] = (const float4*)srcs[i];
        rd.dofs[i] = ofs;
        rd.blkStart[i] = blk;
        wptr[i] = wb + ofs;
        ofs += cnts[i];
        blk += (int)(cnts[i] / 4096);
    }
    rd.blkStart[NW] = blk;
    const __half* w_vq = wb;
    const __half *w_vo = wptr[0], *w_vd = wptr[1];
    const __half *w_eq = wptr[2], *w_eo = wptr[3], *w_ed = wptr[4];
    __half* w_vkv = wb + ofs;  ofs += (long long)W_V_ * 512;
    __half* w_ekv = wb + ofs;  ofs += (long long)W_E_ * 512;
    __half* w_vug = wb + ofs;  ofs += (long long)W_V_ * 2 * MLPV_;
    __half* w_eug = wb + ofs;  ofs += (long long)W_E_ * 2 * MLPE_;

    const int SMG  = 4 * STGB;
    const int SMT  = 4 * STG1;
    const int SM64 = 4 * STG64;
    cudaFuncSetAttribute(gemm16<4>, cudaFuncAttributeMaxDynamicSharedMemorySize, SMG);
    cudaFuncSetAttribute(gemm16<6>, cudaFuncAttributeMaxDynamicSharedMemorySize, SMG);
    cudaFuncSetAttribute(gemm16_tb1, cudaFuncAttributeMaxDynamicSharedMemorySize, SMT);
    cudaFuncSetAttribute((gemm16m64<0,0>), cudaFuncAttributeMaxDynamicSharedMemorySize, SM64);
    cudaFuncSetAttribute((gemm16m64<3,0>), cudaFuncAttributeMaxDynamicSharedMemorySize, SM64);
    cudaFuncSetAttribute((gemm16m64<3,1>), cudaFuncAttributeMaxDynamicSharedMemorySize, SM64);

    float* out_v = (float*)d_out;
    float* out_e = (float*)d_out + (long long)B_ * S_V_ * W_V_;

    long long sHv = (long long)S_V_ * W_V_, sHe = (long long)S_E_ * W_E_;
    long long sQ = (long long)S_ * H_ * DH_;
    long long sKV = (long long)S_ * 512;
    long long sL = (long long)S_ * S_;
    long long sQt = (long long)S_ * DH_;

    // stream plumbing (fallback: everything serial on stream 0)
    const bool mt = g_si.ok;
    cudaStream_t s2 = mt ? g_si.s2 : 0;
    if (mt) { cudaEventRecord(g_si.evF, 0); cudaStreamWaitEvent(s2, g_si.evF, 0); }

    // --- staging on s2 ---
    round4<<<(int)((n_vq / 4 + 255) / 256), 256, 0, s2>>>((const float4*)vlm_q_w, (__half2*)wb, (int)(n_vq / 4));
    if (mt) cudaEventRecord(g_si.evVQ, s2);
    concat_kv<<<(W_V_ * 64 + 255) / 256, 256, 0, s2>>>((const float4*)vlm_k_w, (const float4*)vlm_v_w, (__half2*)w_vkv, W_V_);
    concat_kv<<<(W_E_ * 64 + 255) / 256, 256, 0, s2>>>((const float4*)exp_k_w, (const float4*)exp_v_w, (__half2*)w_ekv, W_E_);
    if (mt) cudaEventRecord(g_si.evKV, s2);
    round_many<<<blk, 256, 0, s2>>>(rd, wb);
    if (mt) cudaEventRecord(g_si.evRM, s2);
    {
        long long n4v = (long long)W_V_ * MLPV_ / 4;
        interleave2<<<(int)((n4v + 1023) / 1024), 256, 0, s2>>>((const float4*)vlm_up_w, (const float4*)vlm_gate_w, (uint4*)w_vug, n4v);
        long long n4e = (long long)W_E_ * MLPE_ / 4;
        interleave2<<<(int)((n4e + 1023) / 1024), 256, 0, s2>>>((const float4*)exp_up_w, (const float4*)exp_gate_w, (uint4*)w_eug, n4e);
    }
    if (mt) cudaEventRecord(g_si.evIL, s2);

    // --- main stream ---
    rms_scale<<<B_ * S_V_, 256>>>(embeds_vlm, vlm_ln1_w, hv, W_V_);
    modmm2d<<<dim3(48, B_, 2), 256>>>(cond, exp_ln1_dw, exp_ln1_db, mod1,
                                      exp_ln2_dw, exp_ln2_db, mod2);
    rms_mod<<<B_ * S_E_, 256>>>(embeds_exp, mod1, he, W_E_, S_E_);

    if (mt) cudaStreamWaitEvent(0, g_si.evVQ, 0);
    gemm16m64<0,0><<<dim3(16, 12, B_), 128, SM64>>>(hv, w_vq, q, nullptr, S_V_, H_ * DH_, W_V_, sHv, 0, sQ, 1, H_ * DH_);

    if (mt) cudaStreamWaitEvent(0, g_si.evKV, 0);
    gemm16m64<0,0><<<dim3(4, 12, B_), 128, SM64>>>(hv, w_vkv, kv, nullptr, S_V_, 512, W_V_, sHv, 0, sKV, 1, 512);
    gemm16m64<0,0><<<dim3(4, 1, B_), 128, SM64>>>(he, w_ekv, kv + S_V_ * 512, nullptr, S_E_, 512, W_E_, sHe, 0, sKV, 1, 512);

    if (mt) cudaStreamWaitEvent(0, g_si.evRM, 0);
    gemm16m64<0,0><<<dim3(16, 1, B_), 128, SM64>>>(he, w_eq, q + (long long)S_V_ * H_ * DH_, nullptr, S_E_, H_ * DH_, W_E_, sHe, 0, sQ, 1, H_ * DH_);

    // RoPE
    rope4h_t<<<(B_ * S_ * H_ * 32 + 255) / 256, 256>>>(q, qt, pos);
    rope_k_kv<<<(B_ * S_ * 32 + 255) / 256, 256>>>(kv, pos);

    // attention
    {
        gemm16_tb1<<<dim3(7, 7, B_ * H_), 256, SMT>>>(qt, kv, probs, attn_mask, S_, S_, DH_, sQt, sKV, sL, H_, 512);
        softmax8h<<<B_ * H_ * S_, 128>>>(probs);
        gemm16m64<0,0><<<dim3(2, 13, B_ * H_), 128, SM64>>>(probs, kv + 256, attnt, nullptr, S_, DH_, S_, sL, sKV, sQt, H_, 512);
        exp_gather<<<(B_ * 64 * 256 + 255) / 256, 256>>>((const uint4*)attnt, (uint4*)attne);
    }

    // output projections + residuals
    gemm16m64<3,1><<<dim3(16, 12, B_), 128, SM64>>>(attnt, w_vo, hv1, embeds_vlm, S_V_, W_V_, H_ * DH_, 0, 0, sHv, 1, W_V_);
    gemm16<4><<<dim3(8, 1, B_), 256, SMG>>>(attne, w_eo, he1, embeds_exp, mod1, S_E_, W_E_, H_ * DH_, (long long)S_E_ * H_ * DH_, 0, sHe, 1);

    // pre-MLP norms
    rms_scale<<<B_ * S_V_, 256>>>(hv1, vlm_ln2_w, hv, W_V_);
    rms_mod<<<B_ * S_E_, 256>>>(he1, mod2, he, W_E_, S_E_);

    // MLPs (need interleaved weights)
    if (mt) cudaStreamWaitEvent(0, g_si.evIL, 0);
    {
        int M = B_ * S_V_;
        gemm16<6><<<dim3(256, 24, 1), 256, SMG>>>(hv, w_vug, mg, nullptr, nullptr, M, 2 * MLPV_, W_V_, 0, 0, 0, 1);
        gemm16m64<3,0><<<dim3(16, 48, 1), 128, SM64>>>(mg, w_vd, out_v, hv1, M, W_V_, MLPV_, 0, 0, 0, 1, W_V_);
    }
    {
        int M = B_ * S_E_;
        gemm16<6><<<dim3(64, 2, 1), 256, SMG>>>(he, w_eug, eg, nullptr, nullptr, M, 2 * MLPE_, W_E_, 0, 0, 0, 1);
        gemm16<4><<<dim3(8, 2, 1), 256, SMG>>>(eg, w_ed, out_e, he1, mod2, M, W_E_, MLPE_, 0, 0, 0, 1);
    }
}

// round 17
// speedup vs baseline: 1.3127x; 1.0609x over previous
#include <cuda_runtime.h>
#include <cuda_fp16.h>
#include <cuda_bf16.h>
#include <math.h>

#define B_    4
#define S_V_  768
#define S_E_  64
#define S_    832
#define W_V_  2048
#define W_E_  1024
#define H_    8
#define DH_   256
#define MLPV_ 16384
#define MLPE_ 4096
#define EPS_  1e-6f
#define SCALE_ 0.0625f

// ---------------- scratch ----------------
__device__ __half g_hv   [B_*S_V_*W_V_];
__device__ __half g_he   [B_*S_E_*W_E_];
__device__ float  g_mod1 [B_*3*W_E_];
__device__ float  g_mod2 [B_*3*W_E_];
__device__ __half g_q    [(long long)B_*S_*H_*DH_];
__device__ __half g_qt   [(long long)B_*H_*S_*DH_];
__device__ __half g_kv   [(long long)B_*S_*512];
__device__ __half g_probs[(long long)B_*H_*S_*S_];
__device__ __half g_attnt[(long long)B_*H_*S_*DH_];
__device__ __half g_attne[B_*S_E_*H_*DH_];
__device__ float  g_hv1  [B_*S_V_*W_V_];
__device__ float  g_he1  [B_*S_E_*W_E_];
__device__ __half g_mg   [(long long)B_*S_V_*MLPV_];
__device__ __half g_eg   [B_*S_E_*MLPE_];
__device__ __half g_wbuf [127401984];

// ---------------- static streams/events ----------------
struct GpuStreams {
    cudaStream_t s2 = 0;
    cudaEvent_t evF = 0, evVQ = 0, evKV = 0, evRM = 0, evIL = 0, evAtt = 0, evExp = 0;
    bool ok = false;
    GpuStreams() {
        if (cudaStreamCreateWithFlags(&s2, cudaStreamNonBlocking) != cudaSuccess) return;
        if (cudaEventCreateWithFlags(&evF,   cudaEventDisableTiming) != cudaSuccess) return;
        if (cudaEventCreateWithFlags(&evVQ,  cudaEventDisableTiming) != cudaSuccess) return;
        if (cudaEventCreateWithFlags(&evKV,  cudaEventDisableTiming) != cudaSuccess) return;
        if (cudaEventCreateWithFlags(&evRM,  cudaEventDisableTiming) != cudaSuccess) return;
        if (cudaEventCreateWithFlags(&evIL,  cudaEventDisableTiming) != cudaSuccess) return;
        if (cudaEventCreateWithFlags(&evAtt, cudaEventDisableTiming) != cudaSuccess) return;
        if (cudaEventCreateWithFlags(&evExp, cudaEventDisableTiming) != cudaSuccess) return;
        ok = true;
    }
};
static GpuStreams g_si;

__device__ __forceinline__ float gelu_t(float x) {
    return 0.5f * x * (1.f + tanhf(0.7978845608028654f * (x + 0.044715f * x * x * x)));
}

__device__ __forceinline__ void mma_f16(float* c, const unsigned* a, const unsigned* b) {
    asm volatile(
        "mma.sync.aligned.m16n8k16.row.col.f32.f16.f16.f32 "
        "{%0,%1,%2,%3}, {%4,%5,%6,%7}, {%8,%9}, {%0,%1,%2,%3};\n"
        : "+f"(c[0]), "+f"(c[1]), "+f"(c[2]), "+f"(c[3])
        : "r"(a[0]), "r"(a[1]), "r"(a[2]), "r"(a[3]), "r"(b[0]), "r"(b[1]));
}

// ============ gemm16: fp16 operands, fp32 accum, TB=0 ============
#define ASTB 10240
#define STGB 18944
template<int EPI>
__global__ __launch_bounds__(256, 2)
void gemm16(const __half* __restrict__ A, const __half* __restrict__ Bm,
            void* __restrict__ Cv, const float* __restrict__ aux,
            const float* __restrict__ modv,
            int M, int N, int K,
            long long sA, long long sB, long long sC, int bInner)
{
    extern __shared__ __align__(16) char sm[];

    const int z = blockIdx.z;
    A  += (long long)z * sA;
    Bm += (long long)(z / bInner) * sB;

    const int tid  = threadIdx.x;
    const int lane = tid & 31;
    const int wid  = tid >> 5;
    const int wm   = (wid & 1) * 64;
    const int wn   = (wid >> 1) * 32;
    const int bm   = blockIdx.y * 128;
    const int bn   = blockIdx.x * 128;
    const int row  = lane >> 2, col = lane & 3;

    unsigned sbase = (unsigned)__cvta_generic_to_shared(sm);

    auto issue = [&](int st) {
        const int ktE = st * 32;
        const unsigned sb = sbase + (unsigned)((st & 3) * STGB);
#pragma unroll
        for (int j = 0; j < 2; j++) {
            int id = tid + j * 256;
            int r = id >> 2, c = id & 3;
            int gm = bm + r;
            const __half* gp = A + (long long)(gm < M ? gm : M - 1) * K + ktE + c * 8;
            unsigned dst = sb + (unsigned)(r * 80 + c * 16);
            int zf = (gm < M) ? 16 : 0;
            asm volatile("cp.async.cg.shared.global [%0], [%1], 16, %2;\n"
                         :: "r"(dst), "l"(gp), "r"(zf));
        }
#pragma unroll
        for (int j = 0; j < 2; j++) {
            int id = tid + j * 256;
            int kr = id >> 4, c = id & 15;
            int gn = bn + c * 8;
            const __half* gp = Bm + (long long)(ktE + kr) * N + (gn < N ? gn : N - 8);
            unsigned dst = sb + (unsigned)(ASTB + kr * 272 + c * 16);
            int zf = (gn < N) ? 16 : 0;
            asm volatile("cp.async.cg.shared.global [%0], [%1], 16, %2;\n"
                         :: "r"(dst), "l"(gp), "r"(zf));
        }
    };

    float c[4][4][4];
#pragma unroll
    for (int i = 0; i < 4; i++)
#pragma unroll
        for (int j = 0; j < 4; j++)
#pragma unroll
            for (int l = 0; l < 4; l++) c[i][j][l] = 0.f;

    const unsigned aoff = (unsigned)((((lane >> 3) & 1) * 8 + (lane & 7)) * 80 + (lane >> 4) * 16);
    const unsigned boff4 = (unsigned)(ASTB + (((lane >> 3) & 1) * 8 + (lane & 7)) * 272
                                      + (lane >> 4) * 16 + wn * 2);

    const int nk = K / 32;
#pragma unroll 1
    for (int s = 0; s < 3; s++) { issue(s); asm volatile("cp.async.commit_group;\n"); }

#pragma unroll 1
    for (int kt = 0; kt < nk; kt++) {
        asm volatile("cp.async.wait_group 2;\n");
        __syncthreads();
        if (kt + 3 < nk) issue(kt + 3);
        asm volatile("cp.async.commit_group;\n");

        const unsigned stg = sbase + (unsigned)((kt & 3) * STGB);
#pragma unroll
        for (int sub = 0; sub < 2; sub++) {
            unsigned af[4][4], bf[4][2];
#pragma unroll
            for (int mt = 0; mt < 4; mt++) {
                unsigned ad = stg + (unsigned)((wm + mt * 16) * 80 + sub * 32) + aoff;
                asm volatile("ldmatrix.sync.aligned.m8n8.x4.shared.b16 {%0,%1,%2,%3}, [%4];"
                             : "=r"(af[mt][0]), "=r"(af[mt][1]), "=r"(af[mt][2]), "=r"(af[mt][3])
                             : "r"(ad));
            }
#pragma unroll
            for (int ntp = 0; ntp < 2; ntp++) {
                unsigned bd = stg + (unsigned)(sub * 16 * 272 + ntp * 32) + boff4;
                asm volatile("ldmatrix.sync.aligned.m8n8.x4.trans.shared.b16 {%0,%1,%2,%3}, [%4];"
                             : "=r"(bf[2*ntp][0]), "=r"(bf[2*ntp][1]),
                               "=r"(bf[2*ntp+1][0]), "=r"(bf[2*ntp+1][1])
                             : "r"(bd));
            }
#pragma unroll
            for (int mt = 0; mt < 4; mt++)
#pragma unroll
                for (int nt = 0; nt < 4; nt++)
                    mma_f16(c[mt][nt], af[mt], bf[nt]);
        }
    }

    if (EPI == 3 || EPI == 4) aux += (long long)z * sC;
    __half* Ch = (__half*)Cv + (long long)z * sC;
    float*  Cf = (float*)Cv + (long long)z * sC;

    auto epi_store = [&](int gm, int gn, float x0, float x1) {
        if (EPI == 6) {
            Ch[(long long)gm * (N >> 1) + (gn >> 1)] = __float2half_rn(gelu_t(x1) * x0);
            return;
        }
        long long o = (long long)gm * N + gn;
        if (EPI == 0) {
            *(__half2*)(Ch + o) = __halves2half2(__float2half_rn(x0), __float2half_rn(x1));
        } else if (EPI == 3) {
            float2 u = *(const float2*)(aux + o);
            *(float2*)(Cf + o) = make_float2(x0 + u.x, x1 + u.y);
        } else if (EPI == 4) {
            int bb = z + gm / S_E_;
            float g0 = modv[(long long)bb * 3 * W_E_ + 2 * W_E_ + gn];
            float g1 = modv[(long long)bb * 3 * W_E_ + 2 * W_E_ + gn + 1];
            float2 u = *(const float2*)(aux + o);
            *(float2*)(Cf + o) = make_float2(u.x + x0 * g0, u.y + x1 * g1);
        }
    };

#pragma unroll
    for (int mt = 0; mt < 4; mt++) {
#pragma unroll
        for (int nt = 0; nt < 4; nt++) {
            int gm = bm + wm + mt * 16 + row;
            int gn = bn + wn + nt * 8 + col * 2;
            if (gn < N) {
                if (gm < M)     epi_store(gm,     gn, c[mt][nt][0], c[mt][nt][1]);
                if (gm + 8 < M) epi_store(gm + 8, gn, c[mt][nt][2], c[mt][nt][3]);
            }
        }
    }
}

// ============ gemm16m64: 64x128 tile, 128 thr, 4 stages ====
#define A64B 5120
#define STG64 (A64B + 8704)
template<int EPI, int GA>
__global__ __launch_bounds__(128, 4)
void gemm16m64(const __half* __restrict__ A, const __half* __restrict__ Bm,
               void* __restrict__ Cv, const float* __restrict__ aux,
               int M, int N, int K, long long sA, long long sB, long long sC,
               int bInner, int ldb)
{
    extern __shared__ __align__(16) char sm[];

    const int z = blockIdx.z;
    if (!GA) A += (long long)z * sA;
    Bm += (long long)(z / bInner) * sB;

    const int tid  = threadIdx.x;
    const int lane = tid & 31;
    const int wid  = tid >> 5;
    const int wn   = wid * 32;
    const int bm   = blockIdx.y * 64;
    const int bn   = blockIdx.x * 128;
    const int row  = lane >> 2, col = lane & 3;

    unsigned sbase = (unsigned)__cvta_generic_to_shared(sm);

    auto issue = [&](int st) {
        const int ktE = st * 32;
        const unsigned sb = sbase + (unsigned)((st & 3) * STG64);
#pragma unroll
        for (int j = 0; j < 2; j++) {
            int id = tid + j * 128;
            int r = id >> 2, c = id & 3;
            int gm = bm + r;
            const __half* gp;
            if (GA) {
                int kc = ktE + c * 8;
                int gmc = gm < M ? gm : M - 1;
                gp = A + ((long long)(z * H_ + (kc >> 8)) * S_ + gmc) * 256 + (kc & 255);
            } else {
                gp = A + (long long)(gm < M ? gm : M - 1) * K + ktE + c * 8;
            }
            unsigned dst = sb + (unsigned)(r * 80 + c * 16);
            int zf = (gm < M) ? 16 : 0;
            asm volatile("cp.async.cg.shared.global [%0], [%1], 16, %2;\n"
                         :: "r"(dst), "l"(gp), "r"(zf));
        }
#pragma unroll
        for (int j = 0; j < 4; j++) {
            int id = tid + j * 128;
            int kr = id >> 4, c = id & 15;
            int gn = bn + c * 8;
            const __half* gp = Bm + (long long)(ktE + kr) * ldb + (gn < N ? gn : N - 8);
            unsigned dst = sb + (unsigned)(A64B + kr * 272 + c * 16);
            int zf = (gn < N) ? 16 : 0;
            asm volatile("cp.async.cg.shared.global [%0], [%1], 16, %2;\n"
                         :: "r"(dst), "l"(gp), "r"(zf));
        }
    };

    float c[4][4][4];
#pragma unroll
    for (int i = 0; i < 4; i++)
#pragma unroll
        for (int j = 0; j < 4; j++)
#pragma unroll
            for (int l = 0; l < 4; l++) c[i][j][l] = 0.f;

    const unsigned aoff = (unsigned)((((lane >> 3) & 1) * 8 + (lane & 7)) * 80 + (lane >> 4) * 16);
    const unsigned boff4 = (unsigned)(A64B + (((lane >> 3) & 1) * 8 + (lane & 7)) * 272
                                      + (lane >> 4) * 16 + wn * 2);

    const int nk = K / 32;
#pragma unroll 1
    for (int s = 0; s < 3; s++) { issue(s); asm volatile("cp.async.commit_group;\n"); }

#pragma unroll 1
    for (int kt = 0; kt < nk; kt++) {
        asm volatile("cp.async.wait_group 2;\n");
        __syncthreads();
        if (kt + 3 < nk) issue(kt + 3);
        asm volatile("cp.async.commit_group;\n");

        const unsigned stg = sbase + (unsigned)((kt & 3) * STG64);
#pragma unroll
        for (int sub = 0; sub < 2; sub++) {
            unsigned af[4][4], bf[4][2];
#pragma unroll
            for (int mt = 0; mt < 4; mt++) {
                unsigned ad = stg + (unsigned)((mt * 16) * 80 + sub * 32) + aoff;
                asm volatile("ldmatrix.sync.aligned.m8n8.x4.shared.b16 {%0,%1,%2,%3}, [%4];"
                             : "=r"(af[mt][0]), "=r"(af[mt][1]), "=r"(af[mt][2]), "=r"(af[mt][3])
                             : "r"(ad));
            }
#pragma unroll
            for (int ntp = 0; ntp < 2; ntp++) {
                unsigned bd = stg + (unsigned)(sub * 16 * 272 + ntp * 32) + boff4;
                asm volatile("ldmatrix.sync.aligned.m8n8.x4.trans.shared.b16 {%0,%1,%2,%3}, [%4];"
                             : "=r"(bf[2*ntp][0]), "=r"(bf[2*ntp][1]),
                               "=r"(bf[2*ntp+1][0]), "=r"(bf[2*ntp+1][1])
                             : "r"(bd));
            }
#pragma unroll
            for (int mt = 0; mt < 4; mt++)
#pragma unroll
                for (int nt = 0; nt < 4; nt++)
                    mma_f16(c[mt][nt], af[mt], bf[nt]);
        }
    }

    if (EPI == 3) aux += (long long)z * sC;
    __half* Ch = (__half*)Cv + (long long)z * sC;
    float*  Cf = (float*)Cv + (long long)z * sC;

#pragma unroll
    for (int mt = 0; mt < 4; mt++) {
#pragma unroll
        for (int nt = 0; nt < 4; nt++) {
            int gm = bm + mt * 16 + row;
            int gn = bn + wn + nt * 8 + col * 2;
            if (gn >= N) continue;
#pragma unroll
            for (int hh = 0; hh < 2; hh++) {
                int g = gm + hh * 8;
                if (g >= M) continue;
                long long o = (long long)g * N + gn;
                float x0 = c[mt][nt][hh * 2], x1 = c[mt][nt][hh * 2 + 1];
                if (EPI == 0) {
                    *(__half2*)(Ch + o) = __halves2half2(__float2half_rn(x0), __float2half_rn(x1));
                } else {
                    float2 u = *(const float2*)(aux + o);
                    *(float2*)(Cf + o) = make_float2(x0 + u.x, x1 + u.y);
                }
            }
        }
    }
}

// ============ gemm16_tb1: QK^T, fused scale+mask -> fp16 probs, ldb B stride ============
#define STG1 20480
__global__ __launch_bounds__(256, 2)
void gemm16_tb1(const __half* __restrict__ A, const __half* __restrict__ Bm,
                __half* __restrict__ C, const float* __restrict__ mask,
                int M, int N, int K,
                long long sA, long long sB, long long sC, int bInner, int ldb)
{
    extern __shared__ __align__(16) char sm[];

    const int z = blockIdx.z;
    A  += (long long)z * sA;
    Bm += (long long)(z / bInner) * sB;
    C  += (long long)z * sC;
    const float* mrow = mask + (long long)(z >> 3) * S_ * S_;

    const int tid  = threadIdx.x;
    const int lane = tid & 31;
    const int wid  = tid >> 5;
    const int wm   = (wid & 1) * 64;
    const int wn   = (wid >> 1) * 32;
    const int bm   = blockIdx.y * 128;
    const int bn   = blockIdx.x * 128;
    const int row  = lane >> 2, col = lane & 3;

    unsigned sbase = (unsigned)__cvta_generic_to_shared(sm);

    auto issue = [&](int st) {
        const int ktE = st * 32;
        const unsigned sb = sbase + (unsigned)((st & 3) * STG1);
#pragma unroll
        for (int j = 0; j < 2; j++) {
            int id = tid + j * 256;
            int r = id >> 2, c = id & 3;
            int gm = bm + r;
            const __half* gp = A + (long long)(gm < M ? gm : M - 1) * K + ktE + c * 8;
            unsigned dst = sb + (unsigned)(r * 80 + c * 16);
            int zf = (gm < M) ? 16 : 0;
            asm volatile("cp.async.cg.shared.global [%0], [%1], 16, %2;\n"
                         :: "r"(dst), "l"(gp), "r"(zf));
        }
#pragma unroll
        for (int j = 0; j < 2; j++) {
            int id = tid + j * 256;
            int r = id >> 2, c = id & 3;
            int gn = bn + r;
            const __half* gp = Bm + (long long)(gn < N ? gn : N - 1) * ldb + ktE + c * 8;
            unsigned dst = sb + (unsigned)(ASTB + r * 80 + c * 16);
            int zf = (gn < N) ? 16 : 0;
            asm volatile("cp.async.cg.shared.global [%0], [%1], 16, %2;\n"
                         :: "r"(dst), "l"(gp), "r"(zf));
        }
    };

    float c[4][4][4];
#pragma unroll
    for (int i = 0; i < 4; i++)
#pragma unroll
        for (int j = 0; j < 4; j++)
#pragma unroll
            for (int l = 0; l < 4; l++) c[i][j][l] = 0.f;

    const unsigned aoff = (unsigned)((((lane >> 3) & 1) * 8 + (lane & 7)) * 80 + (lane >> 4) * 16);
    const unsigned boff4 = (unsigned)(ASTB + ((lane & 7) + (lane >> 4) * 8 + wn) * 80
                                      + (((lane >> 3) & 1) * 16));

    const int nk = K / 32;
#pragma unroll 1
    for (int s = 0; s < 3; s++) { issue(s); asm volatile("cp.async.commit_group;\n"); }

#pragma unroll 1
    for (int kt = 0; kt < nk; kt++) {
        asm volatile("cp.async.wait_group 2;\n");
        __syncthreads();
        if (kt + 3 < nk) issue(kt + 3);
        asm volatile("cp.async.commit_group;\n");

        const unsigned stg = sbase + (unsigned)((kt & 3) * STG1);
#pragma unroll
        for (int sub = 0; sub < 2; sub++) {
            unsigned af[4][4], bf[4][2];
#pragma unroll
            for (int mt = 0; mt < 4; mt++) {
                unsigned ad = stg + (unsigned)((wm + mt * 16) * 80 + sub * 32) + aoff;
                asm volatile("ldmatrix.sync.aligned.m8n8.x4.shared.b16 {%0,%1,%2,%3}, [%4];"
                             : "=r"(af[mt][0]), "=r"(af[mt][1]), "=r"(af[mt][2]), "=r"(af[mt][3])
                             : "r"(ad));
            }
#pragma unroll
            for (int ntp = 0; ntp < 2; ntp++) {
                unsigned bd = stg + (unsigned)(ntp * 16 * 80 + sub * 32) + boff4;
                asm volatile("ldmatrix.sync.aligned.m8n8.x4.shared.b16 {%0,%1,%2,%3}, [%4];"
                             : "=r"(bf[2*ntp][0]), "=r"(bf[2*ntp][1]),
                               "=r"(bf[2*ntp+1][0]), "=r"(bf[2*ntp+1][1])
                             : "r"(bd));
            }
#pragma unroll
            for (int mt = 0; mt < 4; mt++)
#pragma unroll
                for (int nt = 0; nt < 4; nt++)
                    mma_f16(c[mt][nt], af[mt], bf[nt]);
        }
    }

#pragma unroll
    for (int mt = 0; mt < 4; mt++) {
#pragma unroll
        for (int nt = 0; nt < 4; nt++) {
            int gm = bm + wm + mt * 16 + row;
            int gn = bn + wn + nt * 8 + col * 2;
            if (gn >= N) continue;
#pragma unroll
            for (int hh = 0; hh < 2; hh++) {
                int g = gm + hh * 8;
                if (g >= M) continue;
                float2 mv = *(const float2*)(mrow + (long long)g * S_ + gn);
                float x0 = c[mt][nt][hh * 2] * SCALE_ + mv.x;
                float x1 = c[mt][nt][hh * 2 + 1] * SCALE_ + mv.y;
                *(__half2*)(C + (long long)g * N + gn) = __floats2half2_rn(x0, x1);
            }
        }
    }
}

// ---------------- weight staging ----------------
__global__ void round4(const float4* __restrict__ s, __half2* __restrict__ d, int n4)
{
    int i = blockIdx.x * 256 + threadIdx.x;
    if (i >= n4) return;
    float4 v = s[i];
    d[i * 2]     = __floats2half2_rn(v.x, v.y);
    d[i * 2 + 1] = __floats2half2_rn(v.z, v.w);
}

#define NW 5
struct RoundDesc {
    const float4* src[NW];
    long long dofs[NW];
    int blkStart[NW + 1];
};

__global__ void round_many(RoundDesc d, __half* __restrict__ wbuf)
{
    int b = blockIdx.x;
    int w = 0;
#pragma unroll
    for (int i = 0; i < NW; i++) if (b >= d.blkStart[i + 1]) w = i + 1;
    int lb = b - d.blkStart[w];
    const float4* s = d.src[w] + (long long)lb * 1024;
    __half2* o = (__half2*)(wbuf + d.dofs[w]) + (long long)lb * 2048;
    int t = threadIdx.x;
#pragma unroll
    for (int i = 0; i < 4; i++) {
        float4 v = s[t + i * 256];
        o[(t + i * 256) * 2]     = __floats2half2_rn(v.x, v.y);
        o[(t + i * 256) * 2 + 1] = __floats2half2_rn(v.z, v.w);
    }
}

__global__ void interleave2(const float4* __restrict__ up, const float4* __restrict__ gate,
                            uint4* __restrict__ out, long long n4)
{
    long long i0 = (long long)blockIdx.x * 1024 + threadIdx.x;
#pragma unroll
    for (int j = 0; j < 4; j++) {
        long long i = i0 + j * 256;
        if (i >= n4) return;
        float4 u = up[i], g = gate[i];
        __half2 h0 = __floats2half2_rn(u.x, g.x);
        __half2 h1 = __floats2half2_rn(u.y, g.y);
        __half2 h2 = __floats2half2_rn(u.z, g.z);
        __half2 h3 = __floats2half2_rn(u.w, g.w);
        uint4 o;
        o.x = *(unsigned*)&h0; o.y = *(unsigned*)&h1;
        o.z = *(unsigned*)&h2; o.w = *(unsigned*)&h3;
        out[i] = o;
    }
}

__global__ void concat_kv(const float4* __restrict__ Wk, const float4* __restrict__ Wv,
                          __half2* __restrict__ dst, int R)
{
    int i = blockIdx.x * 256 + threadIdx.x;
    int total = R * 64;
    if (i >= total) return;
    int r = i >> 6, c4 = i & 63;
    float4 a = Wk[i], b = Wv[i];
    __half2* dk = dst + (r * 512 + c4 * 4) / 2;
    dk[0] = __floats2half2_rn(a.x, a.y);
    dk[1] = __floats2half2_rn(a.z, a.w);
    __half2* dv = dst + (r * 512 + 256 + c4 * 4) / 2;
    dv[0] = __floats2half2_rn(b.x, b.y);
    dv[1] = __floats2half2_rn(b.z, b.w);
}

__global__ void exp_gather(const uint4* __restrict__ in, uint4* __restrict__ out)
{
    int idx = blockIdx.x * 256 + threadIdx.x;
    int total = B_ * 64 * 256;
    if (idx >= total) return;
    int d8 = idx & 31;
    int h = (idx >> 5) & 7;
    int j = (idx >> 8) & 63;
    int b = idx >> 14;
    out[((b * 64 + j) * 2048 + h * 256 + d8 * 8) >> 3] =
        in[(((long long)(b * H_ + h) * S_ + S_V_ + j) * 256 + d8 * 8) >> 3];
}

// ---------------- row kernels ----------------
__device__ __forceinline__ float blockReduceSum(float v) {
    __shared__ float red[256];
    int t = threadIdx.x;
    red[t] = v; __syncthreads();
    for (int s = 128; s > 0; s >>= 1) {
        if (t < s) red[t] += red[t + s];
        __syncthreads();
    }
    float r = red[0];
    __syncthreads();
    return r;
}

__global__ void rms_scale(const float* __restrict__ x, const float* __restrict__ w,
                          __half* __restrict__ out, int W)
{
    long long base = (long long)blockIdx.x * W;
    float ss = 0.f;
    for (int c = threadIdx.x; c < W; c += 256) { float t = x[base + c]; ss += t * t; }
    float tot = blockReduceSum(ss);
    float inv = rsqrtf(tot / (float)W + EPS_);
    for (int c = threadIdx.x; c < W; c += 256)
        out[base + c] = __float2half_rn(x[base + c] * inv * (1.f + w[c]));
}

__global__ void rms_mod(const float* __restrict__ x, const float* __restrict__ mod,
                        __half* __restrict__ out, int W, int rowsPerB)
{
    long long base = (long long)blockIdx.x * W;
    int b = blockIdx.x / rowsPerB;
    const float* m = mod + (long long)b * 3 * W;
    float ss = 0.f;
    for (int c = threadIdx.x; c < W; c += 256) { float t = x[base + c]; ss += t * t; }
    float tot = blockReduceSum(ss);
    float inv = rsqrtf(tot / (float)W + EPS_);
    for (int c = threadIdx.x; c < W; c += 256)
        out[base + c] = __float2half_rn(x[base + c] * inv * (1.f + m[c]) + m[W + c]);
}

__global__ void modmm2d(const float* __restrict__ cond,
                        const float* __restrict__ W1, const float* __restrict__ b1, float* __restrict__ o1,
                        const float* __restrict__ W2, const float* __restrict__ b2, float* __restrict__ o2)
{
    const int NT = 3 * W_E_;
    const float* W = blockIdx.z ? W2 : W1;
    const float* bias = blockIdx.z ? b2 : b1;
    float* out = blockIdx.z ? o2 : o1;
    __shared__ float cs[W_E_];
    __shared__ float part[4][64];
    int bb = blockIdx.y;
    int tid = threadIdx.x;
    for (int i = tid; i < W_E_; i += 256) cs[i] = cond[bb * W_E_ + i];
    __syncthreads();
    int tx = tid & 63, ty = tid >> 6;
    int c = blockIdx.x * 64 + tx;
    const float* Wp = W + (long long)(ty * 256) * NT + c;
    const float* cp = cs + ty * 256;
    float s = 0.f;
#pragma unroll 4
    for (int k = 0; k < 256; k++) s += cp[k] * Wp[(long long)k * NT];
    part[ty][tx] = s;
    __syncthreads();
    if (ty == 0)
        out[(long long)bb * NT + c] = part[0][tx] + part[1][tx] + part[2][tx] + part[3][tx] + bias[c];
}

__global__ void rope_k_kv(__half* __restrict__ kv, const int* __restrict__ pos)
{
    int idx = blockIdx.x * blockDim.x + threadIdx.x;
    int total = B_ * S_ * 32;
    if (idx >= total) return;
    int d4 = (idx & 31) << 2;
    int s = (idx >> 5) % S_;
    int b = idx / (32 * S_);
    float p = (float)pos[b * S_ + s];
    __half* base = kv + (long long)(b * S_ + s) * 512;
    __half2 x1a = *(__half2*)(base + d4),       x1b = *(__half2*)(base + d4 + 2);
    __half2 x2a = *(__half2*)(base + d4 + 128), x2b = *(__half2*)(base + d4 + 130);
    float r1[4] = {__low2float(x1a), __high2float(x1a), __low2float(x1b), __high2float(x1b)};
    float r2[4] = {__low2float(x2a), __high2float(x2a), __low2float(x2b), __high2float(x2b)};
#pragma unroll
    for (int j = 0; j < 4; j++) {
        float ang = p * powf(10000.f, -(float)(2 * (d4 + j)) / 256.f);
        float sn, cs2; sincosf(ang, &sn, &cs2);
        float a = r1[j], bb = r2[j];
        r1[j] = a * cs2 - bb * sn;
        r2[j] = bb * cs2 + a * sn;
    }
    *(__half2*)(base + d4)       = __floats2half2_rn(r1[0], r1[1]);
    *(__half2*)(base + d4 + 2)   = __floats2half2_rn(r1[2], r1[3]);
    *(__half2*)(base + d4 + 128) = __floats2half2_rn(r2[0], r2[1]);
    *(__half2*)(base + d4 + 130) = __floats2half2_rn(r2[2], r2[3]);
}

__global__ void rope4h_t(const __half* __restrict__ q, __half* __restrict__ qt,
                         const int* __restrict__ pos)
{
    int idx = blockIdx.x * blockDim.x + threadIdx.x;
    int total = B_ * S_ * H_ * 32;
    if (idx >= total) return;
    int d4 = (idx & 31) << 2;
    int h = (idx >> 5) % H_;
    int s = (idx / (32 * H_)) % S_;
    int b = idx / (32 * H_ * S_);
    float p = (float)pos[b * S_ + s];
    const __half* src = q + (((long long)(b * S_ + s) * H_ + h) << 8);
    __half* dst = qt + (((long long)(b * H_ + h) * S_ + s) << 8);
    __half2 x1a = *(const __half2*)(src + d4),       x1b = *(const __half2*)(src + d4 + 2);
    __half2 x2a = *(const __half2*)(src + d4 + 128), x2b = *(const __half2*)(src + d4 + 130);
    float r1[4] = {__low2float(x1a), __high2float(x1a), __low2float(x1b), __high2float(x1b)};
    float r2[4] = {__low2float(x2a), __high2float(x2a), __low2float(x2b), __high2float(x2b)};
#pragma unroll
    for (int j = 0; j < 4; j++) {
        float ang = p * powf(10000.f, -(float)(2 * (d4 + j)) / 256.f);
        float sn, cs2; sincosf(ang, &sn, &cs2);
        float a = r1[j], bb = r2[j];
        r1[j] = a * cs2 - bb * sn;
        r2[j] = bb * cs2 + a * sn;
    }
    *(__half2*)(dst + d4)       = __floats2half2_rn(r1[0], r1[1]);
    *(__half2*)(dst + d4 + 2)   = __floats2half2_rn(r1[2], r1[3]);
    *(__half2*)(dst + d4 + 128) = __floats2half2_rn(r2[0], r2[1]);
    *(__half2*)(dst + d4 + 130) = __floats2half2_rn(r2[2], r2[3]);
}

__global__ __launch_bounds__(128)
void softmax8h(__half* __restrict__ probs)
{
    long long rowid = blockIdx.x;
    __half* row = probs + rowid * S_;
    int t = threadIdx.x;
    const bool act = t < 104;
    float v[8];
    if (act) {
        uint4 raw = *(const uint4*)(row + t * 8);
        const __half2* hp = (const __half2*)&raw;
#pragma unroll
        for (int j = 0; j < 4; j++) {
            v[2 * j]     = __low2float(hp[j]);
            v[2 * j + 1] = __high2float(hp[j]);
        }
    } else {
#pragma unroll
        for (int j = 0; j < 8; j++) v[j] = -1e30f;
    }
    float mx = v[0];
#pragma unroll
    for (int j = 1; j < 8; j++) mx = fmaxf(mx, v[j]);
    __shared__ float red[128];
    red[t] = mx; __syncthreads();
    for (int s = 64; s > 0; s >>= 1) { if (t < s) red[t] = fmaxf(red[t], red[t + s]); __syncthreads(); }
    mx = red[0]; __syncthreads();
    float sum = 0.f;
    if (act) {
#pragma unroll
        for (int j = 0; j < 8; j++) { v[j] = __expf(v[j] - mx); sum += v[j]; }
    }
    red[t] = sum; __syncthreads();
    for (int s = 64; s > 0; s >>= 1) { if (t < s) red[t] += red[t + s]; __syncthreads(); }
    float inv = 1.f / red[0];
    if (act) {
        uint4 out;
        __half2* op = (__half2*)&out;
#pragma unroll
        for (int j = 0; j < 4; j++)
            op[j] = __floats2half2_rn(v[2 * j] * inv, v[2 * j + 1] * inv);
        *(uint4*)(row + t * 8) = out;
    }
}

// ---------------- host launch ----------------
#define GETSYMF(var, sym) do { void* p__; cudaGetSymbolAddress(&p__, sym); var = (float*)p__; } while (0)
#define GETSYMH(var, sym) do { void* p__; cudaGetSymbolAddress(&p__, sym); var = (__half*)p__; } while (0)

extern "C" void kernel_launch(void* const* d_in, const int* in_sizes, int n_in,
                              void* d_out, int out_size)
{
    const float *embeds_vlm, *embeds_exp, *cond, *attn_mask;
    const int* pos;
    const float *vlm_ln1_w, *vlm_ln2_w, *vlm_q_w, *vlm_k_w, *vlm_v_w, *vlm_o_w;
    const float *vlm_gate_w, *vlm_up_w, *vlm_down_w;
    const float *exp_ln1_dw, *exp_ln1_db, *exp_ln2_dw, *exp_ln2_db;
    const float *exp_q_w, *exp_k_w, *exp_v_w, *exp_o_w, *exp_gate_w, *exp_up_w, *exp_down_w;

    if (in_sizes[3] == B_ * S_) {
        embeds_vlm = (const float*)d_in[0];  embeds_exp = (const float*)d_in[1];
        cond       = (const float*)d_in[2];  pos        = (const int*)  d_in[3];
        attn_mask  = (const float*)d_in[4];
        vlm_ln1_w  = (const float*)d_in[5];  vlm_ln2_w  = (const float*)d_in[6];
        vlm_q_w    = (const float*)d_in[7];  vlm_k_w    = (const float*)d_in[8];
        vlm_v_w    = (const float*)d_in[9];  vlm_o_w    = (const float*)d_in[10];
        vlm_gate_w = (const float*)d_in[11]; vlm_up_w   = (const float*)d_in[12];
        vlm_down_w = (const float*)d_in[13];
        exp_ln1_dw = (const float*)d_in[14]; exp_ln1_db = (const float*)d_in[15];
        exp_ln2_dw = (const float*)d_in[16]; exp_ln2_db = (const float*)d_in[17];
        exp_q_w    = (const float*)d_in[18]; exp_k_w    = (const float*)d_in[19];
        exp_v_w    = (const float*)d_in[20]; exp_o_w    = (const float*)d_in[21];
        exp_gate_w = (const float*)d_in[22]; exp_up_w   = (const float*)d_in[23];
        exp_down_w = (const float*)d_in[24];
    } else {
        embeds_vlm = (const float*)d_in[0];  embeds_exp = (const float*)d_in[1];
        cond       = (const float*)d_in[2];
        vlm_ln1_w  = (const float*)d_in[3];  vlm_ln2_w  = (const float*)d_in[4];
        vlm_q_w    = (const float*)d_in[5];  vlm_k_w    = (const float*)d_in[6];
        vlm_v_w    = (const float*)d_in[7];  vlm_o_w    = (const float*)d_in[8];
        vlm_gate_w = (const float*)d_in[9];  vlm_up_w   = (const float*)d_in[10];
        vlm_down_w = (const float*)d_in[11];
        exp_ln1_dw = (const float*)d_in[12]; exp_ln1_db = (const float*)d_in[13];
        exp_ln2_dw = (const float*)d_in[14]; exp_ln2_db = (const float*)d_in[15];
        exp_q_w    = (const float*)d_in[16]; exp_k_w    = (const float*)d_in[17];
        exp_v_w    = (const float*)d_in[18]; exp_o_w    = (const float*)d_in[19];
        exp_gate_w = (const float*)d_in[20]; exp_up_w   = (const float*)d_in[21];
        exp_down_w = (const float*)d_in[22];
        pos        = (const int*)  d_in[23];
        attn_mask  = (const float*)d_in[24];
    }

    __half *hv, *he, *q, *qt, *kv, *probs, *attnt, *attne, *mg, *eg, *wb;
    float *mod1, *mod2, *hv1, *he1;
    GETSYMH(hv, g_hv);   GETSYMH(he, g_he);   GETSYMF(mod1, g_mod1); GETSYMF(mod2, g_mod2);
    GETSYMH(q, g_q);     GETSYMH(qt, g_qt);   GETSYMH(kv, g_kv);
    GETSYMH(probs, g_probs);
    GETSYMH(attnt, g_attnt);   GETSYMH(attne, g_attne);
    GETSYMF(hv1, g_hv1); GETSYMF(he1, g_he1);
    GETSYMH(mg, g_mg);   GETSYMH(eg, g_eg);   GETSYMH(wb, g_wbuf);

    // wbuf layout: vq | round_many(5) | vkv | ekv | vug | eug
    const long long n_vq = (long long)W_V_ * H_ * DH_;
    const float* srcs[NW] = {vlm_o_w, vlm_down_w, exp_q_w, exp_o_w, exp_down_w};
    long long cnts[NW] = {
        (long long)H_*DH_*W_V_, (long long)MLPV_*W_V_,
        (long long)W_E_*H_*DH_, (long long)H_*DH_*W_E_, (long long)MLPE_*W_E_};
    RoundDesc rd;
    long long ofs = n_vq; int blk = 0;
    const __half* wptr[NW];
    for (int i = 0; i < NW; i++) {
        rd.src[i] = (const float4*)srcs[i];
        rd.dofs[i] = ofs;
        rd.blkStart[i] = blk;
        wptr[i] = wb + ofs;
        ofs += cnts[i];
        blk += (int)(cnts[i] / 4096);
    }
    rd.blkStart[NW] = blk;
    const __half* w_vq = wb;
    const __half *w_vo = wptr[0], *w_vd = wptr[1];
    const __half *w_eq = wptr[2], *w_eo = wptr[3], *w_ed = wptr[4];
    __half* w_vkv = wb + ofs;  ofs += (long long)W_V_ * 512;
    __half* w_ekv = wb + ofs;  ofs += (long long)W_E_ * 512;
    __half* w_vug = wb + ofs;  ofs += (long long)W_V_ * 2 * MLPV_;
    __half* w_eug = wb + ofs;  ofs += (long long)W_E_ * 2 * MLPE_;

    const int SMG  = 4 * STGB;
    const int SMT  = 4 * STG1;
    const int SM64 = 4 * STG64;
    cudaFuncSetAttribute(gemm16<4>, cudaFuncAttributeMaxDynamicSharedMemorySize, SMG);
    cudaFuncSetAttribute(gemm16<6>, cudaFuncAttributeMaxDynamicSharedMemorySize, SMG);
    cudaFuncSetAttribute(gemm16_tb1, cudaFuncAttributeMaxDynamicSharedMemorySize, SMT);
    cudaFuncSetAttribute((gemm16m64<0,0>), cudaFuncAttributeMaxDynamicSharedMemorySize, SM64);
    cudaFuncSetAttribute((gemm16m64<3,0>), cudaFuncAttributeMaxDynamicSharedMemorySize, SM64);
    cudaFuncSetAttribute((gemm16m64<3,1>), cudaFuncAttributeMaxDynamicSharedMemorySize, SM64);

    float* out_v = (float*)d_out;
    float* out_e = (float*)d_out + (long long)B_ * S_V_ * W_V_;

    long long sHv = (long long)S_V_ * W_V_, sHe = (long long)S_E_ * W_E_;
    long long sQ = (long long)S_ * H_ * DH_;
    long long sKV = (long long)S_ * 512;
    long long sL = (long long)S_ * S_;
    long long sQt = (long long)S_ * DH_;

    const bool mt = g_si.ok;
    cudaStream_t s2 = mt ? g_si.s2 : 0;
    if (mt) { cudaEventRecord(g_si.evF, 0); cudaStreamWaitEvent(s2, g_si.evF, 0); }

    // --- staging on s2 ---
    round4<<<(int)((n_vq / 4 + 255) / 256), 256, 0, s2>>>((const float4*)vlm_q_w, (__half2*)wb, (int)(n_vq / 4));
    if (mt) cudaEventRecord(g_si.evVQ, s2);
    concat_kv<<<(W_V_ * 64 + 255) / 256, 256, 0, s2>>>((const float4*)vlm_k_w, (const float4*)vlm_v_w, (__half2*)w_vkv, W_V_);
    concat_kv<<<(W_E_ * 64 + 255) / 256, 256, 0, s2>>>((const float4*)exp_k_w, (const float4*)exp_v_w, (__half2*)w_ekv, W_E_);
    if (mt) cudaEventRecord(g_si.evKV, s2);
    round_many<<<blk, 256, 0, s2>>>(rd, wb);
    if (mt) cudaEventRecord(g_si.evRM, s2);
    {
        long long n4v = (long long)W_V_ * MLPV_ / 4;
        interleave2<<<(int)((n4v + 1023) / 1024), 256, 0, s2>>>((const float4*)vlm_up_w, (const float4*)vlm_gate_w, (uint4*)w_vug, n4v);
        long long n4e = (long long)W_E_ * MLPE_ / 4;
        interleave2<<<(int)((n4e + 1023) / 1024), 256, 0, s2>>>((const float4*)exp_up_w, (const float4*)exp_gate_w, (uint4*)w_eug, n4e);
    }
    if (mt) cudaEventRecord(g_si.evIL, s2);

    // --- main stream: pre-attention ---
    rms_scale<<<B_ * S_V_, 256>>>(embeds_vlm, vlm_ln1_w, hv, W_V_);
    modmm2d<<<dim3(48, B_, 2), 256>>>(cond, exp_ln1_dw, exp_ln1_db, mod1,
                                      exp_ln2_dw, exp_ln2_db, mod2);
    rms_mod<<<B_ * S_E_, 256>>>(embeds_exp, mod1, he, W_E_, S_E_);

    if (mt) cudaStreamWaitEvent(0, g_si.evVQ, 0);
    gemm16m64<0,0><<<dim3(16, 12, B_), 128, SM64>>>(hv, w_vq, q, nullptr, S_V_, H_ * DH_, W_V_, sHv, 0, sQ, 1, H_ * DH_);

    if (mt) cudaStreamWaitEvent(0, g_si.evKV, 0);
    gemm16m64<0,0><<<dim3(4, 12, B_), 128, SM64>>>(hv, w_vkv, kv, nullptr, S_V_, 512, W_V_, sHv, 0, sKV, 1, 512);
    gemm16m64<0,0><<<dim3(4, 1, B_), 128, SM64>>>(he, w_ekv, kv + S_V_ * 512, nullptr, S_E_, 512, W_E_, sHe, 0, sKV, 1, 512);

    if (mt) cudaStreamWaitEvent(0, g_si.evRM, 0);
    gemm16m64<0,0><<<dim3(16, 1, B_), 128, SM64>>>(he, w_eq, q + (long long)S_V_ * H_ * DH_, nullptr, S_E_, H_ * DH_, W_E_, sHe, 0, sQ, 1, H_ * DH_);

    // RoPE
    rope4h_t<<<(B_ * S_ * H_ * 32 + 255) / 256, 256>>>(q, qt, pos);
    rope_k_kv<<<(B_ * S_ * 32 + 255) / 256, 256>>>(kv, pos);

    // attention
    gemm16_tb1<<<dim3(7, 7, B_ * H_), 256, SMT>>>(qt, kv, probs, attn_mask, S_, S_, DH_, sQt, sKV, sL, H_, 512);
    softmax8h<<<B_ * H_ * S_, 128>>>(probs);
    gemm16m64<0,0><<<dim3(2, 13, B_ * H_), 128, SM64>>>(probs, kv + 256, attnt, nullptr, S_, DH_, S_, sL, sKV, sQt, H_, 512);
    if (mt) cudaEventRecord(g_si.evAtt, 0);

    // --- expert branch on s2 (tiny kernels; fill VLM tail waves) ---
    if (mt) cudaStreamWaitEvent(s2, g_si.evAtt, 0);
    exp_gather<<<(B_ * 64 * 256 + 255) / 256, 256, 0, s2>>>((const uint4*)attnt, (uint4*)attne);
    gemm16<4><<<dim3(8, 1, B_), 256, SMG, s2>>>(attne, w_eo, he1, embeds_exp, mod1, S_E_, W_E_, H_ * DH_, (long long)S_E_ * H_ * DH_, 0, sHe, 1);
    rms_mod<<<B_ * S_E_, 256, 0, s2>>>(he1, mod2, he, W_E_, S_E_);
    {
        int M = B_ * S_E_;
        gemm16<6><<<dim3(64, 2, 1), 256, SMG, s2>>>(he, w_eug, eg, nullptr, nullptr, M, 2 * MLPE_, W_E_, 0, 0, 0, 1);
        gemm16<4><<<dim3(8, 2, 1), 256, SMG, s2>>>(eg, w_ed, out_e, he1, mod2, M, W_E_, MLPE_, 0, 0, 0, 1);
    }
    if (mt) cudaEventRecord(g_si.evExp, s2);

    // --- VLM branch on main ---
    gemm16m64<3,1><<<dim3(16, 12, B_), 128, SM64>>>(attnt, w_vo, hv1, embeds_vlm, S_V_, W_V_, H_ * DH_, 0, 0, sHv, 1, W_V_);
    rms_scale<<<B_ * S_V_, 256>>>(hv1, vlm_ln2_w, hv, W_V_);
    if (mt) cudaStreamWaitEvent(0, g_si.evIL, 0);
    {
        int M = B_ * S_V_;
        gemm16<6><<<dim3(256, 24, 1), 256, SMG>>>(hv, w_vug, mg, nullptr, nullptr, M, 2 * MLPV_, W_V_, 0, 0, 0, 1);
        gemm16m64<3,0><<<dim3(16, 48, 1), 128, SM64>>>(mg, w_vd, out_v, hv1, M, W_V_, MLPV_, 0, 0, 0, 1, W_V_);
    }

    // join expert branch before graph end
    if (mt) cudaStreamWaitEvent(0, g_si.evExp, 0);
}